// round 1
// baseline (speedup 1.0000x reference)
#include <cuda_runtime.h>
#include <math.h>

#define TT   365
#define NPTS 400
#define DD   104
#define HH   4
#define HD   26
#define TN   (TT*NPTS)      // 146000
#define D2   (2*DD)         // 208
#define D3   (3*DD)         // 312
#define TD   (TT*DD)        // 37960
#define SPLITK 40
#define KCHUNK 960

// ---------------- scratch (device globals; no runtime allocation) -------------
__device__ float g_hcat[(size_t)TN*DD];
__device__ float g_h   [(size_t)TN*DD];
__device__ float g_graph[(size_t)TT*NPTS*NPTS];
__device__ float g_z1  [(size_t)TN*DD];
__device__ float g_qkv [(size_t)TN*D3];
__device__ float g_kvs [(size_t)NPTS*HH*HD*HD];
__device__ float g_ksum[(size_t)NPTS*HH*HD];
__device__ float g_cat2[(size_t)TN*D2];   // attn concat; later reused as MLP hidden
__device__ float g_att0[(size_t)TN*DD];
__device__ float g_att1[(size_t)TN*DD];
__device__ float g_p0  [(size_t)TN*DD];
__device__ float g_p1  [(size_t)TN*DD];
__device__ float g_h1  [(size_t)TN*DD];
__device__ float g_t2  [(size_t)TN*DD];
__device__ float g_h2  [(size_t)TN*DD];
__device__ float g_h2t [(size_t)NPTS*TD];
__device__ float g_part[(size_t)SPLITK*NPTS*DD];
__device__ float g_y   [(size_t)NPTS*DD];
__device__ float g_yh  [(size_t)NPTS*D2];

// ---------------- generic tiled fp32 GEMM ------------------------------------
// C[M,Nc] = A[M,K] @ B  (+bias) ; TRANSB: B is [Nc,K] used transposed.
// ACC: C += result. SPLIT: blockIdx.z picks K-chunk, writes partial C plane.
// Non-split batched via blockIdx.z with element strides sA,sB,sC.
// Requires K % 4 == 0 (true for all call sites).
template<bool TRANSB, bool RELU, bool ACC, bool SPLIT>
__global__ void gemm_kernel(const float* __restrict__ A, const float* __restrict__ B,
                            const float* __restrict__ bias, float* __restrict__ C,
                            int M, int K, int Nc, long sA, long sB_, long sC)
{
    __shared__ float As[16][64];
    __shared__ float Bs[16][64];
    int tid = threadIdx.x;
    int bm = blockIdx.y * 64, bn = blockIdx.x * 64;
    int kbeg = 0, kend = K;
    if (SPLIT) {
        int z = blockIdx.z;
        kbeg = z * KCHUNK;
        kend = min(K, kbeg + KCHUNK);
        C += (long)z * M * Nc;
    } else {
        int z = blockIdx.z;
        A += z * sA; B += z * sB_; C += z * sC;
    }
    int tm = (tid >> 4) << 2;
    int tn = (tid & 15) << 2;
    float acc[4][4];
    #pragma unroll
    for (int i = 0; i < 4; i++)
        #pragma unroll
        for (int j = 0; j < 4; j++) acc[i][j] = 0.f;

    for (int k0 = kbeg; k0 < kend; k0 += 16) {
        { // A tile: each thread one float4 along k (coalesced), scatter to As[k][m]
            int m  = tid >> 2;
            int kq = (tid & 3) << 2;
            int gm = bm + m, gk = k0 + kq;
            float4 av = make_float4(0.f, 0.f, 0.f, 0.f);
            if (gm < M && gk < kend)
                av = *reinterpret_cast<const float4*>(A + (long)gm * K + gk);
            As[kq + 0][m] = av.x; As[kq + 1][m] = av.y;
            As[kq + 2][m] = av.z; As[kq + 3][m] = av.w;
        }
        if (TRANSB) {
            int n  = tid >> 2;
            int kq = (tid & 3) << 2;
            int gn = bn + n, gk = k0 + kq;
            float4 bv = make_float4(0.f, 0.f, 0.f, 0.f);
            if (gn < Nc && gk < kend)
                bv = *reinterpret_cast<const float4*>(B + (long)gn * K + gk);
            Bs[kq + 0][n] = bv.x; Bs[kq + 1][n] = bv.y;
            Bs[kq + 2][n] = bv.z; Bs[kq + 3][n] = bv.w;
        } else {
            #pragma unroll
            for (int i = tid; i < 1024; i += 256) {
                int k = i >> 6, n = i & 63;
                int gk = k0 + k, gn = bn + n;
                Bs[k][n] = (gk < kend && gn < Nc) ? B[(long)gk * Nc + gn] : 0.f;
            }
        }
        __syncthreads();
        #pragma unroll
        for (int k = 0; k < 16; k++) {
            const float4 a4 = *reinterpret_cast<const float4*>(&As[k][tm]);
            const float4 b4 = *reinterpret_cast<const float4*>(&Bs[k][tn]);
            float aa[4] = {a4.x, a4.y, a4.z, a4.w};
            float bb[4] = {b4.x, b4.y, b4.z, b4.w};
            #pragma unroll
            for (int i = 0; i < 4; i++)
                #pragma unroll
                for (int j = 0; j < 4; j++) acc[i][j] += aa[i] * bb[j];
        }
        __syncthreads();
    }
    #pragma unroll
    for (int i = 0; i < 4; i++) {
        int gm = bm + tm + i; if (gm >= M) continue;
        #pragma unroll
        for (int j = 0; j < 4; j++) {
            int gn = bn + tn + j; if (gn >= Nc) continue;
            float v = acc[i][j];
            if (!SPLIT && bias) v += bias[gn];
            if (RELU) v = fmaxf(v, 0.f);
            long ci = (long)gm * Nc + gn;
            if (ACC) v += C[ci];
            C[ci] = v;
        }
    }
}

// ---------------- input proj + concat adaptive embedding ----------------------
__global__ void hcat_kernel(const float* __restrict__ x, const float* __restrict__ W_in,
                            const float* __restrict__ b_in, const float* __restrict__ adp,
                            float* __restrict__ hcat)
{
    long idx = (long)blockIdx.x * 256 + threadIdx.x;
    if (idx >= (long)TN * DD) return;
    long tn = idx / DD; int j = (int)(idx - tn * DD);
    int t = (int)(tn / NPTS), n = (int)(tn - (long)t * NPTS);
    float v;
    if (j < 24) {
        const float* xr = x + ((long)n * TT + t) * 3;
        v = b_in[j] + xr[0] * W_in[0 * 24 + j] + xr[1] * W_in[1 * 24 + j] + xr[2] * W_in[2 * 24 + j];
    } else {
        v = adp[tn * 80 + (j - 24)];
    }
    hcat[idx] = v;
}

// ---------------- relu + row softmax (rows = T*N, cols = N) -------------------
__global__ void relu_softmax_kernel(float* __restrict__ g)
{
    long row = blockIdx.x;
    float* p = g + row * (long)NPTS;
    int tid = threadIdx.x;  // 128
    __shared__ float red[4];
    float mx = 0.f;
    for (int c = tid; c < NPTS; c += 128) mx = fmaxf(mx, p[c]);
    #pragma unroll
    for (int o = 16; o > 0; o >>= 1) mx = fmaxf(mx, __shfl_xor_sync(~0u, mx, o));
    if ((tid & 31) == 0) red[tid >> 5] = mx;
    __syncthreads();
    mx = fmaxf(fmaxf(red[0], red[1]), fmaxf(red[2], red[3]));
    __syncthreads();
    float s = 0.f;
    for (int c = tid; c < NPTS; c += 128) {
        float e = expf(fmaxf(p[c], 0.f) - mx);
        p[c] = e; s += e;
    }
    #pragma unroll
    for (int o = 16; o > 0; o >>= 1) s += __shfl_xor_sync(~0u, s, o);
    if ((tid & 31) == 0) red[tid >> 5] = s;
    __syncthreads();
    s = red[0] + red[1] + red[2] + red[3];
    float inv = 1.f / s;
    for (int c = tid; c < NPTS; c += 128) p[c] *= inv;
}

// ---------------- linear attention: kvs + ksum accumulation -------------------
// block = (b, h). qkv row layout [3D]; k at +DD, v at +2DD. Chunks of 8 l's.
__global__ void kvs_kernel(const float* __restrict__ qkv, long sB, long sL, int L,
                           float* __restrict__ kvs, float* __restrict__ ksum)
{
    int b = blockIdx.x, h = blockIdx.y;
    int tid = threadIdx.x;  // 256
    __shared__ float sk[8][HD], sv[8][HD], sinv[8];
    float acc[3] = {0.f, 0.f, 0.f};
    float accs = 0.f;
    for (int l0 = 0; l0 < L; l0 += 8) {
        for (int i = tid; i < 8 * HD; i += 256) {
            int ll = i / HD, m = i - ll * HD;
            int l = l0 + ll;
            float kk = 0.f, vv = 0.f;
            if (l < L) {
                const float* row = qkv + (long)b * sB + (long)l * sL + h * HD;
                kk = row[DD + m];
                vv = row[2 * DD + m];
            }
            sk[ll][m] = kk; sv[ll][m] = vv;
        }
        __syncthreads();
        int w = tid >> 5, lane = tid & 31;
        {
            float val = (lane < HD) ? sk[w][lane] : 0.f;
            float ss = val * val;
            #pragma unroll
            for (int o = 16; o > 0; o >>= 1) ss += __shfl_xor_sync(~0u, ss, o);
            if (lane == 0) sinv[w] = 1.f / fmaxf(sqrtf(ss), 1e-12f);
        }
        __syncthreads();
        #pragma unroll
        for (int ll = 0; ll < 8; ll++) {
            float iv = sinv[ll];
            #pragma unroll
            for (int c = 0; c < 3; c++) {
                int cell = tid + c * 256;
                if (cell < HD * HD) {
                    int m = cell / HD, d = cell - m * HD;
                    acc[c] += sk[ll][m] * iv * sv[ll][d];
                }
            }
            if (tid < HD) accs += sk[ll][tid] * iv;
        }
        __syncthreads();
    }
    long base = (long)b * HH + h;
    #pragma unroll
    for (int c = 0; c < 3; c++) {
        int cell = tid + c * 256;
        if (cell < HD * HD) kvs[base * (HD * HD) + cell] = acc[c];
    }
    if (tid < HD) ksum[base * HD + tid] = accs;
}

// ---------------- linear attention: per-token output --------------------------
// block = (l = blockIdx.x, b = blockIdx.y), 128 threads (104 active).
__global__ void attnout_kernel(const float* __restrict__ qkv, long sB, long sL, int L,
                               const float* __restrict__ kvs, const float* __restrict__ ksum,
                               float* __restrict__ outb, long oB, long oL, int ooff)
{
    int l = blockIdx.x, b = blockIdx.y;
    int tid = threadIdx.x;
    const float* row = qkv + (long)b * sB + (long)l * sL;
    __shared__ float sq[DD], sv[DD], sinv[HH], sden[HH];
    if (tid < DD) { sq[tid] = row[tid]; sv[tid] = row[2 * DD + tid]; }
    __syncthreads();
    if (tid < HH) {
        const float* qh = sq + tid * HD;
        float ss = 0.f;
        #pragma unroll
        for (int m = 0; m < HD; m++) ss += qh[m] * qh[m];
        float inv = 1.f / fmaxf(sqrtf(ss), 1e-12f);
        sinv[tid] = inv;
        const float* ks = ksum + ((long)b * HH + tid) * HD;
        float dd = 0.f;
        #pragma unroll
        for (int m = 0; m < HD; m++) dd += qh[m] * ks[m];
        sden[tid] = dd * inv + (float)L;
    }
    __syncthreads();
    if (tid < DD) {
        int h = tid / HD, d = tid - h * HD;
        const float* kv = kvs + ((long)b * HH + h) * (HD * HD) + d;
        const float* qh = sq + h * HD;
        float s = 0.f;
        #pragma unroll
        for (int m = 0; m < HD; m++) s += qh[m] * kv[m * HD];
        float num = s * sinv[h] + (float)L * sv[tid];
        outb[((long)b * oB + (long)l * oL) * D2 + ooff + tid] = num / sden[h];
    }
}

// ---------------- fused combine + LayerNorm -----------------------------------
__global__ void combine_ln_kernel(const float* __restrict__ h, const float* __restrict__ a0,
                                  const float* __restrict__ a1, const float* __restrict__ p0,
                                  const float* __restrict__ p1, const float* __restrict__ gam,
                                  const float* __restrict__ bet, float* __restrict__ out)
{
    long row = blockIdx.x; int tid = threadIdx.x;  // 128
    __shared__ float red[4];
    long i = row * DD + tid;
    float v = 0.f;
    if (tid < DD) v = 2.f * (h[i] + a0[i] * p0[i] + 0.01f * a1[i] * p1[i]);
    float s = (tid < DD) ? v : 0.f;
    #pragma unroll
    for (int o = 16; o > 0; o >>= 1) s += __shfl_xor_sync(~0u, s, o);
    if ((tid & 31) == 0) red[tid >> 5] = s;
    __syncthreads();
    float mean = (red[0] + red[1] + red[2] + red[3]) / (float)DD;
    __syncthreads();
    float d = (tid < DD) ? (v - mean) : 0.f;
    float s2 = d * d;
    #pragma unroll
    for (int o = 16; o > 0; o >>= 1) s2 += __shfl_xor_sync(~0u, s2, o);
    if ((tid & 31) == 0) red[tid >> 5] = s2;
    __syncthreads();
    float var = (red[0] + red[1] + red[2] + red[3]) / (float)DD;
    if (tid < DD) out[i] = d * rsqrtf(var + 1e-5f) * gam[tid] + bet[tid];
}

__global__ void ln_res_kernel(const float* __restrict__ a, const float* __restrict__ b,
                              const float* __restrict__ gam, const float* __restrict__ bet,
                              float* __restrict__ out)
{
    long row = blockIdx.x; int tid = threadIdx.x;  // 128
    __shared__ float red[4];
    long i = row * DD + tid;
    float v = 0.f;
    if (tid < DD) v = a[i] + b[i];
    float s = (tid < DD) ? v : 0.f;
    #pragma unroll
    for (int o = 16; o > 0; o >>= 1) s += __shfl_xor_sync(~0u, s, o);
    if ((tid & 31) == 0) red[tid >> 5] = s;
    __syncthreads();
    float mean = (red[0] + red[1] + red[2] + red[3]) / (float)DD;
    __syncthreads();
    float d = (tid < DD) ? (v - mean) : 0.f;
    float s2 = d * d;
    #pragma unroll
    for (int o = 16; o > 0; o >>= 1) s2 += __shfl_xor_sync(~0u, s2, o);
    if ((tid & 31) == 0) red[tid >> 5] = s2;
    __syncthreads();
    float var = (red[0] + red[1] + red[2] + red[3]) / (float)DD;
    if (tid < DD) out[i] = d * rsqrtf(var + 1e-5f) * gam[tid] + bet[tid];
}

// ---------------- [T,N,D] -> [N, T*D] transpose -------------------------------
__global__ void transpose_h2_kernel(const float* __restrict__ h2, float* __restrict__ h2t)
{
    long idx = (long)blockIdx.x * 256 + threadIdx.x;
    if (idx >= (long)TN * DD) return;
    long t = idx / ((long)NPTS * DD);
    long r = idx - t * ((long)NPTS * DD);
    long n = r / DD;
    long d = r - n * DD;
    h2t[n * (long)TD + t * DD + d] = h2[idx];
}

// ---------------- split-K deterministic reduction -----------------------------
__global__ void splitk_reduce_kernel(const float* __restrict__ part, const float* __restrict__ bias,
                                     float* __restrict__ y, int MN, int Z, int Nc)
{
    int i = blockIdx.x * 256 + threadIdx.x;
    if (i >= MN) return;
    float s = bias[i % Nc];
    for (int z = 0; z < Z; z++) s += part[(long)z * MN + i];
    y[i] = s;
}

// ---------------- host orchestration ------------------------------------------
static void run_attention(const float* x4, const float* qw, const float* ow, const float* ob,
                          float* qkv, float* kvs, float* ksum, float* cat2, float* attout)
{
    // qkv = x4 @ qw
    gemm_kernel<false, false, false, false><<<dim3((D3 + 63) / 64, (TN + 63) / 64, 1), 256>>>(
        x4, qw, nullptr, qkv, TN, DD, D3, 0, 0, 0);
    // spatial: b = t (B=TT), l = n (L=NPTS)
    kvs_kernel<<<dim3(TT, HH), 256>>>(qkv, (long)NPTS * D3, (long)D3, NPTS, kvs, ksum);
    attnout_kernel<<<dim3(NPTS, TT), 128>>>(qkv, (long)NPTS * D3, (long)D3, NPTS, kvs, ksum,
                                            cat2, (long)NPTS, 1, 0);
    // temporal: b = n (B=NPTS), l = t (L=TT)
    kvs_kernel<<<dim3(NPTS, HH), 256>>>(qkv, (long)D3, (long)NPTS * D3, TT, kvs, ksum);
    attnout_kernel<<<dim3(TT, NPTS), 128>>>(qkv, (long)D3, (long)NPTS * D3, TT, kvs, ksum,
                                            cat2, 1, (long)NPTS, DD);
    // attout = cat2 @ ow + ob
    gemm_kernel<false, false, false, false><<<dim3((DD + 63) / 64, (TN + 63) / 64, 1), 256>>>(
        cat2, ow, ob, attout, TN, D2, DD, 0, 0, 0);
}

extern "C" void kernel_launch(void* const* d_in, const int* in_sizes, int n_in,
                              void* d_out, int out_size)
{
    (void)in_sizes; (void)n_in; (void)out_size;
    const float* x     = (const float*)d_in[0];
    const float* W_in  = (const float*)d_in[1];
    const float* b_in  = (const float*)d_in[2];
    const float* adp   = (const float*)d_in[3];
    const float* W_tp  = (const float*)d_in[4];
    const float* b_tp  = (const float*)d_in[5];
    const float* qkv_w = (const float*)d_in[6];
    const float* op_w  = (const float*)d_in[7];
    const float* op_b  = (const float*)d_in[8];
    const float* pw_w  = (const float*)d_in[9];
    const float* pw_b  = (const float*)d_in[10];
    const float* fc_w1 = (const float*)d_in[11];
    const float* fc_b1 = (const float*)d_in[12];
    const float* fc_w2 = (const float*)d_in[13];
    const float* fc_b2 = (const float*)d_in[14];
    const float* ln1_g = (const float*)d_in[15];
    const float* ln1_b = (const float*)d_in[16];
    const float* ln2_g = (const float*)d_in[17];
    const float* ln2_b = (const float*)d_in[18];
    const float* ep_w  = (const float*)d_in[19];
    const float* ep_b  = (const float*)d_in[20];
    const float* enc_w1= (const float*)d_in[21];
    const float* enc_b1= (const float*)d_in[22];
    const float* enc_w2= (const float*)d_in[23];
    const float* enc_b2= (const float*)d_in[24];
    const float* out_w = (const float*)d_in[25];
    const float* out_b = (const float*)d_in[26];
    float* out = (float*)d_out;

    float *hcat, *h, *graph, *z1, *qkv, *kvs, *ksum, *cat2, *att0, *att1;
    float *p0, *p1, *h1, *t2, *h2, *h2t, *part, *y, *yh;
    cudaGetSymbolAddress((void**)&hcat, g_hcat);
    cudaGetSymbolAddress((void**)&h,    g_h);
    cudaGetSymbolAddress((void**)&graph,g_graph);
    cudaGetSymbolAddress((void**)&z1,   g_z1);
    cudaGetSymbolAddress((void**)&qkv,  g_qkv);
    cudaGetSymbolAddress((void**)&kvs,  g_kvs);
    cudaGetSymbolAddress((void**)&ksum, g_ksum);
    cudaGetSymbolAddress((void**)&cat2, g_cat2);
    cudaGetSymbolAddress((void**)&att0, g_att0);
    cudaGetSymbolAddress((void**)&att1, g_att1);
    cudaGetSymbolAddress((void**)&p0,   g_p0);
    cudaGetSymbolAddress((void**)&p1,   g_p1);
    cudaGetSymbolAddress((void**)&h1,   g_h1);
    cudaGetSymbolAddress((void**)&t2,   g_t2);
    cudaGetSymbolAddress((void**)&h2,   g_h2);
    cudaGetSymbolAddress((void**)&h2t,  g_h2t);
    cudaGetSymbolAddress((void**)&part, g_part);
    cudaGetSymbolAddress((void**)&y,    g_y);
    cudaGetSymbolAddress((void**)&yh,   g_yh);

    // 1. input proj + concat adaptive embedding
    hcat_kernel<<<((long)TN * DD + 255) / 256, 256>>>(x, W_in, b_in, adp, hcat);
    // 2. temporal 1x1 conv: h = hcat @ W_tp + b_tp
    gemm_kernel<false, false, false, false><<<dim3(2, (TN + 63) / 64, 1), 256>>>(
        hcat, W_tp, b_tp, h, TN, DD, DD, 0, 0, 0);
    // 3. graph[t] = adp_t @ adp_t^T  (batched NT)
    gemm_kernel<true, false, false, false><<<dim3(7, 7, TT), 256>>>(
        adp, adp, nullptr, graph, NPTS, 80, NPTS,
        (long)NPTS * 80, (long)NPTS * 80, (long)NPTS * NPTS);
    // 4. relu + row softmax
    relu_softmax_kernel<<<TN, 128>>>(graph);
    // 5. z1[t] = graph_t @ h_t  (batched NN)
    gemm_kernel<false, false, false, false><<<dim3(2, 7, TT), 256>>>(
        graph, h, nullptr, z1, NPTS, NPTS, DD,
        (long)NPTS * NPTS, (long)NPTS * DD, (long)NPTS * DD);
    // 6-7. two fast-attention branches
    run_attention(h,  qkv_w,            op_w,           op_b,       qkv, kvs, ksum, cat2, att0);
    run_attention(z1, qkv_w + DD * D3,  op_w + D2 * DD, op_b + DD,  qkv, kvs, ksum, cat2, att1);
    // 8. pointwise gates
    gemm_kernel<false, false, false, false><<<dim3(2, (TN + 63) / 64, 1), 256>>>(
        h,    pw_w,            pw_b,       p0, TN, DD, DD, 0, 0, 0);
    gemm_kernel<false, false, false, false><<<dim3(2, (TN + 63) / 64, 1), 256>>>(
        att0, pw_w + DD * DD,  pw_b + DD,  p1, TN, DD, DD, 0, 0, 0);
    // 9. combine + LN1 (input = 2*g due to in-place aliasing)
    combine_ln_kernel<<<TN, 128>>>(h, att0, att1, p0, p1, ln1_g, ln1_b, h1);
    // 10. MLP + residual LN2 (cat2 reused as hidden)
    gemm_kernel<false, true, false, false><<<dim3(4, (TN + 63) / 64, 1), 256>>>(
        h1, fc_w1, fc_b1, cat2, TN, DD, D2, 0, 0, 0);
    gemm_kernel<false, false, false, false><<<dim3(2, (TN + 63) / 64, 1), 256>>>(
        cat2, fc_w2, fc_b2, t2, TN, D2, DD, 0, 0, 0);
    ln_res_kernel<<<TN, 128>>>(h1, t2, ln2_g, ln2_b, h2);
    // 11. encoder_proj: transpose then split-K GEMM (deterministic reduce)
    transpose_h2_kernel<<<((long)TN * DD + 255) / 256, 256>>>(h2, h2t);
    gemm_kernel<false, false, false, true><<<dim3(2, 7, SPLITK), 256>>>(
        h2t, ep_w, nullptr, part, NPTS, TD, DD, 0, 0, 0);
    splitk_reduce_kernel<<<(NPTS * DD + 255) / 256, 256>>>(part, ep_b, y, NPTS * DD, SPLITK, DD);
    // 12. three residual MLP blocks
    for (int i = 0; i < 3; i++) {
        gemm_kernel<false, true, false, false><<<dim3(4, 7, 1), 256>>>(
            y,  enc_w1 + (long)i * DD * D2, enc_b1 + (long)i * D2, yh, NPTS, DD, D2, 0, 0, 0);
        gemm_kernel<false, false, true, false><<<dim3(2, 7, 1), 256>>>(
            yh, enc_w2 + (long)i * D2 * DD, enc_b2 + (long)i * DD, y,  NPTS, D2, DD, 0, 0, 0);
    }
    // 13. output projection -> d_out [N, T]
    gemm_kernel<false, false, false, false><<<dim3(6, 7, 1), 256>>>(
        y, out_w, out_b, out, NPTS, DD, TT, 0, 0, 0);
}

// round 2
// speedup vs baseline: 1.1860x; 1.1860x over previous
#include <cuda_runtime.h>
#include <math.h>

#define TT   365
#define NPTS 400
#define DD   104
#define HH   4
#define HD   26
#define TN   (TT*NPTS)      // 146000
#define D2   (2*DD)         // 208
#define D3   (3*DD)         // 312
#define TD   (TT*DD)        // 37960
#define SPLITK 40
#define KCHUNK 960

// ---------------- scratch (device globals; no runtime allocation) -------------
__device__ float g_hcat[(size_t)TN*DD];
__device__ float g_h   [(size_t)TN*DD];
__device__ float g_graph[(size_t)TT*NPTS*NPTS];
__device__ float g_mx  [(size_t)TN];
__device__ float g_invs[(size_t)TN];
__device__ float g_z1  [(size_t)TN*DD];
__device__ float g_qkv [(size_t)TN*D3];
__device__ float g_kvs [(size_t)NPTS*HH*HD*HD];
__device__ float g_ksum[(size_t)NPTS*HH*HD];
__device__ float g_cat2[(size_t)TN*D2];   // attn concat; later reused as MLP hidden
__device__ float g_att0[(size_t)TN*DD];
__device__ float g_att1[(size_t)TN*DD];
__device__ float g_p0  [(size_t)TN*DD];
__device__ float g_p1  [(size_t)TN*DD];
__device__ float g_h1  [(size_t)TN*DD];
__device__ float g_t2  [(size_t)TN*DD];
__device__ float g_h2  [(size_t)TN*DD];
__device__ float g_h2t [(size_t)NPTS*TD];
__device__ float g_part[(size_t)SPLITK*NPTS*DD];
__device__ float g_y   [(size_t)NPTS*DD];
__device__ float g_yh  [(size_t)NPTS*D2];

// ---------------- tiled fp32 GEMM: 128x64 tile, 8x4 microtile ------------------
// C[M,Nc] = A[M,K] @ B (+bias). TRANSB: B is [Nc,K] used transposed.
// ACC: C += result. SPLIT: blockIdx.z picks K-chunk, writes partial plane.
// SMAX: A element transform exp(max(a,0)-mx[row])*invs[row]  (fused softmax A).
// Batched (non-split) via blockIdx.z with strides sA,sB_,sC (and mx/invs += z*M).
// Requires K % 4 == 0 (true at all call sites).
template<bool TRANSB, bool RELU, bool ACC, bool SPLIT, bool SMAX>
__global__ void gemm_kernel(const float* __restrict__ A, const float* __restrict__ B,
                            const float* __restrict__ bias, float* __restrict__ C,
                            int M, int K, int Nc, long sA, long sB_, long sC,
                            const float* __restrict__ mx, const float* __restrict__ invs)
{
    __shared__ float As[16][128];
    __shared__ float Bs[16][64];
    int tid = threadIdx.x;
    int bm = blockIdx.y * 128, bn = blockIdx.x * 64;
    int kbeg = 0, kend = K;
    const float* mxp = mx;
    const float* ivp = invs;
    if (SPLIT) {
        int z = blockIdx.z;
        kbeg = z * KCHUNK;
        kend = min(K, kbeg + KCHUNK);
        C += (long)z * M * Nc;
    } else {
        int z = blockIdx.z;
        A += z * sA; B += z * sB_; C += z * sC;
        if (SMAX) { mxp += (long)z * M; ivp += (long)z * M; }
    }
    int tm = (tid >> 4) << 3;   // 0..120 step 8
    int tn = (tid & 15) << 2;   // 0..60  step 4
    float acc[8][4];
    #pragma unroll
    for (int i = 0; i < 8; i++)
        #pragma unroll
        for (int j = 0; j < 4; j++) acc[i][j] = 0.f;

    for (int k0 = kbeg; k0 < kend; k0 += 16) {
        // ---- A tile: 2 float4 per thread, scatter to As[k][m] ----
        #pragma unroll
        for (int rep = 0; rep < 2; rep++) {
            int idx = tid + rep * 256;
            int m  = idx >> 2;
            int kq = (idx & 3) << 2;
            int gm = bm + m, gk = k0 + kq;
            float4 av = make_float4(0.f, 0.f, 0.f, 0.f);
            if (gm < M && gk < kend) {
                av = *reinterpret_cast<const float4*>(A + (long)gm * K + gk);
                if (SMAX) {
                    float mm = mxp[gm], iv = ivp[gm];
                    av.x = __expf(fmaxf(av.x, 0.f) - mm) * iv;
                    av.y = __expf(fmaxf(av.y, 0.f) - mm) * iv;
                    av.z = __expf(fmaxf(av.z, 0.f) - mm) * iv;
                    av.w = __expf(fmaxf(av.w, 0.f) - mm) * iv;
                }
            }
            As[kq + 0][m] = av.x; As[kq + 1][m] = av.y;
            As[kq + 2][m] = av.z; As[kq + 3][m] = av.w;
        }
        // ---- B tile ----
        if (TRANSB) {
            int n  = tid >> 2;
            int kq = (tid & 3) << 2;
            int gn = bn + n, gk = k0 + kq;
            float4 bv = make_float4(0.f, 0.f, 0.f, 0.f);
            if (gn < Nc && gk < kend)
                bv = *reinterpret_cast<const float4*>(B + (long)gn * K + gk);
            Bs[kq + 0][n] = bv.x; Bs[kq + 1][n] = bv.y;
            Bs[kq + 2][n] = bv.z; Bs[kq + 3][n] = bv.w;
        } else {
            int k  = tid >> 4;
            int n4 = (tid & 15) << 2;
            int gk = k0 + k;
            #pragma unroll
            for (int j = 0; j < 4; j++) {
                int gn = bn + n4 + j;
                Bs[k][n4 + j] = (gk < kend && gn < Nc) ? B[(long)gk * Nc + gn] : 0.f;
            }
        }
        __syncthreads();
        #pragma unroll
        for (int k = 0; k < 16; k++) {
            float4 a0 = *reinterpret_cast<const float4*>(&As[k][tm]);
            float4 a1 = *reinterpret_cast<const float4*>(&As[k][tm + 4]);
            float4 b4 = *reinterpret_cast<const float4*>(&Bs[k][tn]);
            float aa[8] = {a0.x, a0.y, a0.z, a0.w, a1.x, a1.y, a1.z, a1.w};
            float bb[4] = {b4.x, b4.y, b4.z, b4.w};
            #pragma unroll
            for (int i = 0; i < 8; i++)
                #pragma unroll
                for (int j = 0; j < 4; j++) acc[i][j] += aa[i] * bb[j];
        }
        __syncthreads();
    }
    #pragma unroll
    for (int i = 0; i < 8; i++) {
        int gm = bm + tm + i; if (gm >= M) continue;
        #pragma unroll
        for (int j = 0; j < 4; j++) {
            int gn = bn + tn + j; if (gn >= Nc) continue;
            float v = acc[i][j];
            if (!SPLIT && bias) v += bias[gn];
            if (RELU) v = fmaxf(v, 0.f);
            long ci = (long)gm * Nc + gn;
            if (ACC) v += C[ci];
            C[ci] = v;
        }
    }
}

// ---------------- per-row max + inverse sum of exp(relu(x)-mx) ----------------
__global__ void rowstat_kernel(const float* __restrict__ g, float* __restrict__ mx,
                               float* __restrict__ invs)
{
    long row = (long)blockIdx.x * 8 + (threadIdx.x >> 5);
    if (row >= (long)TN) return;
    int lane = threadIdx.x & 31;
    const float* p = g + row * NPTS;
    float m = 0.f;
    for (int c = lane; c < NPTS; c += 32) m = fmaxf(m, p[c]);
    #pragma unroll
    for (int o = 16; o > 0; o >>= 1) m = fmaxf(m, __shfl_xor_sync(~0u, m, o));
    float s = 0.f;
    for (int c = lane; c < NPTS; c += 32) s += __expf(fmaxf(p[c], 0.f) - m);
    #pragma unroll
    for (int o = 16; o > 0; o >>= 1) s += __shfl_xor_sync(~0u, s, o);
    if (lane == 0) { mx[row] = m; invs[row] = 1.f / s; }
}

// ---------------- input proj + concat adaptive embedding ----------------------
__global__ void hcat_kernel(const float* __restrict__ x, const float* __restrict__ W_in,
                            const float* __restrict__ b_in, const float* __restrict__ adp,
                            float* __restrict__ hcat)
{
    long idx = (long)blockIdx.x * 256 + threadIdx.x;
    if (idx >= (long)TN * DD) return;
    long tn = idx / DD; int j = (int)(idx - tn * DD);
    int t = (int)(tn / NPTS), n = (int)(tn - (long)t * NPTS);
    float v;
    if (j < 24) {
        const float* xr = x + ((long)n * TT + t) * 3;
        v = b_in[j] + xr[0] * W_in[0 * 24 + j] + xr[1] * W_in[1 * 24 + j] + xr[2] * W_in[2 * 24 + j];
    } else {
        v = adp[tn * 80 + (j - 24)];
    }
    hcat[idx] = v;
}

// ---------------- linear attention: kvs + ksum accumulation -------------------
__global__ void kvs_kernel(const float* __restrict__ qkv, long sB, long sL, int L,
                           float* __restrict__ kvs, float* __restrict__ ksum)
{
    int b = blockIdx.x, h = blockIdx.y;
    int tid = threadIdx.x;  // 256
    __shared__ float sk[8][HD], sv[8][HD], sinv[8];
    float acc[3] = {0.f, 0.f, 0.f};
    float accs = 0.f;
    for (int l0 = 0; l0 < L; l0 += 8) {
        for (int i = tid; i < 8 * HD; i += 256) {
            int ll = i / HD, m = i - ll * HD;
            int l = l0 + ll;
            float kk = 0.f, vv = 0.f;
            if (l < L) {
                const float* row = qkv + (long)b * sB + (long)l * sL + h * HD;
                kk = row[DD + m];
                vv = row[2 * DD + m];
            }
            sk[ll][m] = kk; sv[ll][m] = vv;
        }
        __syncthreads();
        int w = tid >> 5, lane = tid & 31;
        {
            float val = (lane < HD) ? sk[w][lane] : 0.f;
            float ss = val * val;
            #pragma unroll
            for (int o = 16; o > 0; o >>= 1) ss += __shfl_xor_sync(~0u, ss, o);
            if (lane == 0) sinv[w] = 1.f / fmaxf(sqrtf(ss), 1e-12f);
        }
        __syncthreads();
        #pragma unroll
        for (int ll = 0; ll < 8; ll++) {
            float iv = sinv[ll];
            #pragma unroll
            for (int c = 0; c < 3; c++) {
                int cell = tid + c * 256;
                if (cell < HD * HD) {
                    int m = cell / HD, d = cell - m * HD;
                    acc[c] += sk[ll][m] * iv * sv[ll][d];
                }
            }
            if (tid < HD) accs += sk[ll][tid] * iv;
        }
        __syncthreads();
    }
    long base = (long)b * HH + h;
    #pragma unroll
    for (int c = 0; c < 3; c++) {
        int cell = tid + c * 256;
        if (cell < HD * HD) kvs[base * (HD * HD) + cell] = acc[c];
    }
    if (tid < HD) ksum[base * HD + tid] = accs;
}

// ---------------- linear attention: per-token output --------------------------
__global__ void attnout_kernel(const float* __restrict__ qkv, long sB, long sL, int L,
                               const float* __restrict__ kvs, const float* __restrict__ ksum,
                               float* __restrict__ outb, long oB, long oL, int ooff)
{
    int l = blockIdx.x, b = blockIdx.y;
    int tid = threadIdx.x;
    const float* row = qkv + (long)b * sB + (long)l * sL;
    __shared__ float sq[DD], sv[DD], sinv[HH], sden[HH];
    if (tid < DD) { sq[tid] = row[tid]; sv[tid] = row[2 * DD + tid]; }
    __syncthreads();
    if (tid < HH) {
        const float* qh = sq + tid * HD;
        float ss = 0.f;
        #pragma unroll
        for (int m = 0; m < HD; m++) ss += qh[m] * qh[m];
        float inv = 1.f / fmaxf(sqrtf(ss), 1e-12f);
        sinv[tid] = inv;
        const float* ks = ksum + ((long)b * HH + tid) * HD;
        float dd = 0.f;
        #pragma unroll
        for (int m = 0; m < HD; m++) dd += qh[m] * ks[m];
        sden[tid] = dd * inv + (float)L;
    }
    __syncthreads();
    if (tid < DD) {
        int h = tid / HD, d = tid - h * HD;
        const float* kv = kvs + ((long)b * HH + h) * (HD * HD) + d;
        const float* qh = sq + h * HD;
        float s = 0.f;
        #pragma unroll
        for (int m = 0; m < HD; m++) s += qh[m] * kv[m * HD];
        float num = s * sinv[h] + (float)L * sv[tid];
        outb[((long)b * oB + (long)l * oL) * D2 + ooff + tid] = num / sden[h];
    }
}

// ---------------- fused combine + LayerNorm -----------------------------------
__global__ void combine_ln_kernel(const float* __restrict__ h, const float* __restrict__ a0,
                                  const float* __restrict__ a1, const float* __restrict__ p0,
                                  const float* __restrict__ p1, const float* __restrict__ gam,
                                  const float* __restrict__ bet, float* __restrict__ out)
{
    long row = blockIdx.x; int tid = threadIdx.x;  // 128
    __shared__ float red[4];
    long i = row * DD + tid;
    float v = 0.f;
    if (tid < DD) v = 2.f * (h[i] + a0[i] * p0[i] + 0.01f * a1[i] * p1[i]);
    float s = (tid < DD) ? v : 0.f;
    #pragma unroll
    for (int o = 16; o > 0; o >>= 1) s += __shfl_xor_sync(~0u, s, o);
    if ((tid & 31) == 0) red[tid >> 5] = s;
    __syncthreads();
    float mean = (red[0] + red[1] + red[2] + red[3]) / (float)DD;
    __syncthreads();
    float d = (tid < DD) ? (v - mean) : 0.f;
    float s2 = d * d;
    #pragma unroll
    for (int o = 16; o > 0; o >>= 1) s2 += __shfl_xor_sync(~0u, s2, o);
    if ((tid & 31) == 0) red[tid >> 5] = s2;
    __syncthreads();
    float var = (red[0] + red[1] + red[2] + red[3]) / (float)DD;
    if (tid < DD) out[i] = d * rsqrtf(var + 1e-5f) * gam[tid] + bet[tid];
}

__global__ void ln_res_kernel(const float* __restrict__ a, const float* __restrict__ b,
                              const float* __restrict__ gam, const float* __restrict__ bet,
                              float* __restrict__ out)
{
    long row = blockIdx.x; int tid = threadIdx.x;  // 128
    __shared__ float red[4];
    long i = row * DD + tid;
    float v = 0.f;
    if (tid < DD) v = a[i] + b[i];
    float s = (tid < DD) ? v : 0.f;
    #pragma unroll
    for (int o = 16; o > 0; o >>= 1) s += __shfl_xor_sync(~0u, s, o);
    if ((tid & 31) == 0) red[tid >> 5] = s;
    __syncthreads();
    float mean = (red[0] + red[1] + red[2] + red[3]) / (float)DD;
    __syncthreads();
    float d = (tid < DD) ? (v - mean) : 0.f;
    float s2 = d * d;
    #pragma unroll
    for (int o = 16; o > 0; o >>= 1) s2 += __shfl_xor_sync(~0u, s2, o);
    if ((tid & 31) == 0) red[tid >> 5] = s2;
    __syncthreads();
    float var = (red[0] + red[1] + red[2] + red[3]) / (float)DD;
    if (tid < DD) out[i] = d * rsqrtf(var + 1e-5f) * gam[tid] + bet[tid];
}

// ---------------- [T,N,D] -> [N, T*D] transpose -------------------------------
__global__ void transpose_h2_kernel(const float* __restrict__ h2, float* __restrict__ h2t)
{
    long idx = (long)blockIdx.x * 256 + threadIdx.x;
    if (idx >= (long)TN * DD) return;
    long t = idx / ((long)NPTS * DD);
    long r = idx - t * ((long)NPTS * DD);
    long n = r / DD;
    long d = r - n * DD;
    h2t[n * (long)TD + t * DD + d] = h2[idx];
}

// ---------------- split-K deterministic reduction -----------------------------
__global__ void splitk_reduce_kernel(const float* __restrict__ part, const float* __restrict__ bias,
                                     float* __restrict__ y, int MN, int Z, int Nc)
{
    int i = blockIdx.x * 256 + threadIdx.x;
    if (i >= MN) return;
    float s = bias[i % Nc];
    for (int z = 0; z < Z; z++) s += part[(long)z * MN + i];
    y[i] = s;
}

#define GEMM(TB,RL,AC,SP,SX, gx,gy,gz, A,B,bias,C, M,K,Nc, sA,sB,sC, mx,iv) \
    gemm_kernel<TB,RL,AC,SP,SX><<<dim3(gx,gy,gz), 256>>>(A,B,bias,C,M,K,Nc,sA,sB,sC,mx,iv)

// ---------------- host orchestration ------------------------------------------
static void run_attention(const float* x4, const float* qw, const float* ow, const float* ob,
                          float* qkv, float* kvs, float* ksum, float* cat2, float* attout)
{
    // qkv = x4 @ qw   [TN,104]x[104,312]
    GEMM(false,false,false,false,false, 5, (TN+127)/128, 1,
         x4, qw, nullptr, qkv, TN, DD, D3, 0,0,0, nullptr,nullptr);
    // spatial: b = t (B=TT), l = n (L=NPTS)
    kvs_kernel<<<dim3(TT, HH), 256>>>(qkv, (long)NPTS * D3, (long)D3, NPTS, kvs, ksum);
    attnout_kernel<<<dim3(NPTS, TT), 128>>>(qkv, (long)NPTS * D3, (long)D3, NPTS, kvs, ksum,
                                            cat2, (long)NPTS, 1, 0);
    // temporal: b = n (B=NPTS), l = t (L=TT)
    kvs_kernel<<<dim3(NPTS, HH), 256>>>(qkv, (long)D3, (long)NPTS * D3, TT, kvs, ksum);
    attnout_kernel<<<dim3(TT, NPTS), 128>>>(qkv, (long)D3, (long)NPTS * D3, TT, kvs, ksum,
                                            cat2, 1, (long)NPTS, DD);
    // attout = cat2 @ ow + ob   [TN,208]x[208,104]
    GEMM(false,false,false,false,false, 2, (TN+127)/128, 1,
         cat2, ow, ob, attout, TN, D2, DD, 0,0,0, nullptr,nullptr);
}

extern "C" void kernel_launch(void* const* d_in, const int* in_sizes, int n_in,
                              void* d_out, int out_size)
{
    (void)in_sizes; (void)n_in; (void)out_size;
    const float* x     = (const float*)d_in[0];
    const float* W_in  = (const float*)d_in[1];
    const float* b_in  = (const float*)d_in[2];
    const float* adp   = (const float*)d_in[3];
    const float* W_tp  = (const float*)d_in[4];
    const float* b_tp  = (const float*)d_in[5];
    const float* qkv_w = (const float*)d_in[6];
    const float* op_w  = (const float*)d_in[7];
    const float* op_b  = (const float*)d_in[8];
    const float* pw_w  = (const float*)d_in[9];
    const float* pw_b  = (const float*)d_in[10];
    const float* fc_w1 = (const float*)d_in[11];
    const float* fc_b1 = (const float*)d_in[12];
    const float* fc_w2 = (const float*)d_in[13];
    const float* fc_b2 = (const float*)d_in[14];
    const float* ln1_g = (const float*)d_in[15];
    const float* ln1_b = (const float*)d_in[16];
    const float* ln2_g = (const float*)d_in[17];
    const float* ln2_b = (const float*)d_in[18];
    const float* ep_w  = (const float*)d_in[19];
    const float* ep_b  = (const float*)d_in[20];
    const float* enc_w1= (const float*)d_in[21];
    const float* enc_b1= (const float*)d_in[22];
    const float* enc_w2= (const float*)d_in[23];
    const float* enc_b2= (const float*)d_in[24];
    const float* out_w = (const float*)d_in[25];
    const float* out_b = (const float*)d_in[26];
    float* out = (float*)d_out;

    float *hcat, *h, *graph, *mxp, *invs, *z1, *qkv, *kvs, *ksum, *cat2, *att0, *att1;
    float *p0, *p1, *h1, *t2, *h2, *h2t, *part, *y, *yh;
    cudaGetSymbolAddress((void**)&hcat, g_hcat);
    cudaGetSymbolAddress((void**)&h,    g_h);
    cudaGetSymbolAddress((void**)&graph,g_graph);
    cudaGetSymbolAddress((void**)&mxp,  g_mx);
    cudaGetSymbolAddress((void**)&invs, g_invs);
    cudaGetSymbolAddress((void**)&z1,   g_z1);
    cudaGetSymbolAddress((void**)&qkv,  g_qkv);
    cudaGetSymbolAddress((void**)&kvs,  g_kvs);
    cudaGetSymbolAddress((void**)&ksum, g_ksum);
    cudaGetSymbolAddress((void**)&cat2, g_cat2);
    cudaGetSymbolAddress((void**)&att0, g_att0);
    cudaGetSymbolAddress((void**)&att1, g_att1);
    cudaGetSymbolAddress((void**)&p0,   g_p0);
    cudaGetSymbolAddress((void**)&p1,   g_p1);
    cudaGetSymbolAddress((void**)&h1,   g_h1);
    cudaGetSymbolAddress((void**)&t2,   g_t2);
    cudaGetSymbolAddress((void**)&h2,   g_h2);
    cudaGetSymbolAddress((void**)&h2t,  g_h2t);
    cudaGetSymbolAddress((void**)&part, g_part);
    cudaGetSymbolAddress((void**)&y,    g_y);
    cudaGetSymbolAddress((void**)&yh,   g_yh);

    const int MY = (TN + 127) / 128;   // 1141

    // 1. input proj + concat adaptive embedding
    hcat_kernel<<<((long)TN * DD + 255) / 256, 256>>>(x, W_in, b_in, adp, hcat);
    // 2. temporal 1x1 conv: h = hcat @ W_tp + b_tp
    GEMM(false,false,false,false,false, 2, MY, 1,
         hcat, W_tp, b_tp, h, TN, DD, DD, 0,0,0, nullptr,nullptr);
    // 3. graph[t] = adp_t @ adp_t^T  (batched NT, raw scores)
    GEMM(true,false,false,false,false, 7, 4, TT,
         adp, adp, nullptr, graph, NPTS, 80, NPTS,
         (long)NPTS*80, (long)NPTS*80, (long)NPTS*NPTS, nullptr,nullptr);
    // 4. per-row softmax stats (max + inv-sum)
    rowstat_kernel<<<(TN + 7) / 8, 256>>>(graph, mxp, invs);
    // 5. z1[t] = softmax(relu(graph_t)) @ h_t — softmax fused into A-tile load
    GEMM(false,false,false,false,true, 2, 4, TT,
         graph, h, nullptr, z1, NPTS, NPTS, DD,
         (long)NPTS*NPTS, (long)NPTS*DD, (long)NPTS*DD, mxp, invs);
    // 6-7. two fast-attention branches
    run_attention(h,  qkv_w,            op_w,           op_b,       qkv, kvs, ksum, cat2, att0);
    run_attention(z1, qkv_w + DD * D3,  op_w + D2 * DD, op_b + DD,  qkv, kvs, ksum, cat2, att1);
    // 8. pointwise gates
    GEMM(false,false,false,false,false, 2, MY, 1,
         h,    pw_w,           pw_b,      p0, TN, DD, DD, 0,0,0, nullptr,nullptr);
    GEMM(false,false,false,false,false, 2, MY, 1,
         att0, pw_w + DD * DD, pw_b + DD, p1, TN, DD, DD, 0,0,0, nullptr,nullptr);
    // 9. combine + LN1 (input = 2*g due to in-place aliasing)
    combine_ln_kernel<<<TN, 128>>>(h, att0, att1, p0, p1, ln1_g, ln1_b, h1);
    // 10. MLP + residual LN2 (cat2 reused as hidden)
    GEMM(false,true,false,false,false, 4, MY, 1,
         h1, fc_w1, fc_b1, cat2, TN, DD, D2, 0,0,0, nullptr,nullptr);
    GEMM(false,false,false,false,false, 2, MY, 1,
         cat2, fc_w2, fc_b2, t2, TN, D2, DD, 0,0,0, nullptr,nullptr);
    ln_res_kernel<<<TN, 128>>>(h1, t2, ln2_g, ln2_b, h2);
    // 11. encoder_proj: transpose then split-K GEMM (deterministic reduce)
    transpose_h2_kernel<<<((long)TN * DD + 255) / 256, 256>>>(h2, h2t);
    GEMM(false,false,false,true,false, 2, 4, SPLITK,
         h2t, ep_w, nullptr, part, NPTS, TD, DD, 0,0,0, nullptr,nullptr);
    splitk_reduce_kernel<<<(NPTS * DD + 255) / 256, 256>>>(part, ep_b, y, NPTS * DD, SPLITK, DD);
    // 12. three residual MLP blocks
    for (int i = 0; i < 3; i++) {
        GEMM(false,true,false,false,false, 4, 4, 1,
             y,  enc_w1 + (long)i * DD * D2, enc_b1 + (long)i * D2, yh, NPTS, DD, D2, 0,0,0, nullptr,nullptr);
        GEMM(false,false,true,false,false, 2, 4, 1,
             yh, enc_w2 + (long)i * D2 * DD, enc_b2 + (long)i * DD, y,  NPTS, D2, DD, 0,0,0, nullptr,nullptr);
    }
    // 13. output projection -> d_out [N, T]
    GEMM(false,false,false,false,false, 6, 4, 1,
         y, out_w, out_b, out, NPTS, DD, TT, 0,0,0, nullptr,nullptr);
}

// round 3
// speedup vs baseline: 1.2691x; 1.0701x over previous
#include <cuda_runtime.h>
#include <math.h>

#define TT   365
#define NPTS 400
#define DD   104
#define HH   4
#define HD   26
#define TN   (TT*NPTS)      // 146000
#define D2   (2*DD)         // 208
#define D3   (3*DD)         // 312
#define TD   (TT*DD)        // 37960
#define SPLITK 40
#define KCHUNK 960

// ---------------- scratch (device globals; no runtime allocation) -------------
__device__ float g_hcat[(size_t)TN*DD];
__device__ float g_h   [(size_t)TN*DD];
__device__ float g_graph[(size_t)TT*NPTS*NPTS];
__device__ float g_mx  [(size_t)TN];
__device__ float g_invs[(size_t)TN];
__device__ float g_z1  [(size_t)TN*DD];
__device__ float g_qkv [(size_t)TN*D3];
__device__ float g_kvs [(size_t)NPTS*HH*HD*HD];
__device__ float g_ksum[(size_t)NPTS*HH*HD];
__device__ float g_cat2[(size_t)TN*D2];
__device__ float g_att0[(size_t)TN*DD];
__device__ float g_att1[(size_t)TN*DD];
__device__ float g_p0  [(size_t)TN*DD];
__device__ float g_p1  [(size_t)TN*DD];
__device__ float g_h1  [(size_t)TN*DD];
__device__ float g_t2  [(size_t)TN*DD];
__device__ float g_h2  [(size_t)TN*DD];
__device__ float g_h2t [(size_t)NPTS*TD];
__device__ float g_part[(size_t)SPLITK*NPTS*DD];
__device__ float g_y   [(size_t)NPTS*DD];
__device__ float g_yh  [(size_t)NPTS*D2];

// ---------------- tiled fp32 GEMM: 128x64 tile, 8x4 microtile, FFMA2 ----------
// C[M,Nc] = A[M,K] @ B (+bias). TRANSB: B is [Nc,K] used transposed.
// ACC: C += result. SPLIT: blockIdx.z picks K-chunk, writes partial plane.
// SMAX: A transform exp(max(a,0)-mx[row])*invs[row] (fused softmax A).
// Double-buffered smem, register-staged prefetch, packed fma.rn.f32x2 core.

template<bool SMAX>
__device__ __forceinline__ void load_a(const float* __restrict__ A, int bm, int k0, int kend,
                                       int M, int K, const float* __restrict__ mxp,
                                       const float* __restrict__ ivp, int tid,
                                       float4& r0, float4& r1)
{
    #pragma unroll
    for (int rep = 0; rep < 2; rep++) {
        int idx = tid + rep * 256;
        int m  = idx >> 2;
        int kq = (idx & 3) << 2;
        int gm = bm + m, gk = k0 + kq;
        float4 av = make_float4(0.f, 0.f, 0.f, 0.f);
        if (gm < M && gk < kend) {
            av = *reinterpret_cast<const float4*>(A + (long)gm * K + gk);
            if (SMAX) {
                float mm = mxp[gm], iv = ivp[gm];
                av.x = __expf(fmaxf(av.x, 0.f) - mm) * iv;
                av.y = __expf(fmaxf(av.y, 0.f) - mm) * iv;
                av.z = __expf(fmaxf(av.z, 0.f) - mm) * iv;
                av.w = __expf(fmaxf(av.w, 0.f) - mm) * iv;
            }
        }
        if (rep == 0) r0 = av; else r1 = av;
    }
}

__device__ __forceinline__ void store_a(float (*As)[128], int tid, float4 r0, float4 r1)
{
    #pragma unroll
    for (int rep = 0; rep < 2; rep++) {
        float4 av = (rep == 0) ? r0 : r1;
        int idx = tid + rep * 256;
        int m  = idx >> 2;
        int kq = (idx & 3) << 2;
        As[kq + 0][m] = av.x; As[kq + 1][m] = av.y;
        As[kq + 2][m] = av.z; As[kq + 3][m] = av.w;
    }
}

template<bool TRANSB>
__device__ __forceinline__ void load_b(const float* __restrict__ B, int bn, int k0, int kend,
                                       int Nc, int K, int tid, float4& rt, float* rs)
{
    if (TRANSB) {
        int n  = tid >> 2;
        int kq = (tid & 3) << 2;
        int gn = bn + n, gk = k0 + kq;
        rt = make_float4(0.f, 0.f, 0.f, 0.f);
        if (gn < Nc && gk < kend)
            rt = *reinterpret_cast<const float4*>(B + (long)gn * K + gk);
    } else {
        int k  = tid >> 4;
        int n4 = (tid & 15) << 2;
        int gk = k0 + k;
        #pragma unroll
        for (int j = 0; j < 4; j++) {
            int gn = bn + n4 + j;
            rs[j] = (gk < kend && gn < Nc) ? B[(long)gk * Nc + gn] : 0.f;
        }
    }
}

template<bool TRANSB>
__device__ __forceinline__ void store_b(float (*Bs)[64], int tid, float4 rt, const float* rs)
{
    if (TRANSB) {
        int n  = tid >> 2;
        int kq = (tid & 3) << 2;
        Bs[kq + 0][n] = rt.x; Bs[kq + 1][n] = rt.y;
        Bs[kq + 2][n] = rt.z; Bs[kq + 3][n] = rt.w;
    } else {
        int k  = tid >> 4;
        int n4 = (tid & 15) << 2;
        #pragma unroll
        for (int j = 0; j < 4; j++) Bs[k][n4 + j] = rs[j];
    }
}

__device__ __forceinline__ void mma_tile(const float (*__restrict__ Asb)[128],
                                         const float (*__restrict__ Bsb)[64],
                                         int tm, int tn, unsigned long long (*accp)[2])
{
    #pragma unroll
    for (int k = 0; k < 16; k++) {
        float4 a0 = *reinterpret_cast<const float4*>(&Asb[k][tm]);
        float4 a1 = *reinterpret_cast<const float4*>(&Asb[k][tm + 4]);
        float4 b4 = *reinterpret_cast<const float4*>(&Bsb[k][tn]);
        unsigned long long B0, B1;
        asm("mov.b64 %0,{%1,%2};" : "=l"(B0) : "f"(b4.x), "f"(b4.y));
        asm("mov.b64 %0,{%1,%2};" : "=l"(B1) : "f"(b4.z), "f"(b4.w));
        float aa[8] = {a0.x, a0.y, a0.z, a0.w, a1.x, a1.y, a1.z, a1.w};
        #pragma unroll
        for (int i = 0; i < 8; i++) {
            unsigned long long A2;
            asm("mov.b64 %0,{%1,%1};" : "=l"(A2) : "f"(aa[i]));
            asm("fma.rn.f32x2 %0,%1,%2,%0;" : "+l"(accp[i][0]) : "l"(A2), "l"(B0));
            asm("fma.rn.f32x2 %0,%1,%2,%0;" : "+l"(accp[i][1]) : "l"(A2), "l"(B1));
        }
    }
}

template<bool TRANSB, bool RELU, bool ACC, bool SPLIT, bool SMAX>
__global__ void gemm_kernel(const float* __restrict__ A, const float* __restrict__ B,
                            const float* __restrict__ bias, float* __restrict__ C,
                            int M, int K, int Nc, long sA, long sB_, long sC,
                            const float* __restrict__ mx, const float* __restrict__ invs)
{
    __shared__ float As[2][16][128];
    __shared__ float Bs[2][16][64];
    int tid = threadIdx.x;
    int bm = blockIdx.y * 128, bn = blockIdx.x * 64;
    int kbeg = 0, kend = K;
    const float* mxp = mx;
    const float* ivp = invs;
    if (SPLIT) {
        int z = blockIdx.z;
        kbeg = z * KCHUNK;
        kend = min(K, kbeg + KCHUNK);
        C += (long)z * M * Nc;
    } else {
        int z = blockIdx.z;
        A += z * sA; B += z * sB_; C += z * sC;
        if (SMAX) { mxp += (long)z * M; ivp += (long)z * M; }
    }
    int tm = (tid >> 4) << 3;
    int tn = (tid & 15) << 2;
    unsigned long long accp[8][2];
    #pragma unroll
    for (int i = 0; i < 8; i++) { accp[i][0] = 0ull; accp[i][1] = 0ull; }

    int nk = (kend - kbeg + 15) >> 4;
    float4 ra0, ra1, rbt; float rbs[4];
    load_a<SMAX>(A, bm, kbeg, kend, M, K, mxp, ivp, tid, ra0, ra1);
    load_b<TRANSB>(B, bn, kbeg, kend, Nc, K, tid, rbt, rbs);
    store_a(As[0], tid, ra0, ra1);
    store_b<TRANSB>(Bs[0], tid, rbt, rbs);
    __syncthreads();
    int buf = 0;
    for (int it = 0; it < nk; it++) {
        bool has_next = (it + 1 < nk);
        if (has_next) {
            int kn = kbeg + (it + 1) * 16;
            load_a<SMAX>(A, bm, kn, kend, M, K, mxp, ivp, tid, ra0, ra1);
            load_b<TRANSB>(B, bn, kn, kend, Nc, K, tid, rbt, rbs);
        }
        mma_tile(As[buf], Bs[buf], tm, tn, accp);
        if (has_next) {
            store_a(As[buf ^ 1], tid, ra0, ra1);
            store_b<TRANSB>(Bs[buf ^ 1], tid, rbt, rbs);
            __syncthreads();
            buf ^= 1;
        }
    }
    #pragma unroll
    for (int i = 0; i < 8; i++) {
        int gm = bm + tm + i; if (gm >= M) continue;
        float av[4];
        asm("mov.b64 {%0,%1}, %2;" : "=f"(av[0]), "=f"(av[1]) : "l"(accp[i][0]));
        asm("mov.b64 {%0,%1}, %2;" : "=f"(av[2]), "=f"(av[3]) : "l"(accp[i][1]));
        #pragma unroll
        for (int j = 0; j < 4; j++) {
            int gn = bn + tn + j; if (gn >= Nc) continue;
            float v = av[j];
            if (!SPLIT && bias) v += bias[gn];
            if (RELU) v = fmaxf(v, 0.f);
            long ci = (long)gm * Nc + gn;
            if (ACC) v += C[ci];
            C[ci] = v;
        }
    }
}

// ---------------- per-row max + inverse sum of exp(relu(x)-mx) ----------------
__global__ void rowstat_kernel(const float* __restrict__ g, float* __restrict__ mx,
                               float* __restrict__ invs)
{
    long row = (long)blockIdx.x * 8 + (threadIdx.x >> 5);
    if (row >= (long)TN) return;
    int lane = threadIdx.x & 31;
    const float4* p = reinterpret_cast<const float4*>(g + row * NPTS);  // 100 float4
    float4 vv[4];
    float m = 0.f;
    #pragma unroll
    for (int r = 0; r < 4; r++) {
        int c = lane + r * 32;
        vv[r] = (c < 100) ? p[c] : make_float4(0.f, 0.f, 0.f, 0.f);
        m = fmaxf(m, fmaxf(fmaxf(vv[r].x, vv[r].y), fmaxf(vv[r].z, vv[r].w)));
    }
    #pragma unroll
    for (int o = 16; o > 0; o >>= 1) m = fmaxf(m, __shfl_xor_sync(~0u, m, o));
    float s = 0.f;
    #pragma unroll
    for (int r = 0; r < 4; r++) {
        int c = lane + r * 32;
        if (c < 100) {
            s += __expf(fmaxf(vv[r].x, 0.f) - m) + __expf(fmaxf(vv[r].y, 0.f) - m)
               + __expf(fmaxf(vv[r].z, 0.f) - m) + __expf(fmaxf(vv[r].w, 0.f) - m);
        }
    }
    #pragma unroll
    for (int o = 16; o > 0; o >>= 1) s += __shfl_xor_sync(~0u, s, o);
    if (lane == 0) { mx[row] = m; invs[row] = 1.f / s; }
}

// ---------------- input proj + concat adaptive embedding ----------------------
__global__ void hcat_kernel(const float* __restrict__ x, const float* __restrict__ W_in,
                            const float* __restrict__ b_in, const float* __restrict__ adp,
                            float* __restrict__ hcat)
{
    long idx = (long)blockIdx.x * 256 + threadIdx.x;
    if (idx >= (long)TN * DD) return;
    long tn = idx / DD; int j = (int)(idx - tn * DD);
    int t = (int)(tn / NPTS), n = (int)(tn - (long)t * NPTS);
    float v;
    if (j < 24) {
        const float* xr = x + ((long)n * TT + t) * 3;
        v = b_in[j] + xr[0] * W_in[0 * 24 + j] + xr[1] * W_in[1 * 24 + j] + xr[2] * W_in[2 * 24 + j];
    } else {
        v = adp[tn * 80 + (j - 24)];
    }
    hcat[idx] = v;
}

// ---------------- linear attention: kvs + ksum (warp-parallel over L) ---------
// block = (b, h), 256 threads = 8 warps, each warp a contiguous L-chunk.
// lane d (<26) owns kvs column d; accumulates acc[m] = sum k[m]*inv*v[d].
__global__ void kvs_kernel(const float* __restrict__ qkv, long sB, long sL, int L,
                           float* __restrict__ kvs, float* __restrict__ ksum)
{
    int b = blockIdx.x, h = blockIdx.y;
    int w = threadIdx.x >> 5, lane = threadIdx.x & 31;
    int chunk = (L + 7) >> 3;
    int l0 = w * chunk, l1 = min(L, l0 + chunk);
    const float* base = qkv + (long)b * sB + h * HD;
    float acc[HD];
    #pragma unroll
    for (int m = 0; m < HD; m++) acc[m] = 0.f;
    float accs = 0.f;
    for (int l = l0; l < l1; l++) {
        const float* row = base + (long)l * sL;
        float kk = (lane < HD) ? row[DD + lane] : 0.f;
        float vv = (lane < HD) ? row[2 * DD + lane] : 0.f;
        float ss = kk * kk;
        #pragma unroll
        for (int o = 16; o > 0; o >>= 1) ss += __shfl_xor_sync(~0u, ss, o);
        float inv = 1.f / fmaxf(sqrtf(ss), 1e-12f);
        float kin = kk * inv;
        accs += kin;          // lane m owns ksum[m]
        #pragma unroll
        for (int m = 0; m < HD; m++) {
            float km = __shfl_sync(~0u, kin, m);
            acc[m] += km * vv;
        }
    }
    __shared__ float red[8][HD][HD + 2];
    __shared__ float redk[8][32];
    if (lane < HD) {
        #pragma unroll
        for (int m = 0; m < HD; m++) red[w][m][lane] = acc[m];
    }
    redk[w][lane] = accs;
    __syncthreads();
    long basec = ((long)b * HH + h);
    for (int cell = threadIdx.x; cell < HD * HD; cell += 256) {
        int m = cell / HD, d = cell - m * HD;
        float s = 0.f;
        #pragma unroll
        for (int ww = 0; ww < 8; ww++) s += red[ww][m][d];
        kvs[basec * (HD * HD) + cell] = s;
    }
    if (threadIdx.x < HD) {
        float s = 0.f;
        #pragma unroll
        for (int ww = 0; ww < 8; ww++) s += redk[ww][threadIdx.x];
        ksum[basec * HD + threadIdx.x] = s;
    }
}

// ---------------- linear attention: per-token output --------------------------
__global__ void attnout_kernel(const float* __restrict__ qkv, long sB, long sL, int L,
                               const float* __restrict__ kvs, const float* __restrict__ ksum,
                               float* __restrict__ outb, long oB, long oL, int ooff)
{
    int l = blockIdx.x, b = blockIdx.y;
    int tid = threadIdx.x;
    const float* row = qkv + (long)b * sB + (long)l * sL;
    __shared__ float sq[DD], sv[DD], sinv[HH], sden[HH];
    if (tid < DD) { sq[tid] = row[tid]; sv[tid] = row[2 * DD + tid]; }
    __syncthreads();
    if (tid < HH) {
        const float* qh = sq + tid * HD;
        float ss = 0.f;
        #pragma unroll
        for (int m = 0; m < HD; m++) ss += qh[m] * qh[m];
        float inv = 1.f / fmaxf(sqrtf(ss), 1e-12f);
        sinv[tid] = inv;
        const float* ks = ksum + ((long)b * HH + tid) * HD;
        float dd = 0.f;
        #pragma unroll
        for (int m = 0; m < HD; m++) dd += qh[m] * ks[m];
        sden[tid] = dd * inv + (float)L;
    }
    __syncthreads();
    if (tid < DD) {
        int h = tid / HD, d = tid - h * HD;
        const float* kv = kvs + ((long)b * HH + h) * (HD * HD) + d;
        const float* qh = sq + h * HD;
        float s = 0.f;
        #pragma unroll
        for (int m = 0; m < HD; m++) s += qh[m] * kv[m * HD];
        float num = s * sinv[h] + (float)L * sv[tid];
        outb[((long)b * oB + (long)l * oL) * D2 + ooff + tid] = num / sden[h];
    }
}

// ---------------- fused combine + LayerNorm -----------------------------------
__global__ void combine_ln_kernel(const float* __restrict__ h, const float* __restrict__ a0,
                                  const float* __restrict__ a1, const float* __restrict__ p0,
                                  const float* __restrict__ p1, const float* __restrict__ gam,
                                  const float* __restrict__ bet, float* __restrict__ out)
{
    long row = blockIdx.x; int tid = threadIdx.x;  // 128
    __shared__ float red[4];
    long i = row * DD + tid;
    float v = 0.f;
    if (tid < DD) v = 2.f * (h[i] + a0[i] * p0[i] + 0.01f * a1[i] * p1[i]);
    float s = (tid < DD) ? v : 0.f;
    #pragma unroll
    for (int o = 16; o > 0; o >>= 1) s += __shfl_xor_sync(~0u, s, o);
    if ((tid & 31) == 0) red[tid >> 5] = s;
    __syncthreads();
    float mean = (red[0] + red[1] + red[2] + red[3]) / (float)DD;
    __syncthreads();
    float d = (tid < DD) ? (v - mean) : 0.f;
    float s2 = d * d;
    #pragma unroll
    for (int o = 16; o > 0; o >>= 1) s2 += __shfl_xor_sync(~0u, s2, o);
    if ((tid & 31) == 0) red[tid >> 5] = s2;
    __syncthreads();
    float var = (red[0] + red[1] + red[2] + red[3]) / (float)DD;
    if (tid < DD) out[i] = d * rsqrtf(var + 1e-5f) * gam[tid] + bet[tid];
}

__global__ void ln_res_kernel(const float* __restrict__ a, const float* __restrict__ b,
                              const float* __restrict__ gam, const float* __restrict__ bet,
                              float* __restrict__ out)
{
    long row = blockIdx.x; int tid = threadIdx.x;  // 128
    __shared__ float red[4];
    long i = row * DD + tid;
    float v = 0.f;
    if (tid < DD) v = a[i] + b[i];
    float s = (tid < DD) ? v : 0.f;
    #pragma unroll
    for (int o = 16; o > 0; o >>= 1) s += __shfl_xor_sync(~0u, s, o);
    if ((tid & 31) == 0) red[tid >> 5] = s;
    __syncthreads();
    float mean = (red[0] + red[1] + red[2] + red[3]) / (float)DD;
    __syncthreads();
    float d = (tid < DD) ? (v - mean) : 0.f;
    float s2 = d * d;
    #pragma unroll
    for (int o = 16; o > 0; o >>= 1) s2 += __shfl_xor_sync(~0u, s2, o);
    if ((tid & 31) == 0) red[tid >> 5] = s2;
    __syncthreads();
    float var = (red[0] + red[1] + red[2] + red[3]) / (float)DD;
    if (tid < DD) out[i] = d * rsqrtf(var + 1e-5f) * gam[tid] + bet[tid];
}

// ---------------- [T,N,D] -> [N, T*D] transpose -------------------------------
__global__ void transpose_h2_kernel(const float* __restrict__ h2, float* __restrict__ h2t)
{
    long idx = (long)blockIdx.x * 256 + threadIdx.x;
    if (idx >= (long)TN * DD) return;
    long t = idx / ((long)NPTS * DD);
    long r = idx - t * ((long)NPTS * DD);
    long n = r / DD;
    long d = r - n * DD;
    h2t[n * (long)TD + t * DD + d] = h2[idx];
}

// ---------------- split-K deterministic reduction -----------------------------
__global__ void splitk_reduce_kernel(const float* __restrict__ part, const float* __restrict__ bias,
                                     float* __restrict__ y, int MN, int Z, int Nc)
{
    int i = blockIdx.x * 256 + threadIdx.x;
    if (i >= MN) return;
    float s = bias[i % Nc];
    for (int z = 0; z < Z; z++) s += part[(long)z * MN + i];
    y[i] = s;
}

#define GEMM(TB,RL,AC,SP,SX, gx,gy,gz, A,B,bias,C, M,K,Nc, sA,sB,sC, mx,iv) \
    gemm_kernel<TB,RL,AC,SP,SX><<<dim3(gx,gy,gz), 256>>>(A,B,bias,C,M,K,Nc,sA,sB,sC,mx,iv)

// ---------------- host orchestration ------------------------------------------
static void run_attention(const float* x4, const float* qw, const float* ow, const float* ob,
                          float* qkv, float* kvs, float* ksum, float* cat2, float* attout)
{
    GEMM(false,false,false,false,false, 5, (TN+127)/128, 1,
         x4, qw, nullptr, qkv, TN, DD, D3, 0,0,0, nullptr,nullptr);
    // spatial: b = t (B=TT), l = n (L=NPTS)
    kvs_kernel<<<dim3(TT, HH), 256>>>(qkv, (long)NPTS * D3, (long)D3, NPTS, kvs, ksum);
    attnout_kernel<<<dim3(NPTS, TT), 128>>>(qkv, (long)NPTS * D3, (long)D3, NPTS, kvs, ksum,
                                            cat2, (long)NPTS, 1, 0);
    // temporal: b = n (B=NPTS), l = t (L=TT)
    kvs_kernel<<<dim3(NPTS, HH), 256>>>(qkv, (long)D3, (long)NPTS * D3, TT, kvs, ksum);
    attnout_kernel<<<dim3(TT, NPTS), 128>>>(qkv, (long)D3, (long)NPTS * D3, TT, kvs, ksum,
                                            cat2, 1, (long)NPTS, DD);
    GEMM(false,false,false,false,false, 2, (TN+127)/128, 1,
         cat2, ow, ob, attout, TN, D2, DD, 0,0,0, nullptr,nullptr);
}

extern "C" void kernel_launch(void* const* d_in, const int* in_sizes, int n_in,
                              void* d_out, int out_size)
{
    (void)in_sizes; (void)n_in; (void)out_size;
    const float* x     = (const float*)d_in[0];
    const float* W_in  = (const float*)d_in[1];
    const float* b_in  = (const float*)d_in[2];
    const float* adp   = (const float*)d_in[3];
    const float* W_tp  = (const float*)d_in[4];
    const float* b_tp  = (const float*)d_in[5];
    const float* qkv_w = (const float*)d_in[6];
    const float* op_w  = (const float*)d_in[7];
    const float* op_b  = (const float*)d_in[8];
    const float* pw_w  = (const float*)d_in[9];
    const float* pw_b  = (const float*)d_in[10];
    const float* fc_w1 = (const float*)d_in[11];
    const float* fc_b1 = (const float*)d_in[12];
    const float* fc_w2 = (const float*)d_in[13];
    const float* fc_b2 = (const float*)d_in[14];
    const float* ln1_g = (const float*)d_in[15];
    const float* ln1_b = (const float*)d_in[16];
    const float* ln2_g = (const float*)d_in[17];
    const float* ln2_b = (const float*)d_in[18];
    const float* ep_w  = (const float*)d_in[19];
    const float* ep_b  = (const float*)d_in[20];
    const float* enc_w1= (const float*)d_in[21];
    const float* enc_b1= (const float*)d_in[22];
    const float* enc_w2= (const float*)d_in[23];
    const float* enc_b2= (const float*)d_in[24];
    const float* out_w = (const float*)d_in[25];
    const float* out_b = (const float*)d_in[26];
    float* out = (float*)d_out;

    float *hcat, *h, *graph, *mxp, *invs, *z1, *qkv, *kvs, *ksum, *cat2, *att0, *att1;
    float *p0, *p1, *h1, *t2, *h2, *h2t, *part, *y, *yh;
    cudaGetSymbolAddress((void**)&hcat, g_hcat);
    cudaGetSymbolAddress((void**)&h,    g_h);
    cudaGetSymbolAddress((void**)&graph,g_graph);
    cudaGetSymbolAddress((void**)&mxp,  g_mx);
    cudaGetSymbolAddress((void**)&invs, g_invs);
    cudaGetSymbolAddress((void**)&z1,   g_z1);
    cudaGetSymbolAddress((void**)&qkv,  g_qkv);
    cudaGetSymbolAddress((void**)&kvs,  g_kvs);
    cudaGetSymbolAddress((void**)&ksum, g_ksum);
    cudaGetSymbolAddress((void**)&cat2, g_cat2);
    cudaGetSymbolAddress((void**)&att0, g_att0);
    cudaGetSymbolAddress((void**)&att1, g_att1);
    cudaGetSymbolAddress((void**)&p0,   g_p0);
    cudaGetSymbolAddress((void**)&p1,   g_p1);
    cudaGetSymbolAddress((void**)&h1,   g_h1);
    cudaGetSymbolAddress((void**)&t2,   g_t2);
    cudaGetSymbolAddress((void**)&h2,   g_h2);
    cudaGetSymbolAddress((void**)&h2t,  g_h2t);
    cudaGetSymbolAddress((void**)&part, g_part);
    cudaGetSymbolAddress((void**)&y,    g_y);
    cudaGetSymbolAddress((void**)&yh,   g_yh);

    const int MY = (TN + 127) / 128;   // 1141

    hcat_kernel<<<((long)TN * DD + 255) / 256, 256>>>(x, W_in, b_in, adp, hcat);
    GEMM(false,false,false,false,false, 2, MY, 1,
         hcat, W_tp, b_tp, h, TN, DD, DD, 0,0,0, nullptr,nullptr);
    GEMM(true,false,false,false,false, 7, 4, TT,
         adp, adp, nullptr, graph, NPTS, 80, NPTS,
         (long)NPTS*80, (long)NPTS*80, (long)NPTS*NPTS, nullptr,nullptr);
    rowstat_kernel<<<(TN + 7) / 8, 256>>>(graph, mxp, invs);
    GEMM(false,false,false,false,true, 2, 4, TT,
         graph, h, nullptr, z1, NPTS, NPTS, DD,
         (long)NPTS*NPTS, (long)NPTS*DD, (long)NPTS*DD, mxp, invs);
    run_attention(h,  qkv_w,            op_w,           op_b,       qkv, kvs, ksum, cat2, att0);
    run_attention(z1, qkv_w + DD * D3,  op_w + D2 * DD, op_b + DD,  qkv, kvs, ksum, cat2, att1);
    GEMM(false,false,false,false,false, 2, MY, 1,
         h,    pw_w,           pw_b,      p0, TN, DD, DD, 0,0,0, nullptr,nullptr);
    GEMM(false,false,false,false,false, 2, MY, 1,
         att0, pw_w + DD * DD, pw_b + DD, p1, TN, DD, DD, 0,0,0, nullptr,nullptr);
    combine_ln_kernel<<<TN, 128>>>(h, att0, att1, p0, p1, ln1_g, ln1_b, h1);
    GEMM(false,true,false,false,false, 4, MY, 1,
         h1, fc_w1, fc_b1, cat2, TN, DD, D2, 0,0,0, nullptr,nullptr);
    GEMM(false,false,false,false,false, 2, MY, 1,
         cat2, fc_w2, fc_b2, t2, TN, D2, DD, 0,0,0, nullptr,nullptr);
    ln_res_kernel<<<TN, 128>>>(h1, t2, ln2_g, ln2_b, h2);
    transpose_h2_kernel<<<((long)TN * DD + 255) / 256, 256>>>(h2, h2t);
    GEMM(false,false,false,true,false, 2, 4, SPLITK,
         h2t, ep_w, nullptr, part, NPTS, TD, DD, 0,0,0, nullptr,nullptr);
    splitk_reduce_kernel<<<(NPTS * DD + 255) / 256, 256>>>(part, ep_b, y, NPTS * DD, SPLITK, DD);
    for (int i = 0; i < 3; i++) {
        GEMM(false,true,false,false,false, 4, 4, 1,
             y,  enc_w1 + (long)i * DD * D2, enc_b1 + (long)i * D2, yh, NPTS, DD, D2, 0,0,0, nullptr,nullptr);
        GEMM(false,false,true,false,false, 2, 4, 1,
             yh, enc_w2 + (long)i * D2 * DD, enc_b2 + (long)i * DD, y,  NPTS, D2, DD, 0,0,0, nullptr,nullptr);
    }
    GEMM(false,false,false,false,false, 6, 4, 1,
         y, out_w, out_b, out, NPTS, DD, TT, 0,0,0, nullptr,nullptr);
}

// round 4
// speedup vs baseline: 1.3036x; 1.0272x over previous
#include <cuda_runtime.h>
#include <math.h>

#define TT   365
#define NPTS 400
#define DD   104
#define HH   4
#define HD   26
#define TN   (TT*NPTS)      // 146000
#define D2   (2*DD)         // 208
#define D3   (3*DD)         // 312
#define TD   (TT*DD)        // 37960
#define SPLITK 40
#define KCHUNK 960

// ---------------- scratch (device globals; no runtime allocation) -------------
__device__ float g_hcat[(size_t)TN*DD];
__device__ float g_h   [(size_t)TN*DD];
__device__ float g_graph[(size_t)TT*NPTS*NPTS];
__device__ float g_mx  [(size_t)TN];
__device__ float g_invs[(size_t)TN];
__device__ float g_z1  [(size_t)TN*DD];
__device__ float g_qkv [(size_t)TN*D3];
__device__ float g_kvs [(size_t)NPTS*HH*HD*HD];
__device__ float g_ksum[(size_t)NPTS*HH*HD];
__device__ float g_cat2[(size_t)TN*D2];
__device__ float g_att0[(size_t)TN*DD];
__device__ float g_att1[(size_t)TN*DD];
__device__ float g_p0  [(size_t)TN*DD];
__device__ float g_p1  [(size_t)TN*DD];
__device__ float g_h1  [(size_t)TN*DD];
__device__ float g_t2  [(size_t)TN*DD];
__device__ float g_h2  [(size_t)TN*DD];
__device__ float g_h2t [(size_t)NPTS*TD];
__device__ float g_part[(size_t)SPLITK*NPTS*DD];
__device__ float g_y   [(size_t)NPTS*DD];
__device__ float g_yh  [(size_t)NPTS*D2];

// ---------------- tiled fp32 GEMM: 128x64 tile, 8x4 microtile, FFMA2 ----------
// m-paired f32x2 accumulators: acc2[i2][j] holds rows (tm+2*i2, tm+2*i2+1) for
// column tn+j. A pairs load natively packed via ld.shared.v2.b64 (no packing);
// B broadcasts need 4 mov.b64 per k-step.

template<bool SMAX>
__device__ __forceinline__ void load_a(const float* __restrict__ A, int bm, int k0, int kend,
                                       int M, int K, const float* __restrict__ mxp,
                                       const float* __restrict__ ivp, int tid,
                                       float4& r0, float4& r1)
{
    #pragma unroll
    for (int rep = 0; rep < 2; rep++) {
        int idx = tid + rep * 256;
        int m  = idx >> 2;
        int kq = (idx & 3) << 2;
        int gm = bm + m, gk = k0 + kq;
        float4 av = make_float4(0.f, 0.f, 0.f, 0.f);
        if (gm < M && gk < kend) {
            av = *reinterpret_cast<const float4*>(A + (long)gm * K + gk);
            if (SMAX) {
                float mm = mxp[gm], iv = ivp[gm];
                av.x = __expf(fmaxf(av.x, 0.f) - mm) * iv;
                av.y = __expf(fmaxf(av.y, 0.f) - mm) * iv;
                av.z = __expf(fmaxf(av.z, 0.f) - mm) * iv;
                av.w = __expf(fmaxf(av.w, 0.f) - mm) * iv;
            }
        }
        if (rep == 0) r0 = av; else r1 = av;
    }
}

__device__ __forceinline__ void store_a(float (*As)[128], int tid, float4 r0, float4 r1)
{
    #pragma unroll
    for (int rep = 0; rep < 2; rep++) {
        float4 av = (rep == 0) ? r0 : r1;
        int idx = tid + rep * 256;
        int m  = idx >> 2;
        int kq = (idx & 3) << 2;
        As[kq + 0][m] = av.x; As[kq + 1][m] = av.y;
        As[kq + 2][m] = av.z; As[kq + 3][m] = av.w;
    }
}

template<bool TRANSB>
__device__ __forceinline__ void load_b(const float* __restrict__ B, int bn, int k0, int kend,
                                       int Nc, int K, int tid, float4& rt, float* rs)
{
    if (TRANSB) {
        int n  = tid >> 2;
        int kq = (tid & 3) << 2;
        int gn = bn + n, gk = k0 + kq;
        rt = make_float4(0.f, 0.f, 0.f, 0.f);
        if (gn < Nc && gk < kend)
            rt = *reinterpret_cast<const float4*>(B + (long)gn * K + gk);
    } else {
        int k  = tid >> 4;
        int n4 = (tid & 15) << 2;
        int gk = k0 + k;
        #pragma unroll
        for (int j = 0; j < 4; j++) {
            int gn = bn + n4 + j;
            rs[j] = (gk < kend && gn < Nc) ? B[(long)gk * Nc + gn] : 0.f;
        }
    }
}

template<bool TRANSB>
__device__ __forceinline__ void store_b(float (*Bs)[64], int tid, float4 rt, const float* rs)
{
    if (TRANSB) {
        int n  = tid >> 2;
        int kq = (tid & 3) << 2;
        Bs[kq + 0][n] = rt.x; Bs[kq + 1][n] = rt.y;
        Bs[kq + 2][n] = rt.z; Bs[kq + 3][n] = rt.w;
    } else {
        int k  = tid >> 4;
        int n4 = (tid & 15) << 2;
        #pragma unroll
        for (int j = 0; j < 4; j++) Bs[k][n4 + j] = rs[j];
    }
}

// asA/asB: shared-space u32 addresses of current As/Bs buffers.
__device__ __forceinline__ void mma_tile(unsigned asA, unsigned asB, int tm, int tn,
                                         unsigned long long (*acc2)[4])
{
    #pragma unroll
    for (int k = 0; k < 16; k++) {
        unsigned long long A01, A23, A45, A67;
        unsigned aAddr = asA + (unsigned)(k * 128 + tm) * 4u;
        asm("ld.shared.v2.b64 {%0,%1}, [%2];" : "=l"(A01), "=l"(A23) : "r"(aAddr));
        asm("ld.shared.v2.b64 {%0,%1}, [%2];" : "=l"(A45), "=l"(A67) : "r"(aAddr + 16u));
        float bx, by, bz, bw;
        unsigned bAddr = asB + (unsigned)(k * 64 + tn) * 4u;
        asm("ld.shared.v4.f32 {%0,%1,%2,%3}, [%4];"
            : "=f"(bx), "=f"(by), "=f"(bz), "=f"(bw) : "r"(bAddr));
        unsigned long long B0, B1, B2, B3;
        asm("mov.b64 %0,{%1,%1};" : "=l"(B0) : "f"(bx));
        asm("mov.b64 %0,{%1,%1};" : "=l"(B1) : "f"(by));
        asm("mov.b64 %0,{%1,%1};" : "=l"(B2) : "f"(bz));
        asm("mov.b64 %0,{%1,%1};" : "=l"(B3) : "f"(bw));
        asm("fma.rn.f32x2 %0,%1,%2,%0;" : "+l"(acc2[0][0]) : "l"(A01), "l"(B0));
        asm("fma.rn.f32x2 %0,%1,%2,%0;" : "+l"(acc2[0][1]) : "l"(A01), "l"(B1));
        asm("fma.rn.f32x2 %0,%1,%2,%0;" : "+l"(acc2[0][2]) : "l"(A01), "l"(B2));
        asm("fma.rn.f32x2 %0,%1,%2,%0;" : "+l"(acc2[0][3]) : "l"(A01), "l"(B3));
        asm("fma.rn.f32x2 %0,%1,%2,%0;" : "+l"(acc2[1][0]) : "l"(A23), "l"(B0));
        asm("fma.rn.f32x2 %0,%1,%2,%0;" : "+l"(acc2[1][1]) : "l"(A23), "l"(B1));
        asm("fma.rn.f32x2 %0,%1,%2,%0;" : "+l"(acc2[1][2]) : "l"(A23), "l"(B2));
        asm("fma.rn.f32x2 %0,%1,%2,%0;" : "+l"(acc2[1][3]) : "l"(A23), "l"(B3));
        asm("fma.rn.f32x2 %0,%1,%2,%0;" : "+l"(acc2[2][0]) : "l"(A45), "l"(B0));
        asm("fma.rn.f32x2 %0,%1,%2,%0;" : "+l"(acc2[2][1]) : "l"(A45), "l"(B1));
        asm("fma.rn.f32x2 %0,%1,%2,%0;" : "+l"(acc2[2][2]) : "l"(A45), "l"(B2));
        asm("fma.rn.f32x2 %0,%1,%2,%0;" : "+l"(acc2[2][3]) : "l"(A45), "l"(B3));
        asm("fma.rn.f32x2 %0,%1,%2,%0;" : "+l"(acc2[3][0]) : "l"(A67), "l"(B0));
        asm("fma.rn.f32x2 %0,%1,%2,%0;" : "+l"(acc2[3][1]) : "l"(A67), "l"(B1));
        asm("fma.rn.f32x2 %0,%1,%2,%0;" : "+l"(acc2[3][2]) : "l"(A67), "l"(B2));
        asm("fma.rn.f32x2 %0,%1,%2,%0;" : "+l"(acc2[3][3]) : "l"(A67), "l"(B3));
    }
}

template<bool TRANSB, bool RELU, bool ACC, bool SPLIT, bool SMAX>
__global__ void gemm_kernel(const float* __restrict__ A, const float* __restrict__ B,
                            const float* __restrict__ bias, float* __restrict__ C,
                            int M, int K, int Nc, long sA, long sB_, long sC,
                            const float* __restrict__ mx, const float* __restrict__ invs)
{
    __shared__ float As[2][16][128];
    __shared__ float Bs[2][16][64];
    int tid = threadIdx.x;
    int bm = blockIdx.y * 128, bn = blockIdx.x * 64;
    int kbeg = 0, kend = K;
    const float* mxp = mx;
    const float* ivp = invs;
    if (SPLIT) {
        int z = blockIdx.z;
        kbeg = z * KCHUNK;
        kend = min(K, kbeg + KCHUNK);
        C += (long)z * M * Nc;
    } else {
        int z = blockIdx.z;
        A += z * sA; B += z * sB_; C += z * sC;
        if (SMAX) { mxp += (long)z * M; ivp += (long)z * M; }
    }
    int tm = (tid >> 4) << 3;
    int tn = (tid & 15) << 2;
    unsigned long long acc2[4][4];
    #pragma unroll
    for (int i = 0; i < 4; i++)
        #pragma unroll
        for (int j = 0; j < 4; j++) acc2[i][j] = 0ull;

    unsigned asA = (unsigned)__cvta_generic_to_shared(&As[0][0][0]);
    unsigned asB = (unsigned)__cvta_generic_to_shared(&Bs[0][0][0]);
    const unsigned aBufB = 16u * 128u * 4u;
    const unsigned bBufB = 16u * 64u * 4u;

    int nk = (kend - kbeg + 15) >> 4;
    float4 ra0, ra1, rbt; float rbs[4];
    load_a<SMAX>(A, bm, kbeg, kend, M, K, mxp, ivp, tid, ra0, ra1);
    load_b<TRANSB>(B, bn, kbeg, kend, Nc, K, tid, rbt, rbs);
    store_a(As[0], tid, ra0, ra1);
    store_b<TRANSB>(Bs[0], tid, rbt, rbs);
    __syncthreads();
    int buf = 0;
    for (int it = 0; it < nk; it++) {
        bool has_next = (it + 1 < nk);
        if (has_next) {
            int kn = kbeg + (it + 1) * 16;
            load_a<SMAX>(A, bm, kn, kend, M, K, mxp, ivp, tid, ra0, ra1);
            load_b<TRANSB>(B, bn, kn, kend, Nc, K, tid, rbt, rbs);
        }
        mma_tile(asA + (unsigned)buf * aBufB, asB + (unsigned)buf * bBufB, tm, tn, acc2);
        if (has_next) {
            store_a(As[buf ^ 1], tid, ra0, ra1);
            store_b<TRANSB>(Bs[buf ^ 1], tid, rbt, rbs);
            __syncthreads();
            buf ^= 1;
        }
    }
    #pragma unroll
    for (int i2 = 0; i2 < 4; i2++) {
        #pragma unroll
        for (int j = 0; j < 4; j++) {
            float v0, v1;
            asm("mov.b64 {%0,%1}, %2;" : "=f"(v0), "=f"(v1) : "l"(acc2[i2][j]));
            int gn = bn + tn + j; if (gn >= Nc) continue;
            float bb = (!SPLIT && bias) ? bias[gn] : 0.f;
            int gm0 = bm + tm + 2 * i2;
            #pragma unroll
            for (int half = 0; half < 2; half++) {
                int gm = gm0 + half;
                if (gm >= M) continue;
                float v = (half == 0 ? v0 : v1) + bb;
                if (RELU) v = fmaxf(v, 0.f);
                long ci = (long)gm * Nc + gn;
                if (ACC) v += C[ci];
                C[ci] = v;
            }
        }
    }
}

// ---------------- per-row max + inverse sum of exp(relu(x)-mx) ----------------
__global__ void rowstat_kernel(const float* __restrict__ g, float* __restrict__ mx,
                               float* __restrict__ invs)
{
    long row = (long)blockIdx.x * 8 + (threadIdx.x >> 5);
    if (row >= (long)TN) return;
    int lane = threadIdx.x & 31;
    const float4* p = reinterpret_cast<const float4*>(g + row * NPTS);  // 100 float4
    float4 vv[4];
    float m = 0.f;
    #pragma unroll
    for (int r = 0; r < 4; r++) {
        int c = lane + r * 32;
        vv[r] = (c < 100) ? p[c] : make_float4(0.f, 0.f, 0.f, 0.f);
        m = fmaxf(m, fmaxf(fmaxf(vv[r].x, vv[r].y), fmaxf(vv[r].z, vv[r].w)));
    }
    #pragma unroll
    for (int o = 16; o > 0; o >>= 1) m = fmaxf(m, __shfl_xor_sync(~0u, m, o));
    float s = 0.f;
    #pragma unroll
    for (int r = 0; r < 4; r++) {
        int c = lane + r * 32;
        if (c < 100) {
            s += __expf(fmaxf(vv[r].x, 0.f) - m) + __expf(fmaxf(vv[r].y, 0.f) - m)
               + __expf(fmaxf(vv[r].z, 0.f) - m) + __expf(fmaxf(vv[r].w, 0.f) - m);
        }
    }
    #pragma unroll
    for (int o = 16; o > 0; o >>= 1) s += __shfl_xor_sync(~0u, s, o);
    if (lane == 0) { mx[row] = m; invs[row] = 1.f / s; }
}

// ---------------- input proj + concat adaptive embedding ----------------------
__global__ void hcat_kernel(const float* __restrict__ x, const float* __restrict__ W_in,
                            const float* __restrict__ b_in, const float* __restrict__ adp,
                            float* __restrict__ hcat)
{
    long idx = (long)blockIdx.x * 256 + threadIdx.x;
    if (idx >= (long)TN * DD) return;
    long tn = idx / DD; int j = (int)(idx - tn * DD);
    int t = (int)(tn / NPTS), n = (int)(tn - (long)t * NPTS);
    float v;
    if (j < 24) {
        const float* xr = x + ((long)n * TT + t) * 3;
        v = b_in[j] + xr[0] * W_in[0 * 24 + j] + xr[1] * W_in[1 * 24 + j] + xr[2] * W_in[2 * 24 + j];
    } else {
        v = adp[tn * 80 + (j - 24)];
    }
    hcat[idx] = v;
}

// ---------------- linear attention: kvs + ksum (warp-parallel over L) ---------
__global__ void kvs_kernel(const float* __restrict__ qkv, long sB, long sL, int L,
                           float* __restrict__ kvs, float* __restrict__ ksum)
{
    int b = blockIdx.x, h = blockIdx.y;
    int w = threadIdx.x >> 5, lane = threadIdx.x & 31;
    int chunk = (L + 7) >> 3;
    int l0 = w * chunk, l1 = min(L, l0 + chunk);
    const float* base = qkv + (long)b * sB + h * HD;
    float acc[HD];
    #pragma unroll
    for (int m = 0; m < HD; m++) acc[m] = 0.f;
    float accs = 0.f;
    for (int l = l0; l < l1; l++) {
        const float* row = base + (long)l * sL;
        float kk = (lane < HD) ? row[DD + lane] : 0.f;
        float vv = (lane < HD) ? row[2 * DD + lane] : 0.f;
        float ss = kk * kk;
        #pragma unroll
        for (int o = 16; o > 0; o >>= 1) ss += __shfl_xor_sync(~0u, ss, o);
        float inv = 1.f / fmaxf(sqrtf(ss), 1e-12f);
        float kin = kk * inv;
        accs += kin;
        #pragma unroll
        for (int m = 0; m < HD; m++) {
            float km = __shfl_sync(~0u, kin, m);
            acc[m] += km * vv;
        }
    }
    __shared__ float red[8][HD][HD + 2];
    __shared__ float redk[8][32];
    if (lane < HD) {
        #pragma unroll
        for (int m = 0; m < HD; m++) red[w][m][lane] = acc[m];
    }
    redk[w][lane] = accs;
    __syncthreads();
    long basec = ((long)b * HH + h);
    for (int cell = threadIdx.x; cell < HD * HD; cell += 256) {
        int m = cell / HD, d = cell - m * HD;
        float s = 0.f;
        #pragma unroll
        for (int ww = 0; ww < 8; ww++) s += red[ww][m][d];
        kvs[basec * (HD * HD) + cell] = s;
    }
    if (threadIdx.x < HD) {
        float s = 0.f;
        #pragma unroll
        for (int ww = 0; ww < 8; ww++) s += redk[ww][threadIdx.x];
        ksum[basec * HD + threadIdx.x] = s;
    }
}

// ---------------- linear attention: per-token output --------------------------
__global__ void attnout_kernel(const float* __restrict__ qkv, long sB, long sL, int L,
                               const float* __restrict__ kvs, const float* __restrict__ ksum,
                               float* __restrict__ outb, long oB, long oL, int ooff)
{
    int l = blockIdx.x, b = blockIdx.y;
    int tid = threadIdx.x;
    const float* row = qkv + (long)b * sB + (long)l * sL;
    __shared__ float sq[DD], sv[DD], sinv[HH], sden[HH];
    if (tid < DD) { sq[tid] = row[tid]; sv[tid] = row[2 * DD + tid]; }
    __syncthreads();
    if (tid < HH) {
        const float* qh = sq + tid * HD;
        float ss = 0.f;
        #pragma unroll
        for (int m = 0; m < HD; m++) ss += qh[m] * qh[m];
        float inv = 1.f / fmaxf(sqrtf(ss), 1e-12f);
        sinv[tid] = inv;
        const float* ks = ksum + ((long)b * HH + tid) * HD;
        float dd = 0.f;
        #pragma unroll
        for (int m = 0; m < HD; m++) dd += qh[m] * ks[m];
        sden[tid] = dd * inv + (float)L;
    }
    __syncthreads();
    if (tid < DD) {
        int h = tid / HD, d = tid - h * HD;
        const float* kv = kvs + ((long)b * HH + h) * (HD * HD) + d;
        const float* qh = sq + h * HD;
        float s = 0.f;
        #pragma unroll
        for (int m = 0; m < HD; m++) s += qh[m] * kv[m * HD];
        float num = s * sinv[h] + (float)L * sv[tid];
        outb[((long)b * oB + (long)l * oL) * D2 + ooff + tid] = num / sden[h];
    }
}

// ---------------- fused combine + LayerNorm -----------------------------------
__global__ void combine_ln_kernel(const float* __restrict__ h, const float* __restrict__ a0,
                                  const float* __restrict__ a1, const float* __restrict__ p0,
                                  const float* __restrict__ p1, const float* __restrict__ gam,
                                  const float* __restrict__ bet, float* __restrict__ out)
{
    long row = blockIdx.x; int tid = threadIdx.x;  // 128
    __shared__ float red[4];
    long i = row * DD + tid;
    float v = 0.f;
    if (tid < DD) v = 2.f * (h[i] + a0[i] * p0[i] + 0.01f * a1[i] * p1[i]);
    float s = (tid < DD) ? v : 0.f;
    #pragma unroll
    for (int o = 16; o > 0; o >>= 1) s += __shfl_xor_sync(~0u, s, o);
    if ((tid & 31) == 0) red[tid >> 5] = s;
    __syncthreads();
    float mean = (red[0] + red[1] + red[2] + red[3]) / (float)DD;
    __syncthreads();
    float d = (tid < DD) ? (v - mean) : 0.f;
    float s2 = d * d;
    #pragma unroll
    for (int o = 16; o > 0; o >>= 1) s2 += __shfl_xor_sync(~0u, s2, o);
    if ((tid & 31) == 0) red[tid >> 5] = s2;
    __syncthreads();
    float var = (red[0] + red[1] + red[2] + red[3]) / (float)DD;
    if (tid < DD) out[i] = d * rsqrtf(var + 1e-5f) * gam[tid] + bet[tid];
}

__global__ void ln_res_kernel(const float* __restrict__ a, const float* __restrict__ b,
                              const float* __restrict__ gam, const float* __restrict__ bet,
                              float* __restrict__ out)
{
    long row = blockIdx.x; int tid = threadIdx.x;  // 128
    __shared__ float red[4];
    long i = row * DD + tid;
    float v = 0.f;
    if (tid < DD) v = a[i] + b[i];
    float s = (tid < DD) ? v : 0.f;
    #pragma unroll
    for (int o = 16; o > 0; o >>= 1) s += __shfl_xor_sync(~0u, s, o);
    if ((tid & 31) == 0) red[tid >> 5] = s;
    __syncthreads();
    float mean = (red[0] + red[1] + red[2] + red[3]) / (float)DD;
    __syncthreads();
    float d = (tid < DD) ? (v - mean) : 0.f;
    float s2 = d * d;
    #pragma unroll
    for (int o = 16; o > 0; o >>= 1) s2 += __shfl_xor_sync(~0u, s2, o);
    if ((tid & 31) == 0) red[tid >> 5] = s2;
    __syncthreads();
    float var = (red[0] + red[1] + red[2] + red[3]) / (float)DD;
    if (tid < DD) out[i] = d * rsqrtf(var + 1e-5f) * gam[tid] + bet[tid];
}

// ---------------- [T,N,D] -> [N, T*D] transpose -------------------------------
__global__ void transpose_h2_kernel(const float* __restrict__ h2, float* __restrict__ h2t)
{
    long idx = (long)blockIdx.x * 256 + threadIdx.x;
    if (idx >= (long)TN * DD) return;
    long t = idx / ((long)NPTS * DD);
    long r = idx - t * ((long)NPTS * DD);
    long n = r / DD;
    long d = r - n * DD;
    h2t[n * (long)TD + t * DD + d] = h2[idx];
}

// ---------------- split-K deterministic reduction -----------------------------
__global__ void splitk_reduce_kernel(const float* __restrict__ part, const float* __restrict__ bias,
                                     float* __restrict__ y, int MN, int Z, int Nc)
{
    int i = blockIdx.x * 256 + threadIdx.x;
    if (i >= MN) return;
    float s = bias[i % Nc];
    for (int z = 0; z < Z; z++) s += part[(long)z * MN + i];
    y[i] = s;
}

#define GEMM(TB,RL,AC,SP,SX, gx,gy,gz, A,B,bias,C, M,K,Nc, sA,sB,sC, mx,iv) \
    gemm_kernel<TB,RL,AC,SP,SX><<<dim3(gx,gy,gz), 256>>>(A,B,bias,C,M,K,Nc,sA,sB,sC,mx,iv)

// ---------------- host orchestration ------------------------------------------
static void run_attention(const float* x4, const float* qw, const float* ow, const float* ob,
                          float* qkv, float* kvs, float* ksum, float* cat2, float* attout)
{
    GEMM(false,false,false,false,false, 5, (TN+127)/128, 1,
         x4, qw, nullptr, qkv, TN, DD, D3, 0,0,0, nullptr,nullptr);
    kvs_kernel<<<dim3(TT, HH), 256>>>(qkv, (long)NPTS * D3, (long)D3, NPTS, kvs, ksum);
    attnout_kernel<<<dim3(NPTS, TT), 128>>>(qkv, (long)NPTS * D3, (long)D3, NPTS, kvs, ksum,
                                            cat2, (long)NPTS, 1, 0);
    kvs_kernel<<<dim3(NPTS, HH), 256>>>(qkv, (long)D3, (long)NPTS * D3, TT, kvs, ksum);
    attnout_kernel<<<dim3(TT, NPTS), 128>>>(qkv, (long)D3, (long)NPTS * D3, TT, kvs, ksum,
                                            cat2, 1, (long)NPTS, DD);
    GEMM(false,false,false,false,false, 2, (TN+127)/128, 1,
         cat2, ow, ob, attout, TN, D2, DD, 0,0,0, nullptr,nullptr);
}

extern "C" void kernel_launch(void* const* d_in, const int* in_sizes, int n_in,
                              void* d_out, int out_size)
{
    (void)in_sizes; (void)n_in; (void)out_size;
    const float* x     = (const float*)d_in[0];
    const float* W_in  = (const float*)d_in[1];
    const float* b_in  = (const float*)d_in[2];
    const float* adp   = (const float*)d_in[3];
    const float* W_tp  = (const float*)d_in[4];
    const float* b_tp  = (const float*)d_in[5];
    const float* qkv_w = (const float*)d_in[6];
    const float* op_w  = (const float*)d_in[7];
    const float* op_b  = (const float*)d_in[8];
    const float* pw_w  = (const float*)d_in[9];
    const float* pw_b  = (const float*)d_in[10];
    const float* fc_w1 = (const float*)d_in[11];
    const float* fc_b1 = (const float*)d_in[12];
    const float* fc_w2 = (const float*)d_in[13];
    const float* fc_b2 = (const float*)d_in[14];
    const float* ln1_g = (const float*)d_in[15];
    const float* ln1_b = (const float*)d_in[16];
    const float* ln2_g = (const float*)d_in[17];
    const float* ln2_b = (const float*)d_in[18];
    const float* ep_w  = (const float*)d_in[19];
    const float* ep_b  = (const float*)d_in[20];
    const float* enc_w1= (const float*)d_in[21];
    const float* enc_b1= (const float*)d_in[22];
    const float* enc_w2= (const float*)d_in[23];
    const float* enc_b2= (const float*)d_in[24];
    const float* out_w = (const float*)d_in[25];
    const float* out_b = (const float*)d_in[26];
    float* out = (float*)d_out;

    float *hcat, *h, *graph, *mxp, *invs, *z1, *qkv, *kvs, *ksum, *cat2, *att0, *att1;
    float *p0, *p1, *h1, *t2, *h2, *h2t, *part, *y, *yh;
    cudaGetSymbolAddress((void**)&hcat, g_hcat);
    cudaGetSymbolAddress((void**)&h,    g_h);
    cudaGetSymbolAddress((void**)&graph,g_graph);
    cudaGetSymbolAddress((void**)&mxp,  g_mx);
    cudaGetSymbolAddress((void**)&invs, g_invs);
    cudaGetSymbolAddress((void**)&z1,   g_z1);
    cudaGetSymbolAddress((void**)&qkv,  g_qkv);
    cudaGetSymbolAddress((void**)&kvs,  g_kvs);
    cudaGetSymbolAddress((void**)&ksum, g_ksum);
    cudaGetSymbolAddress((void**)&cat2, g_cat2);
    cudaGetSymbolAddress((void**)&att0, g_att0);
    cudaGetSymbolAddress((void**)&att1, g_att1);
    cudaGetSymbolAddress((void**)&p0,   g_p0);
    cudaGetSymbolAddress((void**)&p1,   g_p1);
    cudaGetSymbolAddress((void**)&h1,   g_h1);
    cudaGetSymbolAddress((void**)&t2,   g_t2);
    cudaGetSymbolAddress((void**)&h2,   g_h2);
    cudaGetSymbolAddress((void**)&h2t,  g_h2t);
    cudaGetSymbolAddress((void**)&part, g_part);
    cudaGetSymbolAddress((void**)&y,    g_y);
    cudaGetSymbolAddress((void**)&yh,   g_yh);

    const int MY = (TN + 127) / 128;   // 1141

    hcat_kernel<<<((long)TN * DD + 255) / 256, 256>>>(x, W_in, b_in, adp, hcat);
    GEMM(false,false,false,false,false, 2, MY, 1,
         hcat, W_tp, b_tp, h, TN, DD, DD, 0,0,0, nullptr,nullptr);
    GEMM(true,false,false,false,false, 7, 4, TT,
         adp, adp, nullptr, graph, NPTS, 80, NPTS,
         (long)NPTS*80, (long)NPTS*80, (long)NPTS*NPTS, nullptr,nullptr);
    rowstat_kernel<<<(TN + 7) / 8, 256>>>(graph, mxp, invs);
    GEMM(false,false,false,false,true, 2, 4, TT,
         graph, h, nullptr, z1, NPTS, NPTS, DD,
         (long)NPTS*NPTS, (long)NPTS*DD, (long)NPTS*DD, mxp, invs);
    run_attention(h,  qkv_w,            op_w,           op_b,       qkv, kvs, ksum, cat2, att0);
    run_attention(z1, qkv_w + DD * D3,  op_w + D2 * DD, op_b + DD,  qkv, kvs, ksum, cat2, att1);
    GEMM(false,false,false,false,false, 2, MY, 1,
         h,    pw_w,           pw_b,      p0, TN, DD, DD, 0,0,0, nullptr,nullptr);
    GEMM(false,false,false,false,false, 2, MY, 1,
         att0, pw_w + DD * DD, pw_b + DD, p1, TN, DD, DD, 0,0,0, nullptr,nullptr);
    combine_ln_kernel<<<TN, 128>>>(h, att0, att1, p0, p1, ln1_g, ln1_b, h1);
    GEMM(false,true,false,false,false, 4, MY, 1,
         h1, fc_w1, fc_b1, cat2, TN, DD, D2, 0,0,0, nullptr,nullptr);
    GEMM(false,false,false,false,false, 2, MY, 1,
         cat2, fc_w2, fc_b2, t2, TN, D2, DD, 0,0,0, nullptr,nullptr);
    ln_res_kernel<<<TN, 128>>>(h1, t2, ln2_g, ln2_b, h2);
    transpose_h2_kernel<<<((long)TN * DD + 255) / 256, 256>>>(h2, h2t);
    GEMM(false,false,false,true,false, 2, 4, SPLITK,
         h2t, ep_w, nullptr, part, NPTS, TD, DD, 0,0,0, nullptr,nullptr);
    splitk_reduce_kernel<<<(NPTS * DD + 255) / 256, 256>>>(part, ep_b, y, NPTS * DD, SPLITK, DD);
    for (int i = 0; i < 3; i++) {
        GEMM(false,true,false,false,false, 4, 4, 1,
             y,  enc_w1 + (long)i * DD * D2, enc_b1 + (long)i * D2, yh, NPTS, DD, D2, 0,0,0, nullptr,nullptr);
        GEMM(false,false,true,false,false, 2, 4, 1,
             yh, enc_w2 + (long)i * D2 * DD, enc_b2 + (long)i * DD, y,  NPTS, D2, DD, 0,0,0, nullptr,nullptr);
    }
    GEMM(false,false,false,false,false, 6, 4, 1,
         y, out_w, out_b, out, NPTS, DD, TT, 0,0,0, nullptr,nullptr);
}

// round 5
// speedup vs baseline: 1.6127x; 1.2371x over previous
#include <cuda_runtime.h>
#include <math.h>

#define TT   365
#define NPTS 400
#define DD   104
#define HH   4
#define HD   26
#define TN   (TT*NPTS)      // 146000
#define D2   (2*DD)         // 208
#define D3   (3*DD)         // 312
#define TD   (TT*DD)        // 37960
#define SPLITK 40
#define KCHUNK 960
#define SMA  20              // smem row stride (16 k + 4 pad) — bank-conflict-free frags

// ---------------- scratch (device globals; no runtime allocation) -------------
__device__ float g_hcat[(size_t)TN*DD];
__device__ float g_h   [(size_t)TN*DD];
__device__ float g_graph[(size_t)TT*NPTS*NPTS];
__device__ float g_mx  [(size_t)TN];
__device__ float g_invs[(size_t)TN];
__device__ float g_z1  [(size_t)TN*DD];
__device__ float g_qkv [(size_t)TN*D3];
__device__ float g_kvs [(size_t)NPTS*HH*HD*HD];
__device__ float g_ksum[(size_t)NPTS*HH*HD];
__device__ float g_cat2[(size_t)TN*D2];
__device__ float g_att0[(size_t)TN*DD];
__device__ float g_att1[(size_t)TN*DD];
__device__ float g_p0  [(size_t)TN*DD];
__device__ float g_p1  [(size_t)TN*DD];
__device__ float g_h1  [(size_t)TN*DD];
__device__ float g_t2  [(size_t)TN*DD];
__device__ float g_h2  [(size_t)TN*DD];
__device__ float g_h2t [(size_t)NPTS*TD];
__device__ float g_part[(size_t)SPLITK*NPTS*DD];
__device__ float g_y   [(size_t)NPTS*DD];
__device__ float g_yh  [(size_t)NPTS*D2];

// ---------------- tf32 helpers -------------------------------------------------
__device__ __forceinline__ float cvt_tf32(float f)
{
    unsigned u;
    asm("cvt.rna.tf32.f32 %0, %1;" : "=r"(u) : "f"(f));
    return __uint_as_float(u);
}

// ---------------- tiled tf32-MMA GEMM: 128x64 block, 8 warps (4m x 2n) --------
// Each warp: 32x32 tile = 2(m) x 4(n) mma.m16n8k8 tiles, K chunked by 16.
// A smem [128][SMA] row-major-per-k-chunk; B smem [64][SMA] (n-major, k inner).
// Values stored already tf32-rounded. fp32 accumulate.

template<bool SMAX>
__device__ __forceinline__ void load_a(const float* __restrict__ A, int bm, int k0, int kend,
                                       int M, int K, const float* __restrict__ mxp,
                                       const float* __restrict__ ivp, int tid,
                                       float4& r0, float4& r1)
{
    #pragma unroll
    for (int rep = 0; rep < 2; rep++) {
        int idx = tid + rep * 256;
        int m  = idx >> 2;
        int kq = (idx & 3) << 2;
        int gm = bm + m, gk = k0 + kq;
        float4 av = make_float4(0.f, 0.f, 0.f, 0.f);
        if (gm < M && gk < kend) {
            av = *reinterpret_cast<const float4*>(A + (long)gm * K + gk);
            if (SMAX) {
                float mm = mxp[gm], iv = ivp[gm];
                av.x = __expf(fmaxf(av.x, 0.f) - mm) * iv;
                av.y = __expf(fmaxf(av.y, 0.f) - mm) * iv;
                av.z = __expf(fmaxf(av.z, 0.f) - mm) * iv;
                av.w = __expf(fmaxf(av.w, 0.f) - mm) * iv;
            }
            av.x = cvt_tf32(av.x); av.y = cvt_tf32(av.y);
            av.z = cvt_tf32(av.z); av.w = cvt_tf32(av.w);
        }
        if (rep == 0) r0 = av; else r1 = av;
    }
}

__device__ __forceinline__ void store_a(float* As, int tid, float4 r0, float4 r1)
{
    #pragma unroll
    for (int rep = 0; rep < 2; rep++) {
        float4 av = (rep == 0) ? r0 : r1;
        int idx = tid + rep * 256;
        int m  = idx >> 2;
        int kq = (idx & 3) << 2;
        *reinterpret_cast<float4*>(As + m * SMA + kq) = av;
    }
}

template<bool TRANSB>
__device__ __forceinline__ void load_b(const float* __restrict__ B, int bn, int k0, int kend,
                                       int Nc, int K, int tid, float4& rt, float* rs)
{
    if (TRANSB) {
        int n  = tid >> 2;
        int kq = (tid & 3) << 2;
        int gn = bn + n, gk = k0 + kq;
        rt = make_float4(0.f, 0.f, 0.f, 0.f);
        if (gn < Nc && gk < kend) {
            rt = *reinterpret_cast<const float4*>(B + (long)gn * K + gk);
            rt.x = cvt_tf32(rt.x); rt.y = cvt_tf32(rt.y);
            rt.z = cvt_tf32(rt.z); rt.w = cvt_tf32(rt.w);
        }
    } else {
        int k  = tid >> 4;
        int n4 = (tid & 15) << 2;
        int gk = k0 + k;
        #pragma unroll
        for (int j = 0; j < 4; j++) {
            int gn = bn + n4 + j;
            rs[j] = (gk < kend && gn < Nc) ? cvt_tf32(B[(long)gk * Nc + gn]) : 0.f;
        }
    }
}

template<bool TRANSB>
__device__ __forceinline__ void store_b(float* Bs, int tid, float4 rt, const float* rs)
{
    if (TRANSB) {
        int n  = tid >> 2;
        int kq = (tid & 3) << 2;
        *reinterpret_cast<float4*>(Bs + n * SMA + kq) = rt;
    } else {
        int k  = tid >> 4;
        int n4 = (tid & 15) << 2;
        #pragma unroll
        for (int j = 0; j < 4; j++) Bs[(n4 + j) * SMA + k] = rs[j];
    }
}

__device__ __forceinline__ void mma_chunk(const float* __restrict__ As,
                                          const float* __restrict__ Bs,
                                          int wm, int wn, int lane, float (*acc)[4][4])
{
    int r = lane >> 2, c = lane & 3;
    #pragma unroll
    for (int ks = 0; ks < 2; ks++) {
        int k0 = ks * 8;
        unsigned a[2][4], b[4][2];
        #pragma unroll
        for (int mt = 0; mt < 2; mt++) {
            const float* p = As + (wm * 32 + mt * 16 + r) * SMA + k0 + c;
            a[mt][0] = __float_as_uint(p[0]);
            a[mt][1] = __float_as_uint(p[8 * SMA]);
            a[mt][2] = __float_as_uint(p[4]);
            a[mt][3] = __float_as_uint(p[8 * SMA + 4]);
        }
        #pragma unroll
        for (int nt = 0; nt < 4; nt++) {
            const float* p = Bs + (wn * 32 + nt * 8 + r) * SMA + k0 + c;
            b[nt][0] = __float_as_uint(p[0]);
            b[nt][1] = __float_as_uint(p[4]);
        }
        #pragma unroll
        for (int mt = 0; mt < 2; mt++)
            #pragma unroll
            for (int nt = 0; nt < 4; nt++)
                asm("mma.sync.aligned.m16n8k8.row.col.f32.tf32.tf32.f32 "
                    "{%0,%1,%2,%3},{%4,%5,%6,%7},{%8,%9},{%0,%1,%2,%3};"
                    : "+f"(acc[mt][nt][0]), "+f"(acc[mt][nt][1]),
                      "+f"(acc[mt][nt][2]), "+f"(acc[mt][nt][3])
                    : "r"(a[mt][0]), "r"(a[mt][1]), "r"(a[mt][2]), "r"(a[mt][3]),
                      "r"(b[nt][0]), "r"(b[nt][1]));
    }
}

template<bool TRANSB, bool RELU, bool ACC, bool SPLIT, bool SMAX>
__global__ void gemm_kernel(const float* __restrict__ A, const float* __restrict__ B,
                            const float* __restrict__ bias, float* __restrict__ C,
                            int M, int K, int Nc, long sA, long sB_, long sC,
                            const float* __restrict__ mx, const float* __restrict__ invs)
{
    __shared__ float As[2][128 * SMA];
    __shared__ float Bs[2][64 * SMA];
    int tid = threadIdx.x;
    int bm = blockIdx.y * 128, bn = blockIdx.x * 64;
    int kbeg = 0, kend = K;
    const float* mxp = mx;
    const float* ivp = invs;
    if (SPLIT) {
        int z = blockIdx.z;
        kbeg = z * KCHUNK;
        kend = min(K, kbeg + KCHUNK);
        C += (long)z * M * Nc;
    } else {
        int z = blockIdx.z;
        A += z * sA; B += z * sB_; C += z * sC;
        if (SMAX) { mxp += (long)z * M; ivp += (long)z * M; }
    }
    int w = tid >> 5, lane = tid & 31;
    int wm = w >> 1, wn = w & 1;
    float acc[2][4][4];
    #pragma unroll
    for (int mt = 0; mt < 2; mt++)
        #pragma unroll
        for (int nt = 0; nt < 4; nt++)
            #pragma unroll
            for (int q = 0; q < 4; q++) acc[mt][nt][q] = 0.f;

    int nk = (kend - kbeg + 15) >> 4;
    float4 ra0, ra1, rbt; float rbs[4];
    load_a<SMAX>(A, bm, kbeg, kend, M, K, mxp, ivp, tid, ra0, ra1);
    load_b<TRANSB>(B, bn, kbeg, kend, Nc, K, tid, rbt, rbs);
    store_a(As[0], tid, ra0, ra1);
    store_b<TRANSB>(Bs[0], tid, rbt, rbs);
    __syncthreads();
    int buf = 0;
    for (int it = 0; it < nk; it++) {
        bool has_next = (it + 1 < nk);
        if (has_next) {
            int kn = kbeg + (it + 1) * 16;
            load_a<SMAX>(A, bm, kn, kend, M, K, mxp, ivp, tid, ra0, ra1);
            load_b<TRANSB>(B, bn, kn, kend, Nc, K, tid, rbt, rbs);
        }
        mma_chunk(As[buf], Bs[buf], wm, wn, lane, acc);
        if (has_next) {
            store_a(As[buf ^ 1], tid, ra0, ra1);
            store_b<TRANSB>(Bs[buf ^ 1], tid, rbt, rbs);
            __syncthreads();
            buf ^= 1;
        }
    }
    // epilogue: mma C-fragment layout
    int r = lane >> 2, c2 = (lane & 3) << 1;
    #pragma unroll
    for (int mt = 0; mt < 2; mt++) {
        #pragma unroll
        for (int nt = 0; nt < 4; nt++) {
            int gm0 = bm + wm * 32 + mt * 16 + r;
            int gn0 = bn + wn * 32 + nt * 8 + c2;
            #pragma unroll
            for (int hh = 0; hh < 2; hh++) {
                int gm = gm0 + hh * 8;
                if (gm >= M) continue;
                #pragma unroll
                for (int j = 0; j < 2; j++) {
                    int gn = gn0 + j;
                    if (gn >= Nc) continue;
                    float v = acc[mt][nt][hh * 2 + j];
                    if (!SPLIT && bias) v += bias[gn];
                    if (RELU) v = fmaxf(v, 0.f);
                    long ci = (long)gm * Nc + gn;
                    if (ACC) v += C[ci];
                    C[ci] = v;
                }
            }
        }
    }
}

// ---------------- per-row max + inverse sum of exp(relu(x)-mx) ----------------
__global__ void rowstat_kernel(const float* __restrict__ g, float* __restrict__ mx,
                               float* __restrict__ invs)
{
    long row = (long)blockIdx.x * 8 + (threadIdx.x >> 5);
    if (row >= (long)TN) return;
    int lane = threadIdx.x & 31;
    const float4* p = reinterpret_cast<const float4*>(g + row * NPTS);  // 100 float4
    float4 vv[4];
    float m = 0.f;
    #pragma unroll
    for (int r = 0; r < 4; r++) {
        int c = lane + r * 32;
        vv[r] = (c < 100) ? p[c] : make_float4(0.f, 0.f, 0.f, 0.f);
        m = fmaxf(m, fmaxf(fmaxf(vv[r].x, vv[r].y), fmaxf(vv[r].z, vv[r].w)));
    }
    #pragma unroll
    for (int o = 16; o > 0; o >>= 1) m = fmaxf(m, __shfl_xor_sync(~0u, m, o));
    float s = 0.f;
    #pragma unroll
    for (int r = 0; r < 4; r++) {
        int c = lane + r * 32;
        if (c < 100) {
            s += __expf(fmaxf(vv[r].x, 0.f) - m) + __expf(fmaxf(vv[r].y, 0.f) - m)
               + __expf(fmaxf(vv[r].z, 0.f) - m) + __expf(fmaxf(vv[r].w, 0.f) - m);
        }
    }
    #pragma unroll
    for (int o = 16; o > 0; o >>= 1) s += __shfl_xor_sync(~0u, s, o);
    if (lane == 0) { mx[row] = m; invs[row] = 1.f / s; }
}

// ---------------- input proj + concat adaptive embedding ----------------------
__global__ void hcat_kernel(const float* __restrict__ x, const float* __restrict__ W_in,
                            const float* __restrict__ b_in, const float* __restrict__ adp,
                            float* __restrict__ hcat)
{
    long idx = (long)blockIdx.x * 256 + threadIdx.x;
    if (idx >= (long)TN * DD) return;
    long tn = idx / DD; int j = (int)(idx - tn * DD);
    int t = (int)(tn / NPTS), n = (int)(tn - (long)t * NPTS);
    float v;
    if (j < 24) {
        const float* xr = x + ((long)n * TT + t) * 3;
        v = b_in[j] + xr[0] * W_in[0 * 24 + j] + xr[1] * W_in[1 * 24 + j] + xr[2] * W_in[2 * 24 + j];
    } else {
        v = adp[tn * 80 + (j - 24)];
    }
    hcat[idx] = v;
}

// ---------------- linear attention: kvs + ksum (warp-parallel over L) ---------
__global__ void kvs_kernel(const float* __restrict__ qkv, long sB, long sL, int L,
                           float* __restrict__ kvs, float* __restrict__ ksum)
{
    int b = blockIdx.x, h = blockIdx.y;
    int w = threadIdx.x >> 5, lane = threadIdx.x & 31;
    int chunk = (L + 7) >> 3;
    int l0 = w * chunk, l1 = min(L, l0 + chunk);
    const float* base = qkv + (long)b * sB + h * HD;
    float acc[HD];
    #pragma unroll
    for (int m = 0; m < HD; m++) acc[m] = 0.f;
    float accs = 0.f;
    for (int l = l0; l < l1; l++) {
        const float* row = base + (long)l * sL;
        float kk = (lane < HD) ? row[DD + lane] : 0.f;
        float vv = (lane < HD) ? row[2 * DD + lane] : 0.f;
        float ss = kk * kk;
        #pragma unroll
        for (int o = 16; o > 0; o >>= 1) ss += __shfl_xor_sync(~0u, ss, o);
        float inv = 1.f / fmaxf(sqrtf(ss), 1e-12f);
        float kin = kk * inv;
        accs += kin;
        #pragma unroll
        for (int m = 0; m < HD; m++) {
            float km = __shfl_sync(~0u, kin, m);
            acc[m] += km * vv;
        }
    }
    __shared__ float red[8][HD][HD + 2];
    __shared__ float redk[8][32];
    if (lane < HD) {
        #pragma unroll
        for (int m = 0; m < HD; m++) red[w][m][lane] = acc[m];
    }
    redk[w][lane] = accs;
    __syncthreads();
    long basec = ((long)b * HH + h);
    for (int cell = threadIdx.x; cell < HD * HD; cell += 256) {
        int m = cell / HD, d = cell - m * HD;
        float s = 0.f;
        #pragma unroll
        for (int ww = 0; ww < 8; ww++) s += red[ww][m][d];
        kvs[basec * (HD * HD) + cell] = s;
    }
    if (threadIdx.x < HD) {
        float s = 0.f;
        #pragma unroll
        for (int ww = 0; ww < 8; ww++) s += redk[ww][threadIdx.x];
        ksum[basec * HD + threadIdx.x] = s;
    }
}

// ---------------- linear attention: per-token output --------------------------
__global__ void attnout_kernel(const float* __restrict__ qkv, long sB, long sL, int L,
                               const float* __restrict__ kvs, const float* __restrict__ ksum,
                               float* __restrict__ outb, long oB, long oL, int ooff)
{
    int l = blockIdx.x, b = blockIdx.y;
    int tid = threadIdx.x;
    const float* row = qkv + (long)b * sB + (long)l * sL;
    __shared__ float sq[DD], sv[DD], sinv[HH], sden[HH];
    if (tid < DD) { sq[tid] = row[tid]; sv[tid] = row[2 * DD + tid]; }
    __syncthreads();
    if (tid < HH) {
        const float* qh = sq + tid * HD;
        float ss = 0.f;
        #pragma unroll
        for (int m = 0; m < HD; m++) ss += qh[m] * qh[m];
        float inv = 1.f / fmaxf(sqrtf(ss), 1e-12f);
        sinv[tid] = inv;
        const float* ks = ksum + ((long)b * HH + tid) * HD;
        float dd = 0.f;
        #pragma unroll
        for (int m = 0; m < HD; m++) dd += qh[m] * ks[m];
        sden[tid] = dd * inv + (float)L;
    }
    __syncthreads();
    if (tid < DD) {
        int h = tid / HD, d = tid - h * HD;
        const float* kv = kvs + ((long)b * HH + h) * (HD * HD) + d;
        const float* qh = sq + h * HD;
        float s = 0.f;
        #pragma unroll
        for (int m = 0; m < HD; m++) s += qh[m] * kv[m * HD];
        float num = s * sinv[h] + (float)L * sv[tid];
        outb[((long)b * oB + (long)l * oL) * D2 + ooff + tid] = num / sden[h];
    }
}

// ---------------- fused combine + LayerNorm -----------------------------------
__global__ void combine_ln_kernel(const float* __restrict__ h, const float* __restrict__ a0,
                                  const float* __restrict__ a1, const float* __restrict__ p0,
                                  const float* __restrict__ p1, const float* __restrict__ gam,
                                  const float* __restrict__ bet, float* __restrict__ out)
{
    long row = blockIdx.x; int tid = threadIdx.x;  // 128
    __shared__ float red[4];
    long i = row * DD + tid;
    float v = 0.f;
    if (tid < DD) v = 2.f * (h[i] + a0[i] * p0[i] + 0.01f * a1[i] * p1[i]);
    float s = (tid < DD) ? v : 0.f;
    #pragma unroll
    for (int o = 16; o > 0; o >>= 1) s += __shfl_xor_sync(~0u, s, o);
    if ((tid & 31) == 0) red[tid >> 5] = s;
    __syncthreads();
    float mean = (red[0] + red[1] + red[2] + red[3]) / (float)DD;
    __syncthreads();
    float d = (tid < DD) ? (v - mean) : 0.f;
    float s2 = d * d;
    #pragma unroll
    for (int o = 16; o > 0; o >>= 1) s2 += __shfl_xor_sync(~0u, s2, o);
    if ((tid & 31) == 0) red[tid >> 5] = s2;
    __syncthreads();
    float var = (red[0] + red[1] + red[2] + red[3]) / (float)DD;
    if (tid < DD) out[i] = d * rsqrtf(var + 1e-5f) * gam[tid] + bet[tid];
}

__global__ void ln_res_kernel(const float* __restrict__ a, const float* __restrict__ b,
                              const float* __restrict__ gam, const float* __restrict__ bet,
                              float* __restrict__ out)
{
    long row = blockIdx.x; int tid = threadIdx.x;  // 128
    __shared__ float red[4];
    long i = row * DD + tid;
    float v = 0.f;
    if (tid < DD) v = a[i] + b[i];
    float s = (tid < DD) ? v : 0.f;
    #pragma unroll
    for (int o = 16; o > 0; o >>= 1) s += __shfl_xor_sync(~0u, s, o);
    if ((tid & 31) == 0) red[tid >> 5] = s;
    __syncthreads();
    float mean = (red[0] + red[1] + red[2] + red[3]) / (float)DD;
    __syncthreads();
    float d = (tid < DD) ? (v - mean) : 0.f;
    float s2 = d * d;
    #pragma unroll
    for (int o = 16; o > 0; o >>= 1) s2 += __shfl_xor_sync(~0u, s2, o);
    if ((tid & 31) == 0) red[tid >> 5] = s2;
    __syncthreads();
    float var = (red[0] + red[1] + red[2] + red[3]) / (float)DD;
    if (tid < DD) out[i] = d * rsqrtf(var + 1e-5f) * gam[tid] + bet[tid];
}

// ---------------- [T,N,D] -> [N, T*D] transpose -------------------------------
__global__ void transpose_h2_kernel(const float* __restrict__ h2, float* __restrict__ h2t)
{
    long idx = (long)blockIdx.x * 256 + threadIdx.x;
    if (idx >= (long)TN * DD) return;
    long t = idx / ((long)NPTS * DD);
    long r = idx - t * ((long)NPTS * DD);
    long n = r / DD;
    long d = r - n * DD;
    h2t[n * (long)TD + t * DD + d] = h2[idx];
}

// ---------------- split-K deterministic reduction -----------------------------
__global__ void splitk_reduce_kernel(const float* __restrict__ part, const float* __restrict__ bias,
                                     float* __restrict__ y, int MN, int Z, int Nc)
{
    int i = blockIdx.x * 256 + threadIdx.x;
    if (i >= MN) return;
    float s = bias[i % Nc];
    for (int z = 0; z < Z; z++) s += part[(long)z * MN + i];
    y[i] = s;
}

#define GEMM(TB,RL,AC,SP,SX, gx,gy,gz, A,B,bias,C, M,K,Nc, sA,sB,sC, mx,iv) \
    gemm_kernel<TB,RL,AC,SP,SX><<<dim3(gx,gy,gz), 256>>>(A,B,bias,C,M,K,Nc,sA,sB,sC,mx,iv)

// ---------------- host orchestration ------------------------------------------
static void run_attention(const float* x4, const float* qw, const float* ow, const float* ob,
                          float* qkv, float* kvs, float* ksum, float* cat2, float* attout)
{
    GEMM(false,false,false,false,false, 5, (TN+127)/128, 1,
         x4, qw, nullptr, qkv, TN, DD, D3, 0,0,0, nullptr,nullptr);
    kvs_kernel<<<dim3(TT, HH), 256>>>(qkv, (long)NPTS * D3, (long)D3, NPTS, kvs, ksum);
    attnout_kernel<<<dim3(NPTS, TT), 128>>>(qkv, (long)NPTS * D3, (long)D3, NPTS, kvs, ksum,
                                            cat2, (long)NPTS, 1, 0);
    kvs_kernel<<<dim3(NPTS, HH), 256>>>(qkv, (long)D3, (long)NPTS * D3, TT, kvs, ksum);
    attnout_kernel<<<dim3(TT, NPTS), 128>>>(qkv, (long)D3, (long)NPTS * D3, TT, kvs, ksum,
                                            cat2, 1, (long)NPTS, DD);
    GEMM(false,false,false,false,false, 2, (TN+127)/128, 1,
         cat2, ow, ob, attout, TN, D2, DD, 0,0,0, nullptr,nullptr);
}

extern "C" void kernel_launch(void* const* d_in, const int* in_sizes, int n_in,
                              void* d_out, int out_size)
{
    (void)in_sizes; (void)n_in; (void)out_size;
    const float* x     = (const float*)d_in[0];
    const float* W_in  = (const float*)d_in[1];
    const float* b_in  = (const float*)d_in[2];
    const float* adp   = (const float*)d_in[3];
    const float* W_tp  = (const float*)d_in[4];
    const float* b_tp  = (const float*)d_in[5];
    const float* qkv_w = (const float*)d_in[6];
    const float* op_w  = (const float*)d_in[7];
    const float* op_b  = (const float*)d_in[8];
    const float* pw_w  = (const float*)d_in[9];
    const float* pw_b  = (const float*)d_in[10];
    const float* fc_w1 = (const float*)d_in[11];
    const float* fc_b1 = (const float*)d_in[12];
    const float* fc_w2 = (const float*)d_in[13];
    const float* fc_b2 = (const float*)d_in[14];
    const float* ln1_g = (const float*)d_in[15];
    const float* ln1_b = (const float*)d_in[16];
    const float* ln2_g = (const float*)d_in[17];
    const float* ln2_b = (const float*)d_in[18];
    const float* ep_w  = (const float*)d_in[19];
    const float* ep_b  = (const float*)d_in[20];
    const float* enc_w1= (const float*)d_in[21];
    const float* enc_b1= (const float*)d_in[22];
    const float* enc_w2= (const float*)d_in[23];
    const float* enc_b2= (const float*)d_in[24];
    const float* out_w = (const float*)d_in[25];
    const float* out_b = (const float*)d_in[26];
    float* out = (float*)d_out;

    float *hcat, *h, *graph, *mxp, *invs, *z1, *qkv, *kvs, *ksum, *cat2, *att0, *att1;
    float *p0, *p1, *h1, *t2, *h2, *h2t, *part, *y, *yh;
    cudaGetSymbolAddress((void**)&hcat, g_hcat);
    cudaGetSymbolAddress((void**)&h,    g_h);
    cudaGetSymbolAddress((void**)&graph,g_graph);
    cudaGetSymbolAddress((void**)&mxp,  g_mx);
    cudaGetSymbolAddress((void**)&invs, g_invs);
    cudaGetSymbolAddress((void**)&z1,   g_z1);
    cudaGetSymbolAddress((void**)&qkv,  g_qkv);
    cudaGetSymbolAddress((void**)&kvs,  g_kvs);
    cudaGetSymbolAddress((void**)&ksum, g_ksum);
    cudaGetSymbolAddress((void**)&cat2, g_cat2);
    cudaGetSymbolAddress((void**)&att0, g_att0);
    cudaGetSymbolAddress((void**)&att1, g_att1);
    cudaGetSymbolAddress((void**)&p0,   g_p0);
    cudaGetSymbolAddress((void**)&p1,   g_p1);
    cudaGetSymbolAddress((void**)&h1,   g_h1);
    cudaGetSymbolAddress((void**)&t2,   g_t2);
    cudaGetSymbolAddress((void**)&h2,   g_h2);
    cudaGetSymbolAddress((void**)&h2t,  g_h2t);
    cudaGetSymbolAddress((void**)&part, g_part);
    cudaGetSymbolAddress((void**)&y,    g_y);
    cudaGetSymbolAddress((void**)&yh,   g_yh);

    const int MY = (TN + 127) / 128;   // 1141

    hcat_kernel<<<((long)TN * DD + 255) / 256, 256>>>(x, W_in, b_in, adp, hcat);
    GEMM(false,false,false,false,false, 2, MY, 1,
         hcat, W_tp, b_tp, h, TN, DD, DD, 0,0,0, nullptr,nullptr);
    GEMM(true,false,false,false,false, 7, 4, TT,
         adp, adp, nullptr, graph, NPTS, 80, NPTS,
         (long)NPTS*80, (long)NPTS*80, (long)NPTS*NPTS, nullptr,nullptr);
    rowstat_kernel<<<(TN + 7) / 8, 256>>>(graph, mxp, invs);
    GEMM(false,false,false,false,true, 2, 4, TT,
         graph, h, nullptr, z1, NPTS, NPTS, DD,
         (long)NPTS*NPTS, (long)NPTS*DD, (long)NPTS*DD, mxp, invs);
    run_attention(h,  qkv_w,            op_w,           op_b,       qkv, kvs, ksum, cat2, att0);
    run_attention(z1, qkv_w + DD * D3,  op_w + D2 * DD, op_b + DD,  qkv, kvs, ksum, cat2, att1);
    GEMM(false,false,false,false,false, 2, MY, 1,
         h,    pw_w,           pw_b,      p0, TN, DD, DD, 0,0,0, nullptr,nullptr);
    GEMM(false,false,false,false,false, 2, MY, 1,
         att0, pw_w + DD * DD, pw_b + DD, p1, TN, DD, DD, 0,0,0, nullptr,nullptr);
    combine_ln_kernel<<<TN, 128>>>(h, att0, att1, p0, p1, ln1_g, ln1_b, h1);
    GEMM(false,true,false,false,false, 4, MY, 1,
         h1, fc_w1, fc_b1, cat2, TN, DD, D2, 0,0,0, nullptr,nullptr);
    GEMM(false,false,false,false,false, 2, MY, 1,
         cat2, fc_w2, fc_b2, t2, TN, D2, DD, 0,0,0, nullptr,nullptr);
    ln_res_kernel<<<TN, 128>>>(h1, t2, ln2_g, ln2_b, h2);
    transpose_h2_kernel<<<((long)TN * DD + 255) / 256, 256>>>(h2, h2t);
    GEMM(false,false,false,true,false, 2, 4, SPLITK,
         h2t, ep_w, nullptr, part, NPTS, TD, DD, 0,0,0, nullptr,nullptr);
    splitk_reduce_kernel<<<(NPTS * DD + 255) / 256, 256>>>(part, ep_b, y, NPTS * DD, SPLITK, DD);
    for (int i = 0; i < 3; i++) {
        GEMM(false,true,false,false,false, 4, 4, 1,
             y,  enc_w1 + (long)i * DD * D2, enc_b1 + (long)i * D2, yh, NPTS, DD, D2, 0,0,0, nullptr,nullptr);
        GEMM(false,false,true,false,false, 2, 4, 1,
             yh, enc_w2 + (long)i * D2 * DD, enc_b2 + (long)i * DD, y,  NPTS, D2, DD, 0,0,0, nullptr,nullptr);
    }
    GEMM(false,false,false,false,false, 6, 4, 1,
         y, out_w, out_b, out, NPTS, DD, TT, 0,0,0, nullptr,nullptr);
}

// round 6
// speedup vs baseline: 1.8469x; 1.1452x over previous
#include <cuda_runtime.h>
#include <math.h>

#define TT   365
#define NPTS 400
#define DD   104
#define HH   4
#define HD   26
#define TN   (TT*NPTS)      // 146000
#define D2   (2*DD)         // 208
#define D3   (3*DD)         // 312
#define TD   (TT*DD)        // 37960
#define SPLITK 40
#define KCHUNK 960
#define SMA  36              // smem row stride for K-chunk 32 (+4 pad)
#define A_ST (128*SMA)       // 4608 floats per A stage
#define B_ST (64*SMA)        // 2304 floats per B stage
#define SMEM_GEMM ((3*A_ST + 3*B_ST)*4)   // 82944 bytes

// ---------------- scratch (device globals; no runtime allocation) -------------
__device__ float g_hcat[(size_t)TN*DD];
__device__ float g_h   [(size_t)TN*DD];
__device__ float g_graph[(size_t)TT*NPTS*NPTS];
__device__ float g_z1  [(size_t)TN*DD];
__device__ float g_qkv [(size_t)TN*D3];
__device__ float g_kvs [(size_t)NPTS*HH*HD*HD];
__device__ float g_ksum[(size_t)NPTS*HH*HD];
__device__ float g_cat2[(size_t)TN*D2];
__device__ float g_att0[(size_t)TN*DD];
__device__ float g_att1[(size_t)TN*DD];
__device__ float g_p0  [(size_t)TN*DD];
__device__ float g_p1  [(size_t)TN*DD];
__device__ float g_h1  [(size_t)TN*DD];
__device__ float g_t2  [(size_t)TN*DD];
__device__ float g_h2  [(size_t)TN*DD];
__device__ float g_h2t [(size_t)NPTS*TD];
__device__ float g_part[(size_t)SPLITK*NPTS*DD];
__device__ float g_y   [(size_t)NPTS*DD];
__device__ float g_yh  [(size_t)NPTS*D2];
__device__ float g_wts [(size_t)16000000];   // tf32-rounded weights arena

// offsets into g_wts (floats)
#define O_ADP   0L
#define O_WTP   11680000L
#define O_QKVW  11690816L
#define O_OPW   11755712L
#define O_PWW   11798976L
#define O_FC1   11820608L
#define O_FC2   11842240L
#define O_EPW   11863872L
#define O_ENC1  15811712L
#define O_ENC2  15876608L
#define O_OUTW  15941504L

// ---------------- tf32 helpers -------------------------------------------------
__device__ __forceinline__ float cvt_tf32(float f)
{
    unsigned u;
    asm("cvt.rna.tf32.f32 %0, %1;" : "=r"(u) : "f"(f));
    return __uint_as_float(u);
}

// ---------------- cp.async issue helpers ---------------------------------------
__device__ __forceinline__ void issue_a(const float* __restrict__ A, unsigned sAs,
                                        int bm, int k0, int kend, int M, int K, int tid)
{
    #pragma unroll
    for (int p = 0; p < 4; p++) {
        int idx = tid + p * 256;
        int m = idx >> 3, kq = (idx & 7) << 2;
        int gm = bm + m;
        int rem = kend - (k0 + kq);
        int sz = (gm < M) ? min(max(rem, 0) * 4, 16) : 0;
        const float* src = (sz > 0) ? A + (long)gm * K + k0 + kq : A;
        unsigned dst = sAs + (unsigned)(m * SMA + kq) * 4u;
        asm volatile("cp.async.cg.shared.global [%0],[%1],16,%2;"
                     :: "r"(dst), "l"(src), "r"(sz));
    }
}

template<bool TRANSB>
__device__ __forceinline__ void issue_b(const float* __restrict__ B, unsigned sBs,
                                        int bn, int k0, int kend, int Nc, int K, int tid)
{
    if (TRANSB) {
        #pragma unroll
        for (int p = 0; p < 2; p++) {
            int idx = tid + p * 256;
            int n = idx >> 3, kq = (idx & 7) << 2;
            int gn = bn + n;
            int rem = kend - (k0 + kq);
            int sz = (gn < Nc) ? min(max(rem, 0) * 4, 16) : 0;
            const float* src = (sz > 0) ? B + (long)gn * K + k0 + kq : B;
            unsigned dst = sBs + (unsigned)(n * SMA + kq) * 4u;
            asm volatile("cp.async.cg.shared.global [%0],[%1],16,%2;"
                         :: "r"(dst), "l"(src), "r"(sz));
        }
    } else {
        #pragma unroll
        for (int p = 0; p < 8; p++) {
            int e = tid + p * 256;
            int k = e >> 6, n = e & 63;
            int gk = k0 + k, gn = bn + n;
            int sz = (gk < kend && gn < Nc) ? 4 : 0;
            const float* src = sz ? B + (long)gk * Nc + gn : B;
            unsigned dst = sBs + (unsigned)(n * SMA + k) * 4u;
            asm volatile("cp.async.ca.shared.global [%0],[%1],4,%2;"
                         :: "r"(dst), "l"(src), "r"(sz));
        }
    }
}

// ---------------- tf32 MMA on a k32 chunk --------------------------------------
__device__ __forceinline__ void mma_chunk(const float* __restrict__ As,
                                          const float* __restrict__ Bs,
                                          int wm, int wn, int lane, float (*acc)[4][4])
{
    int r = lane >> 2, c = lane & 3;
    #pragma unroll
    for (int ks = 0; ks < 4; ks++) {
        int k0 = ks * 8;
        unsigned a[2][4], b[4][2];
        #pragma unroll
        for (int mt = 0; mt < 2; mt++) {
            const float* p = As + (wm * 32 + mt * 16 + r) * SMA + k0 + c;
            a[mt][0] = __float_as_uint(p[0]);
            a[mt][1] = __float_as_uint(p[8 * SMA]);
            a[mt][2] = __float_as_uint(p[4]);
            a[mt][3] = __float_as_uint(p[8 * SMA + 4]);
        }
        #pragma unroll
        for (int nt = 0; nt < 4; nt++) {
            const float* p = Bs + (wn * 32 + nt * 8 + r) * SMA + k0 + c;
            b[nt][0] = __float_as_uint(p[0]);
            b[nt][1] = __float_as_uint(p[4]);
        }
        #pragma unroll
        for (int mt = 0; mt < 2; mt++)
            #pragma unroll
            for (int nt = 0; nt < 4; nt++)
                asm("mma.sync.aligned.m16n8k8.row.col.f32.tf32.tf32.f32 "
                    "{%0,%1,%2,%3},{%4,%5,%6,%7},{%8,%9},{%0,%1,%2,%3};"
                    : "+f"(acc[mt][nt][0]), "+f"(acc[mt][nt][1]),
                      "+f"(acc[mt][nt][2]), "+f"(acc[mt][nt][3])
                    : "r"(a[mt][0]), "r"(a[mt][1]), "r"(a[mt][2]), "r"(a[mt][3]),
                      "r"(b[nt][0]), "r"(b[nt][1]));
    }
}

// ---------------- tiled tf32-MMA GEMM: 128x64 block, cp.async 3-stage ----------
template<bool TRANSB, bool RELU, bool ACC, bool SPLIT>
__global__ void __launch_bounds__(256)
gemm_kernel(const float* __restrict__ A, const float* __restrict__ B,
            const float* __restrict__ bias, float* __restrict__ C,
            int M, int K, int Nc, long sA, long sB_, long sC, int rnd)
{
    extern __shared__ float dsm[];
    int tid = threadIdx.x;
    int bm = blockIdx.y * 128, bn = blockIdx.x * 64;
    int kbeg = 0, kend = K;
    if (SPLIT) {
        int z = blockIdx.z;
        kbeg = z * KCHUNK;
        kend = min(K, kbeg + KCHUNK);
        C += (long)z * M * Nc;
    } else {
        int z = blockIdx.z;
        A += z * sA; B += z * sB_; C += z * sC;
    }
    int w = tid >> 5, lane = tid & 31;
    int wm = w >> 1, wn = w & 1;
    float acc[2][4][4];
    #pragma unroll
    for (int mt = 0; mt < 2; mt++)
        #pragma unroll
        for (int nt = 0; nt < 4; nt++)
            #pragma unroll
            for (int q = 0; q < 4; q++) acc[mt][nt][q] = 0.f;

    unsigned sbase = (unsigned)__cvta_generic_to_shared(dsm);
    unsigned sA0 = sbase;
    unsigned sB0 = sbase + 3u * A_ST * 4u;

    int nk = (kend - kbeg + 31) >> 5;
    issue_a(A, sA0, bm, kbeg, kend, M, K, tid);
    issue_b<TRANSB>(B, sB0, bn, kbeg, kend, Nc, K, tid);
    asm volatile("cp.async.commit_group;" ::: "memory");
    issue_a(A, sA0 + A_ST * 4u, bm, kbeg + 32, kend, M, K, tid);
    issue_b<TRANSB>(B, sB0 + B_ST * 4u, bn, kbeg + 32, kend, Nc, K, tid);
    asm volatile("cp.async.commit_group;" ::: "memory");

    for (int it = 0; it < nk; it++) {
        asm volatile("cp.async.wait_group 1;" ::: "memory");
        __syncthreads();
        int s2 = (it + 2) % 3;
        int kn = kbeg + (it + 2) * 32;
        issue_a(A, sA0 + (unsigned)s2 * A_ST * 4u, bm, kn, kend, M, K, tid);
        issue_b<TRANSB>(B, sB0 + (unsigned)s2 * B_ST * 4u, bn, kn, kend, Nc, K, tid);
        asm volatile("cp.async.commit_group;" ::: "memory");
        int sc = it % 3;
        mma_chunk(dsm + sc * A_ST, dsm + 3 * A_ST + sc * B_ST, wm, wn, lane, acc);
    }

    int r = lane >> 2, c2 = (lane & 3) << 1;
    #pragma unroll
    for (int mt = 0; mt < 2; mt++) {
        #pragma unroll
        for (int nt = 0; nt < 4; nt++) {
            int gm0 = bm + wm * 32 + mt * 16 + r;
            int gn0 = bn + wn * 32 + nt * 8 + c2;
            #pragma unroll
            for (int hh = 0; hh < 2; hh++) {
                int gm = gm0 + hh * 8;
                if (gm >= M) continue;
                #pragma unroll
                for (int j = 0; j < 2; j++) {
                    int gn = gn0 + j;
                    if (gn >= Nc) continue;
                    float v = acc[mt][nt][hh * 2 + j];
                    if (!SPLIT && bias) v += bias[gn];
                    if (RELU) v = fmaxf(v, 0.f);
                    long ci = (long)gm * Nc + gn;
                    if (ACC) v += C[ci];
                    if (rnd) v = cvt_tf32(v);
                    C[ci] = v;
                }
            }
        }
    }
}

// ---------------- fused relu-softmax normalize (+tf32 round) in place ----------
__global__ void normgraph_kernel(float* __restrict__ g)
{
    long row = (long)blockIdx.x * 8 + (threadIdx.x >> 5);
    if (row >= (long)TN) return;
    int lane = threadIdx.x & 31;
    float4* p = reinterpret_cast<float4*>(g + row * NPTS);  // 100 float4
    float4 vv[4];
    float m = 0.f;
    #pragma unroll
    for (int r = 0; r < 4; r++) {
        int c = lane + r * 32;
        vv[r] = (c < 100) ? p[c] : make_float4(0.f, 0.f, 0.f, 0.f);
        m = fmaxf(m, fmaxf(fmaxf(vv[r].x, vv[r].y), fmaxf(vv[r].z, vv[r].w)));
    }
    #pragma unroll
    for (int o = 16; o > 0; o >>= 1) m = fmaxf(m, __shfl_xor_sync(~0u, m, o));
    float s = 0.f;
    #pragma unroll
    for (int r = 0; r < 4; r++) {
        int c = lane + r * 32;
        if (c < 100) {
            vv[r].x = __expf(fmaxf(vv[r].x, 0.f) - m);
            vv[r].y = __expf(fmaxf(vv[r].y, 0.f) - m);
            vv[r].z = __expf(fmaxf(vv[r].z, 0.f) - m);
            vv[r].w = __expf(fmaxf(vv[r].w, 0.f) - m);
            s += vv[r].x + vv[r].y + vv[r].z + vv[r].w;
        }
    }
    #pragma unroll
    for (int o = 16; o > 0; o >>= 1) s += __shfl_xor_sync(~0u, s, o);
    float inv = 1.f / s;
    #pragma unroll
    for (int r = 0; r < 4; r++) {
        int c = lane + r * 32;
        if (c < 100) {
            float4 ov;
            ov.x = cvt_tf32(vv[r].x * inv);
            ov.y = cvt_tf32(vv[r].y * inv);
            ov.z = cvt_tf32(vv[r].z * inv);
            ov.w = cvt_tf32(vv[r].w * inv);
            p[c] = ov;
        }
    }
}

// ---------------- weight tf32 rounding copy ------------------------------------
__global__ void round4_kernel(const float* __restrict__ src, float* __restrict__ dst, int n4)
{
    int i = blockIdx.x * 256 + threadIdx.x;
    if (i >= n4) return;
    float4 v = reinterpret_cast<const float4*>(src)[i];
    v.x = cvt_tf32(v.x); v.y = cvt_tf32(v.y);
    v.z = cvt_tf32(v.z); v.w = cvt_tf32(v.w);
    reinterpret_cast<float4*>(dst)[i] = v;
}

// ---------------- input proj + concat adaptive embedding (tf32 out) ------------
__global__ void hcat_kernel(const float* __restrict__ x, const float* __restrict__ W_in,
                            const float* __restrict__ b_in, const float* __restrict__ adp_r,
                            float* __restrict__ hcat)
{
    long idx = (long)blockIdx.x * 256 + threadIdx.x;
    if (idx >= (long)TN * DD) return;
    long tn = idx / DD; int j = (int)(idx - tn * DD);
    int t = (int)(tn / NPTS), n = (int)(tn - (long)t * NPTS);
    float v;
    if (j < 24) {
        const float* xr = x + ((long)n * TT + t) * 3;
        v = cvt_tf32(b_in[j] + xr[0] * W_in[0 * 24 + j] + xr[1] * W_in[1 * 24 + j]
                     + xr[2] * W_in[2 * 24 + j]);
    } else {
        v = adp_r[tn * 80 + (j - 24)];   // already rounded
    }
    hcat[idx] = v;
}

// ---------------- linear attention: kvs + ksum (warp-parallel over L) ----------
__global__ void kvs_kernel(const float* __restrict__ qkv, long sB, long sL, int L,
                           float* __restrict__ kvs, float* __restrict__ ksum)
{
    int b = blockIdx.x, h = blockIdx.y;
    int w = threadIdx.x >> 5, lane = threadIdx.x & 31;
    int chunk = (L + 7) >> 3;
    int l0 = w * chunk, l1 = min(L, l0 + chunk);
    const float* base = qkv + (long)b * sB + h * HD;
    float acc[HD];
    #pragma unroll
    for (int m = 0; m < HD; m++) acc[m] = 0.f;
    float accs = 0.f;
    for (int l = l0; l < l1; l++) {
        const float* row = base + (long)l * sL;
        float kk = (lane < HD) ? row[DD + lane] : 0.f;
        float vv = (lane < HD) ? row[2 * DD + lane] : 0.f;
        float ss = kk * kk;
        #pragma unroll
        for (int o = 16; o > 0; o >>= 1) ss += __shfl_xor_sync(~0u, ss, o);
        float inv = 1.f / fmaxf(sqrtf(ss), 1e-12f);
        float kin = kk * inv;
        accs += kin;
        #pragma unroll
        for (int m = 0; m < HD; m++) {
            float km = __shfl_sync(~0u, kin, m);
            acc[m] += km * vv;
        }
    }
    __shared__ float red[8][HD][HD + 2];
    __shared__ float redk[8][32];
    if (lane < HD) {
        #pragma unroll
        for (int m = 0; m < HD; m++) red[w][m][lane] = acc[m];
    }
    redk[w][lane] = accs;
    __syncthreads();
    long basec = ((long)b * HH + h);
    for (int cell = threadIdx.x; cell < HD * HD; cell += 256) {
        int m = cell / HD, d = cell - m * HD;
        float s = 0.f;
        #pragma unroll
        for (int ww = 0; ww < 8; ww++) s += red[ww][m][d];
        kvs[basec * (HD * HD) + cell] = s;
    }
    if (threadIdx.x < HD) {
        float s = 0.f;
        #pragma unroll
        for (int ww = 0; ww < 8; ww++) s += redk[ww][threadIdx.x];
        ksum[basec * HD + threadIdx.x] = s;
    }
}

// ---------------- linear attention: per-token output (tf32-rounded out) --------
__global__ void attnout_kernel(const float* __restrict__ qkv, long sB, long sL, int L,
                               const float* __restrict__ kvs, const float* __restrict__ ksum,
                               float* __restrict__ outb, long oB, long oL, int ooff)
{
    int l = blockIdx.x, b = blockIdx.y;
    int tid = threadIdx.x;
    const float* row = qkv + (long)b * sB + (long)l * sL;
    __shared__ float sq[DD], sv[DD], sinv[HH], sden[HH];
    if (tid < DD) { sq[tid] = row[tid]; sv[tid] = row[2 * DD + tid]; }
    __syncthreads();
    if (tid < HH) {
        const float* qh = sq + tid * HD;
        float ss = 0.f;
        #pragma unroll
        for (int m = 0; m < HD; m++) ss += qh[m] * qh[m];
        float inv = 1.f / fmaxf(sqrtf(ss), 1e-12f);
        sinv[tid] = inv;
        const float* ks = ksum + ((long)b * HH + tid) * HD;
        float dd = 0.f;
        #pragma unroll
        for (int m = 0; m < HD; m++) dd += qh[m] * ks[m];
        sden[tid] = dd * inv + (float)L;
    }
    __syncthreads();
    if (tid < DD) {
        int h = tid / HD, d = tid - h * HD;
        const float* kv = kvs + ((long)b * HH + h) * (HD * HD) + d;
        const float* qh = sq + h * HD;
        float s = 0.f;
        #pragma unroll
        for (int m = 0; m < HD; m++) s += qh[m] * kv[m * HD];
        float num = s * sinv[h] + (float)L * sv[tid];
        outb[((long)b * oB + (long)l * oL) * D2 + ooff + tid] = cvt_tf32(num / sden[h]);
    }
}

// ---------------- fused combine + LayerNorm (tf32 out) -------------------------
__global__ void combine_ln_kernel(const float* __restrict__ h, const float* __restrict__ a0,
                                  const float* __restrict__ a1, const float* __restrict__ p0,
                                  const float* __restrict__ p1, const float* __restrict__ gam,
                                  const float* __restrict__ bet, float* __restrict__ out)
{
    long row = blockIdx.x; int tid = threadIdx.x;  // 128
    __shared__ float red[4];
    long i = row * DD + tid;
    float v = 0.f;
    if (tid < DD) v = 2.f * (h[i] + a0[i] * p0[i] + 0.01f * a1[i] * p1[i]);
    float s = (tid < DD) ? v : 0.f;
    #pragma unroll
    for (int o = 16; o > 0; o >>= 1) s += __shfl_xor_sync(~0u, s, o);
    if ((tid & 31) == 0) red[tid >> 5] = s;
    __syncthreads();
    float mean = (red[0] + red[1] + red[2] + red[3]) / (float)DD;
    __syncthreads();
    float d = (tid < DD) ? (v - mean) : 0.f;
    float s2 = d * d;
    #pragma unroll
    for (int o = 16; o > 0; o >>= 1) s2 += __shfl_xor_sync(~0u, s2, o);
    if ((tid & 31) == 0) red[tid >> 5] = s2;
    __syncthreads();
    float var = (red[0] + red[1] + red[2] + red[3]) / (float)DD;
    if (tid < DD) out[i] = cvt_tf32(d * rsqrtf(var + 1e-5f) * gam[tid] + bet[tid]);
}

__global__ void ln_res_kernel(const float* __restrict__ a, const float* __restrict__ b,
                              const float* __restrict__ gam, const float* __restrict__ bet,
                              float* __restrict__ out)
{
    long row = blockIdx.x; int tid = threadIdx.x;  // 128
    __shared__ float red[4];
    long i = row * DD + tid;
    float v = 0.f;
    if (tid < DD) v = a[i] + b[i];
    float s = (tid < DD) ? v : 0.f;
    #pragma unroll
    for (int o = 16; o > 0; o >>= 1) s += __shfl_xor_sync(~0u, s, o);
    if ((tid & 31) == 0) red[tid >> 5] = s;
    __syncthreads();
    float mean = (red[0] + red[1] + red[2] + red[3]) / (float)DD;
    __syncthreads();
    float d = (tid < DD) ? (v - mean) : 0.f;
    float s2 = d * d;
    #pragma unroll
    for (int o = 16; o > 0; o >>= 1) s2 += __shfl_xor_sync(~0u, s2, o);
    if ((tid & 31) == 0) red[tid >> 5] = s2;
    __syncthreads();
    float var = (red[0] + red[1] + red[2] + red[3]) / (float)DD;
    if (tid < DD) out[i] = cvt_tf32(d * rsqrtf(var + 1e-5f) * gam[tid] + bet[tid]);
}

// ---------------- [T,N,D] -> [N, T*D] transpose --------------------------------
__global__ void transpose_h2_kernel(const float* __restrict__ h2, float* __restrict__ h2t)
{
    long idx = (long)blockIdx.x * 256 + threadIdx.x;
    if (idx >= (long)TN * DD) return;
    long t = idx / ((long)NPTS * DD);
    long r = idx - t * ((long)NPTS * DD);
    long n = r / DD;
    long d = r - n * DD;
    h2t[n * (long)TD + t * DD + d] = h2[idx];
}

// ---------------- split-K deterministic reduction (tf32 out) -------------------
__global__ void splitk_reduce_kernel(const float* __restrict__ part, const float* __restrict__ bias,
                                     float* __restrict__ y, int MN, int Z, int Nc)
{
    int i = blockIdx.x * 256 + threadIdx.x;
    if (i >= MN) return;
    float s = bias[i % Nc];
    for (int z = 0; z < Z; z++) s += part[(long)z * MN + i];
    y[i] = cvt_tf32(s);
}

#define GEMM(TB,RL,AC,SP, gx,gy,gz, A,B,bias,C, M,K,Nc, sA,sB,sC, RND) \
    gemm_kernel<TB,RL,AC,SP><<<dim3(gx,gy,gz), 256, SMEM_GEMM>>>(A,B,bias,C,M,K,Nc,sA,sB,sC,RND)

// ---------------- host orchestration ------------------------------------------
static void run_attention(const float* x4, const float* qw_r, const float* ow_r, const float* ob,
                          float* qkv, float* kvs, float* ksum, float* cat2, float* attout,
                          int rnd_att)
{
    GEMM(false,false,false,false, 5, (TN+127)/128, 1,
         x4, qw_r, nullptr, qkv, TN, DD, D3, 0,0,0, 0);
    kvs_kernel<<<dim3(TT, HH), 256>>>(qkv, (long)NPTS * D3, (long)D3, NPTS, kvs, ksum);
    attnout_kernel<<<dim3(NPTS, TT), 128>>>(qkv, (long)NPTS * D3, (long)D3, NPTS, kvs, ksum,
                                            cat2, (long)NPTS, 1, 0);
    kvs_kernel<<<dim3(NPTS, HH), 256>>>(qkv, (long)D3, (long)NPTS * D3, TT, kvs, ksum);
    attnout_kernel<<<dim3(TT, NPTS), 128>>>(qkv, (long)D3, (long)NPTS * D3, TT, kvs, ksum,
                                            cat2, 1, (long)NPTS, DD);
    GEMM(false,false,false,false, 2, (TN+127)/128, 1,
         cat2, ow_r, ob, attout, TN, D2, DD, 0,0,0, rnd_att);
}

extern "C" void kernel_launch(void* const* d_in, const int* in_sizes, int n_in,
                              void* d_out, int out_size)
{
    (void)in_sizes; (void)n_in; (void)out_size;
    const float* x     = (const float*)d_in[0];
    const float* W_in  = (const float*)d_in[1];
    const float* b_in  = (const float*)d_in[2];
    const float* adp   = (const float*)d_in[3];
    const float* W_tp  = (const float*)d_in[4];
    const float* b_tp  = (const float*)d_in[5];
    const float* qkv_w = (const float*)d_in[6];
    const float* op_w  = (const float*)d_in[7];
    const float* op_b  = (const float*)d_in[8];
    const float* pw_w  = (const float*)d_in[9];
    const float* pw_b  = (const float*)d_in[10];
    const float* fc_w1 = (const float*)d_in[11];
    const float* fc_b1 = (const float*)d_in[12];
    const float* fc_w2 = (const float*)d_in[13];
    const float* fc_b2 = (const float*)d_in[14];
    const float* ln1_g = (const float*)d_in[15];
    const float* ln1_b = (const float*)d_in[16];
    const float* ln2_g = (const float*)d_in[17];
    const float* ln2_b = (const float*)d_in[18];
    const float* ep_w  = (const float*)d_in[19];
    const float* ep_b  = (const float*)d_in[20];
    const float* enc_w1= (const float*)d_in[21];
    const float* enc_b1= (const float*)d_in[22];
    const float* enc_w2= (const float*)d_in[23];
    const float* enc_b2= (const float*)d_in[24];
    const float* out_w = (const float*)d_in[25];
    const float* out_b = (const float*)d_in[26];
    float* out = (float*)d_out;

    static int attr_done = 0;
    if (!attr_done) {
        cudaFuncSetAttribute(gemm_kernel<false,false,false,false>,
                             cudaFuncAttributeMaxDynamicSharedMemorySize, SMEM_GEMM);
        cudaFuncSetAttribute(gemm_kernel<true,false,false,false>,
                             cudaFuncAttributeMaxDynamicSharedMemorySize, SMEM_GEMM);
        cudaFuncSetAttribute(gemm_kernel<false,true,false,false>,
                             cudaFuncAttributeMaxDynamicSharedMemorySize, SMEM_GEMM);
        cudaFuncSetAttribute(gemm_kernel<false,false,true,false>,
                             cudaFuncAttributeMaxDynamicSharedMemorySize, SMEM_GEMM);
        cudaFuncSetAttribute(gemm_kernel<false,false,false,true>,
                             cudaFuncAttributeMaxDynamicSharedMemorySize, SMEM_GEMM);
        attr_done = 1;
    }

    float *hcat, *h, *graph, *z1, *qkv, *kvs, *ksum, *cat2, *att0, *att1;
    float *p0, *p1, *h1, *t2, *h2, *h2t, *part, *y, *yh, *wts;
    cudaGetSymbolAddress((void**)&hcat, g_hcat);
    cudaGetSymbolAddress((void**)&h,    g_h);
    cudaGetSymbolAddress((void**)&graph,g_graph);
    cudaGetSymbolAddress((void**)&z1,   g_z1);
    cudaGetSymbolAddress((void**)&qkv,  g_qkv);
    cudaGetSymbolAddress((void**)&kvs,  g_kvs);
    cudaGetSymbolAddress((void**)&ksum, g_ksum);
    cudaGetSymbolAddress((void**)&cat2, g_cat2);
    cudaGetSymbolAddress((void**)&att0, g_att0);
    cudaGetSymbolAddress((void**)&att1, g_att1);
    cudaGetSymbolAddress((void**)&p0,   g_p0);
    cudaGetSymbolAddress((void**)&p1,   g_p1);
    cudaGetSymbolAddress((void**)&h1,   g_h1);
    cudaGetSymbolAddress((void**)&t2,   g_t2);
    cudaGetSymbolAddress((void**)&h2,   g_h2);
    cudaGetSymbolAddress((void**)&h2t,  g_h2t);
    cudaGetSymbolAddress((void**)&part, g_part);
    cudaGetSymbolAddress((void**)&y,    g_y);
    cudaGetSymbolAddress((void**)&yh,   g_yh);
    cudaGetSymbolAddress((void**)&wts,  g_wts);

    float* adp_r  = wts + O_ADP;
    float* Wtp_r  = wts + O_WTP;
    float* qkvw_r = wts + O_QKVW;
    float* opw_r  = wts + O_OPW;
    float* pww_r  = wts + O_PWW;
    float* fc1_r  = wts + O_FC1;
    float* fc2_r  = wts + O_FC2;
    float* epw_r  = wts + O_EPW;
    float* enc1_r = wts + O_ENC1;
    float* enc2_r = wts + O_ENC2;
    float* outw_r = wts + O_OUTW;

    #define RND4(src, dst, n) round4_kernel<<<(((n)/4) + 255) / 256, 256>>>(src, dst, (n)/4)
    RND4(adp,    adp_r,  TT*NPTS*80);
    RND4(W_tp,   Wtp_r,  DD*DD);
    RND4(qkv_w,  qkvw_r, 2*DD*D3);
    RND4(op_w,   opw_r,  2*D2*DD);
    RND4(pw_w,   pww_r,  2*DD*DD);
    RND4(fc_w1,  fc1_r,  DD*D2);
    RND4(fc_w2,  fc2_r,  D2*DD);
    RND4(ep_w,   epw_r,  TD*DD);
    RND4(enc_w1, enc1_r, 3*DD*D2);
    RND4(enc_w2, enc2_r, 3*D2*DD);
    RND4(out_w,  outw_r, DD*TT);

    const int MY = (TN + 127) / 128;   // 1141

    hcat_kernel<<<((long)TN * DD + 255) / 256, 256>>>(x, W_in, b_in, adp_r, hcat);
    GEMM(false,false,false,false, 2, MY, 1,
         hcat, Wtp_r, b_tp, h, TN, DD, DD, 0,0,0, 1);
    GEMM(true,false,false,false, 7, 4, TT,
         adp_r, adp_r, nullptr, graph, NPTS, 80, NPTS,
         (long)NPTS*80, (long)NPTS*80, (long)NPTS*NPTS, 0);
    normgraph_kernel<<<(TN + 7) / 8, 256>>>(graph);
    GEMM(false,false,false,false, 2, 4, TT,
         graph, h, nullptr, z1, NPTS, NPTS, DD,
         (long)NPTS*NPTS, (long)NPTS*DD, (long)NPTS*DD, 1);
    run_attention(h,  qkvw_r,            opw_r,           op_b,      qkv, kvs, ksum, cat2, att0, 1);
    run_attention(z1, qkvw_r + DD * D3,  opw_r + D2 * DD, op_b + DD, qkv, kvs, ksum, cat2, att1, 0);
    GEMM(false,false,false,false, 2, MY, 1,
         h,    pww_r,           pw_b,      p0, TN, DD, DD, 0,0,0, 0);
    GEMM(false,false,false,false, 2, MY, 1,
         att0, pww_r + DD * DD, pw_b + DD, p1, TN, DD, DD, 0,0,0, 0);
    combine_ln_kernel<<<TN, 128>>>(h, att0, att1, p0, p1, ln1_g, ln1_b, h1);
    GEMM(false,true,false,false, 4, MY, 1,
         h1, fc1_r, fc_b1, cat2, TN, DD, D2, 0,0,0, 1);
    GEMM(false,false,false,false, 2, MY, 1,
         cat2, fc2_r, fc_b2, t2, TN, D2, DD, 0,0,0, 0);
    ln_res_kernel<<<TN, 128>>>(h1, t2, ln2_g, ln2_b, h2);
    transpose_h2_kernel<<<((long)TN * DD + 255) / 256, 256>>>(h2, h2t);
    GEMM(false,false,false,true, 2, 4, SPLITK,
         h2t, epw_r, nullptr, part, NPTS, TD, DD, 0,0,0, 0);
    splitk_reduce_kernel<<<(NPTS * DD + 255) / 256, 256>>>(part, ep_b, y, NPTS * DD, SPLITK, DD);
    for (int i = 0; i < 3; i++) {
        GEMM(false,true,false,false, 4, 4, 1,
             y,  enc1_r + (long)i * DD * D2, enc_b1 + (long)i * D2, yh, NPTS, DD, D2, 0,0,0, 1);
        GEMM(false,false,true,false, 2, 4, 1,
             yh, enc2_r + (long)i * D2 * DD, enc_b2 + (long)i * DD, y,  NPTS, D2, DD, 0,0,0, 1);
    }
    GEMM(false,false,false,false, 6, 4, 1,
         y, outw_r, out_b, out, NPTS, DD, TT, 0,0,0, 0);
}

// round 7
// speedup vs baseline: 1.9377x; 1.0492x over previous
#include <cuda_runtime.h>
#include <math.h>

#define TT   365
#define NPTS 400
#define DD   104
#define HH   4
#define HD   26
#define TN   (TT*NPTS)      // 146000
#define D2   (2*DD)         // 208
#define D3   (3*DD)         // 312
#define TD   (TT*DD)        // 37960
#define SPLITK 40
#define KCHUNK 960
#define SMA  36              // A-stage smem row stride (32 k + 4 pad)
#define A_ST (128*SMA)       // 4608 floats per A stage
#define B_ST (64*SMA)        // 2304 floats per B stage (batched kernel)
#define SMEM_GEMM ((3*A_ST + 3*B_ST)*4)   // 82944 bytes
#define SMEM_STREAM_MAX ((3*A_ST + 64*228)*4)  // 113664 bytes (K=208)

// ---------------- scratch (device globals; no runtime allocation) -------------
__device__ float g_hcat[(size_t)TN*DD];
__device__ float g_h   [(size_t)TN*DD];
__device__ float g_graph[(size_t)TT*NPTS*NPTS];
__device__ float g_z1  [(size_t)TN*DD];
__device__ float g_qkv [(size_t)TN*D3];
__device__ float g_kvs [(size_t)NPTS*HH*HD*HD];
__device__ float g_ksum[(size_t)NPTS*HH*HD];
__device__ float g_cat2[(size_t)TN*D2];
__device__ float g_att0[(size_t)TN*DD];
__device__ float g_att1[(size_t)TN*DD];
__device__ float g_p0  [(size_t)TN*DD];
__device__ float g_p1  [(size_t)TN*DD];
__device__ float g_h1  [(size_t)TN*DD];
__device__ float g_t2  [(size_t)TN*DD];
__device__ float g_h2  [(size_t)TN*DD];
__device__ float g_h2t [(size_t)NPTS*TD];
__device__ float g_part[(size_t)SPLITK*NPTS*DD];
__device__ float g_y   [(size_t)NPTS*DD];
__device__ float g_yh  [(size_t)NPTS*D2];
__device__ float g_wts [(size_t)16000000];   // tf32-rounded weights arena

// offsets into g_wts (floats)
#define O_ADP   0L
#define O_WTP   11680000L
#define O_QKVW  11690816L
#define O_OPW   11755712L
#define O_PWW   11798976L
#define O_FC1   11820608L
#define O_FC2   11842240L
#define O_EPW   11863872L
#define O_ENC1  15811712L
#define O_ENC2  15876608L
#define O_OUTW  15941504L

// ---------------- tf32 helpers -------------------------------------------------
__device__ __forceinline__ float cvt_tf32(float f)
{
    unsigned u;
    asm("cvt.rna.tf32.f32 %0, %1;" : "=r"(u) : "f"(f));
    return __uint_as_float(u);
}

// ---------------- cp.async issue helpers ---------------------------------------
__device__ __forceinline__ void issue_a(const float* __restrict__ A, unsigned sAs,
                                        int bm, int k0, int kend, int M, int K, int tid)
{
    #pragma unroll
    for (int p = 0; p < 4; p++) {
        int idx = tid + p * 256;
        int m = idx >> 3, kq = (idx & 7) << 2;
        int gm = bm + m;
        int rem = kend - (k0 + kq);
        int sz = (gm < M) ? min(max(rem, 0) * 4, 16) : 0;
        const float* src = (sz > 0) ? A + (long)gm * K + k0 + kq : A;
        unsigned dst = sAs + (unsigned)(m * SMA + kq) * 4u;
        asm volatile("cp.async.cg.shared.global [%0],[%1],16,%2;"
                     :: "r"(dst), "l"(src), "r"(sz));
    }
}

template<bool TRANSB>
__device__ __forceinline__ void issue_b(const float* __restrict__ B, unsigned sBs,
                                        int bn, int k0, int kend, int Nc, int K, int tid)
{
    if (TRANSB) {
        #pragma unroll
        for (int p = 0; p < 2; p++) {
            int idx = tid + p * 256;
            int n = idx >> 3, kq = (idx & 7) << 2;
            int gn = bn + n;
            int rem = kend - (k0 + kq);
            int sz = (gn < Nc) ? min(max(rem, 0) * 4, 16) : 0;
            const float* src = (sz > 0) ? B + (long)gn * K + k0 + kq : B;
            unsigned dst = sBs + (unsigned)(n * SMA + kq) * 4u;
            asm volatile("cp.async.cg.shared.global [%0],[%1],16,%2;"
                         :: "r"(dst), "l"(src), "r"(sz));
        }
    } else {
        #pragma unroll
        for (int p = 0; p < 8; p++) {
            int e = tid + p * 256;
            int k = e >> 6, n = e & 63;
            int gk = k0 + k, gn = bn + n;
            int sz = (gk < kend && gn < Nc) ? 4 : 0;
            const float* src = sz ? B + (long)gk * Nc + gn : B;
            unsigned dst = sBs + (unsigned)(n * SMA + k) * 4u;
            asm volatile("cp.async.ca.shared.global [%0],[%1],4,%2;"
                         :: "r"(dst), "l"(src), "r"(sz));
        }
    }
}

// ---------------- tf32 MMA on a k32 chunk (B row stride sb) --------------------
__device__ __forceinline__ void mma_chunk(const float* __restrict__ As,
                                          const float* __restrict__ Bs, int sb,
                                          int wm, int wn, int lane, float (*acc)[4][4])
{
    int r = lane >> 2, c = lane & 3;
    #pragma unroll
    for (int ks = 0; ks < 4; ks++) {
        int k0 = ks * 8;
        unsigned a[2][4], b[4][2];
        #pragma unroll
        for (int mt = 0; mt < 2; mt++) {
            const float* p = As + (wm * 32 + mt * 16 + r) * SMA + k0 + c;
            a[mt][0] = __float_as_uint(p[0]);
            a[mt][1] = __float_as_uint(p[8 * SMA]);
            a[mt][2] = __float_as_uint(p[4]);
            a[mt][3] = __float_as_uint(p[8 * SMA + 4]);
        }
        #pragma unroll
        for (int nt = 0; nt < 4; nt++) {
            const float* p = Bs + (wn * 32 + nt * 8 + r) * sb + k0 + c;
            b[nt][0] = __float_as_uint(p[0]);
            b[nt][1] = __float_as_uint(p[4]);
        }
        #pragma unroll
        for (int mt = 0; mt < 2; mt++)
            #pragma unroll
            for (int nt = 0; nt < 4; nt++)
                asm("mma.sync.aligned.m16n8k8.row.col.f32.tf32.tf32.f32 "
                    "{%0,%1,%2,%3},{%4,%5,%6,%7},{%8,%9},{%0,%1,%2,%3};"
                    : "+f"(acc[mt][nt][0]), "+f"(acc[mt][nt][1]),
                      "+f"(acc[mt][nt][2]), "+f"(acc[mt][nt][3])
                    : "r"(a[mt][0]), "r"(a[mt][1]), "r"(a[mt][2]), "r"(a[mt][3]),
                      "r"(b[nt][0]), "r"(b[nt][1]));
    }
}

// ---------------- epilogue ------------------------------------------------------
template<bool RELU, bool ACC, bool SPLIT>
__device__ __forceinline__ void epilogue(float (*acc)[4][4], const float* bias,
                                         float* __restrict__ C, int bm, int bn,
                                         int M, int Nc, int wm, int wn, int lane, int rnd)
{
    int r = lane >> 2, c2 = (lane & 3) << 1;
    #pragma unroll
    for (int mt = 0; mt < 2; mt++) {
        #pragma unroll
        for (int nt = 0; nt < 4; nt++) {
            int gm0 = bm + wm * 32 + mt * 16 + r;
            int gn0 = bn + wn * 32 + nt * 8 + c2;
            #pragma unroll
            for (int hh = 0; hh < 2; hh++) {
                int gm = gm0 + hh * 8;
                if (gm >= M) continue;
                #pragma unroll
                for (int j = 0; j < 2; j++) {
                    int gn = gn0 + j;
                    if (gn >= Nc) continue;
                    float v = acc[mt][nt][hh * 2 + j];
                    if (!SPLIT && bias) v += bias[gn];
                    if (RELU) v = fmaxf(v, 0.f);
                    long ci = (long)gm * Nc + gn;
                    if (ACC) v += C[ci];
                    if (rnd) v = cvt_tf32(v);
                    C[ci] = v;
                }
            }
        }
    }
}

// ---------------- batched / split tf32 GEMM (3-stage per-block pipeline) --------
template<bool TRANSB, bool RELU, bool ACC, bool SPLIT>
__global__ void __launch_bounds__(256)
gemm_kernel(const float* __restrict__ A, const float* __restrict__ B,
            const float* __restrict__ bias, float* __restrict__ C,
            int M, int K, int Nc, long sA, long sB_, long sC, int rnd)
{
    extern __shared__ float dsm[];
    int tid = threadIdx.x;
    int bm = blockIdx.y * 128, bn = blockIdx.x * 64;
    int kbeg = 0, kend = K;
    if (SPLIT) {
        int z = blockIdx.z;
        kbeg = z * KCHUNK;
        kend = min(K, kbeg + KCHUNK);
        C += (long)z * M * Nc;
    } else {
        int z = blockIdx.z;
        A += z * sA; B += z * sB_; C += z * sC;
    }
    int w = tid >> 5, lane = tid & 31;
    int wm = w >> 1, wn = w & 1;
    float acc[2][4][4];
    #pragma unroll
    for (int mt = 0; mt < 2; mt++)
        #pragma unroll
        for (int nt = 0; nt < 4; nt++)
            #pragma unroll
            for (int q = 0; q < 4; q++) acc[mt][nt][q] = 0.f;

    unsigned sbase = (unsigned)__cvta_generic_to_shared(dsm);
    unsigned sA0 = sbase;
    unsigned sB0 = sbase + 3u * A_ST * 4u;

    int nk = (kend - kbeg + 31) >> 5;
    issue_a(A, sA0, bm, kbeg, kend, M, K, tid);
    issue_b<TRANSB>(B, sB0, bn, kbeg, kend, Nc, K, tid);
    asm volatile("cp.async.commit_group;" ::: "memory");
    issue_a(A, sA0 + A_ST * 4u, bm, kbeg + 32, kend, M, K, tid);
    issue_b<TRANSB>(B, sB0 + B_ST * 4u, bn, kbeg + 32, kend, Nc, K, tid);
    asm volatile("cp.async.commit_group;" ::: "memory");

    for (int it = 0; it < nk; it++) {
        asm volatile("cp.async.wait_group 1;" ::: "memory");
        __syncthreads();
        int s2 = (it + 2) % 3;
        int kn = kbeg + (it + 2) * 32;
        issue_a(A, sA0 + (unsigned)s2 * A_ST * 4u, bm, kn, kend, M, K, tid);
        issue_b<TRANSB>(B, sB0 + (unsigned)s2 * B_ST * 4u, bn, kn, kend, Nc, K, tid);
        asm volatile("cp.async.commit_group;" ::: "memory");
        int sc = it % 3;
        mma_chunk(dsm + sc * A_ST, dsm + 3 * A_ST + sc * B_ST, SMA, wm, wn, lane, acc);
    }
    epilogue<RELU, ACC, SPLIT>(acc, bias, C, bm, bn, M, Nc, wm, wn, lane, rnd);
}

// ---------------- persistent-B streaming GEMM (NN, non-batched) -----------------
// B for this block's 64-column slab resident in smem for ALL K; block grid-strides
// over M-tiles with a flat 3-stage A pipeline that never drains between tiles.
template<bool RELU, bool ACC>
__global__ void __launch_bounds__(256)
gemm_stream(const float* __restrict__ A, const float* __restrict__ B,
            const float* __restrict__ bias, float* __restrict__ C,
            int M, int K, int Nc, int KP, int rnd)
{
    extern __shared__ float dsm[];
    float* Asm = dsm;
    float* Bsm = dsm + 3 * A_ST;
    int tid = threadIdx.x;
    int bn = blockIdx.x * 64;
    int nkc = (K + 31) >> 5;
    int KP32 = nkc * 32;
    int MT = (M + 127) >> 7;
    int w = tid >> 5, lane = tid & 31;
    int wm = w >> 1, wn = w & 1;

    unsigned sbase = (unsigned)__cvta_generic_to_shared(dsm);
    unsigned sA0 = sbase;
    unsigned sB0 = sbase + 3u * A_ST * 4u;

    // ---- one-time B load: Bsm[n][k], zero-filled beyond K / Nc ----
    for (int e = tid; e < 64 * KP32; e += 256) {
        int n = e / KP32, k = e - n * KP32;
        int gn = bn + n;
        int sz = (gn < Nc && k < K) ? 4 : 0;
        const float* src = sz ? B + (long)k * Nc + gn : B;
        unsigned dst = sB0 + (unsigned)(n * KP + k) * 4u;
        asm volatile("cp.async.ca.shared.global [%0],[%1],4,%2;"
                     :: "r"(dst), "l"(src), "r"(sz));
    }

    // ---- issue cursor over flat (mt, kc) pieces ----
    int mt_i = blockIdx.x * 0 + blockIdx.y;   // issue m-tile
    int kc_i = 0;
    // piece 0 (grouped with B)
    if (mt_i < MT) issue_a(A, sA0, mt_i * 128, 0, K, M, K, tid);
    asm volatile("cp.async.commit_group;" ::: "memory");
    if (++kc_i == nkc) { kc_i = 0; mt_i += gridDim.y; }
    // piece 1
    if (mt_i < MT) issue_a(A, sA0 + A_ST * 4u, mt_i * 128, kc_i * 32, K, M, K, tid);
    asm volatile("cp.async.commit_group;" ::: "memory");
    if (++kc_i == nkc) { kc_i = 0; mt_i += gridDim.y; }

    float acc[2][4][4];
    int stage = 0;
    for (int mt = blockIdx.y; mt < MT; mt += gridDim.y) {
        #pragma unroll
        for (int mtt = 0; mtt < 2; mtt++)
            #pragma unroll
            for (int nt = 0; nt < 4; nt++)
                #pragma unroll
                for (int q = 0; q < 4; q++) acc[mtt][nt][q] = 0.f;
        for (int kc = 0; kc < nkc; kc++) {
            asm volatile("cp.async.wait_group 1;" ::: "memory");
            __syncthreads();
            int s2 = (stage + 2) % 3;
            if (mt_i < MT) issue_a(A, sA0 + (unsigned)s2 * A_ST * 4u,
                                   mt_i * 128, kc_i * 32, K, M, K, tid);
            asm volatile("cp.async.commit_group;" ::: "memory");
            if (++kc_i == nkc) { kc_i = 0; mt_i += gridDim.y; }
            mma_chunk(Asm + stage * A_ST, Bsm + kc * 32, KP, wm, wn, lane, acc);
            stage = (stage + 1) % 3;
        }
        epilogue<RELU, ACC, false>(acc, bias, C, mt * 128, bn, M, Nc, wm, wn, lane, rnd);
    }
}

// ---------------- fused relu-softmax normalize (+tf32 round) in place ----------
__global__ void normgraph_kernel(float* __restrict__ g)
{
    long row = (long)blockIdx.x * 8 + (threadIdx.x >> 5);
    if (row >= (long)TN) return;
    int lane = threadIdx.x & 31;
    float4* p = reinterpret_cast<float4*>(g + row * NPTS);  // 100 float4
    float4 vv[4];
    float m = 0.f;
    #pragma unroll
    for (int r = 0; r < 4; r++) {
        int c = lane + r * 32;
        vv[r] = (c < 100) ? p[c] : make_float4(0.f, 0.f, 0.f, 0.f);
        m = fmaxf(m, fmaxf(fmaxf(vv[r].x, vv[r].y), fmaxf(vv[r].z, vv[r].w)));
    }
    #pragma unroll
    for (int o = 16; o > 0; o >>= 1) m = fmaxf(m, __shfl_xor_sync(~0u, m, o));
    float s = 0.f;
    #pragma unroll
    for (int r = 0; r < 4; r++) {
        int c = lane + r * 32;
        if (c < 100) {
            vv[r].x = __expf(fmaxf(vv[r].x, 0.f) - m);
            vv[r].y = __expf(fmaxf(vv[r].y, 0.f) - m);
            vv[r].z = __expf(fmaxf(vv[r].z, 0.f) - m);
            vv[r].w = __expf(fmaxf(vv[r].w, 0.f) - m);
            s += vv[r].x + vv[r].y + vv[r].z + vv[r].w;
        }
    }
    #pragma unroll
    for (int o = 16; o > 0; o >>= 1) s += __shfl_xor_sync(~0u, s, o);
    float inv = 1.f / s;
    #pragma unroll
    for (int r = 0; r < 4; r++) {
        int c = lane + r * 32;
        if (c < 100) {
            float4 ov;
            ov.x = cvt_tf32(vv[r].x * inv);
            ov.y = cvt_tf32(vv[r].y * inv);
            ov.z = cvt_tf32(vv[r].z * inv);
            ov.w = cvt_tf32(vv[r].w * inv);
            p[c] = ov;
        }
    }
}

// ---------------- weight tf32 rounding copy ------------------------------------
__global__ void round4_kernel(const float* __restrict__ src, float* __restrict__ dst, int n4)
{
    int i = blockIdx.x * 256 + threadIdx.x;
    if (i >= n4) return;
    float4 v = reinterpret_cast<const float4*>(src)[i];
    v.x = cvt_tf32(v.x); v.y = cvt_tf32(v.y);
    v.z = cvt_tf32(v.z); v.w = cvt_tf32(v.w);
    reinterpret_cast<float4*>(dst)[i] = v;
}

// ---------------- input proj + concat adaptive embedding (tf32 out) ------------
__global__ void hcat_kernel(const float* __restrict__ x, const float* __restrict__ W_in,
                            const float* __restrict__ b_in, const float* __restrict__ adp_r,
                            float* __restrict__ hcat)
{
    long idx = (long)blockIdx.x * 256 + threadIdx.x;
    if (idx >= (long)TN * DD) return;
    long tn = idx / DD; int j = (int)(idx - tn * DD);
    int t = (int)(tn / NPTS), n = (int)(tn - (long)t * NPTS);
    float v;
    if (j < 24) {
        const float* xr = x + ((long)n * TT + t) * 3;
        v = cvt_tf32(b_in[j] + xr[0] * W_in[0 * 24 + j] + xr[1] * W_in[1 * 24 + j]
                     + xr[2] * W_in[2 * 24 + j]);
    } else {
        v = adp_r[tn * 80 + (j - 24)];   // already rounded
    }
    hcat[idx] = v;
}

// ---------------- linear attention: kvs + ksum (warp-parallel over L) ----------
__global__ void kvs_kernel(const float* __restrict__ qkv, long sB, long sL, int L,
                           float* __restrict__ kvs, float* __restrict__ ksum)
{
    int b = blockIdx.x, h = blockIdx.y;
    int w = threadIdx.x >> 5, lane = threadIdx.x & 31;
    int chunk = (L + 7) >> 3;
    int l0 = w * chunk, l1 = min(L, l0 + chunk);
    const float* base = qkv + (long)b * sB + h * HD;
    float acc[HD];
    #pragma unroll
    for (int m = 0; m < HD; m++) acc[m] = 0.f;
    float accs = 0.f;
    for (int l = l0; l < l1; l++) {
        const float* row = base + (long)l * sL;
        float kk = (lane < HD) ? row[DD + lane] : 0.f;
        float vv = (lane < HD) ? row[2 * DD + lane] : 0.f;
        float ss = kk * kk;
        #pragma unroll
        for (int o = 16; o > 0; o >>= 1) ss += __shfl_xor_sync(~0u, ss, o);
        float inv = 1.f / fmaxf(sqrtf(ss), 1e-12f);
        float kin = kk * inv;
        accs += kin;
        #pragma unroll
        for (int m = 0; m < HD; m++) {
            float km = __shfl_sync(~0u, kin, m);
            acc[m] += km * vv;
        }
    }
    __shared__ float red[8][HD][HD + 2];
    __shared__ float redk[8][32];
    if (lane < HD) {
        #pragma unroll
        for (int m = 0; m < HD; m++) red[w][m][lane] = acc[m];
    }
    redk[w][lane] = accs;
    __syncthreads();
    long basec = ((long)b * HH + h);
    for (int cell = threadIdx.x; cell < HD * HD; cell += 256) {
        int m = cell / HD, d = cell - m * HD;
        float s = 0.f;
        #pragma unroll
        for (int ww = 0; ww < 8; ww++) s += red[ww][m][d];
        kvs[basec * (HD * HD) + cell] = s;
    }
    if (threadIdx.x < HD) {
        float s = 0.f;
        #pragma unroll
        for (int ww = 0; ww < 8; ww++) s += redk[ww][threadIdx.x];
        ksum[basec * HD + threadIdx.x] = s;
    }
}

// ---------------- linear attention: per-token output (tf32-rounded out) --------
__global__ void attnout_kernel(const float* __restrict__ qkv, long sB, long sL, int L,
                               const float* __restrict__ kvs, const float* __restrict__ ksum,
                               float* __restrict__ outb, long oB, long oL, int ooff)
{
    int l = blockIdx.x, b = blockIdx.y;
    int tid = threadIdx.x;
    const float* row = qkv + (long)b * sB + (long)l * sL;
    __shared__ float sq[DD], sv[DD], sinv[HH], sden[HH];
    if (tid < DD) { sq[tid] = row[tid]; sv[tid] = row[2 * DD + tid]; }
    __syncthreads();
    if (tid < HH) {
        const float* qh = sq + tid * HD;
        float ss = 0.f;
        #pragma unroll
        for (int m = 0; m < HD; m++) ss += qh[m] * qh[m];
        float inv = 1.f / fmaxf(sqrtf(ss), 1e-12f);
        sinv[tid] = inv;
        const float* ks = ksum + ((long)b * HH + tid) * HD;
        float dd = 0.f;
        #pragma unroll
        for (int m = 0; m < HD; m++) dd += qh[m] * ks[m];
        sden[tid] = dd * inv + (float)L;
    }
    __syncthreads();
    if (tid < DD) {
        int h = tid / HD, d = tid - h * HD;
        const float* kv = kvs + ((long)b * HH + h) * (HD * HD) + d;
        const float* qh = sq + h * HD;
        float s = 0.f;
        #pragma unroll
        for (int m = 0; m < HD; m++) s += qh[m] * kv[m * HD];
        float num = s * sinv[h] + (float)L * sv[tid];
        outb[((long)b * oB + (long)l * oL) * D2 + ooff + tid] = cvt_tf32(num / sden[h]);
    }
}

// ---------------- fused combine + LayerNorm (tf32 out) -------------------------
__global__ void combine_ln_kernel(const float* __restrict__ h, const float* __restrict__ a0,
                                  const float* __restrict__ a1, const float* __restrict__ p0,
                                  const float* __restrict__ p1, const float* __restrict__ gam,
                                  const float* __restrict__ bet, float* __restrict__ out)
{
    long row = blockIdx.x; int tid = threadIdx.x;  // 128
    __shared__ float red[4];
    long i = row * DD + tid;
    float v = 0.f;
    if (tid < DD) v = 2.f * (h[i] + a0[i] * p0[i] + 0.01f * a1[i] * p1[i]);
    float s = (tid < DD) ? v : 0.f;
    #pragma unroll
    for (int o = 16; o > 0; o >>= 1) s += __shfl_xor_sync(~0u, s, o);
    if ((tid & 31) == 0) red[tid >> 5] = s;
    __syncthreads();
    float mean = (red[0] + red[1] + red[2] + red[3]) / (float)DD;
    __syncthreads();
    float d = (tid < DD) ? (v - mean) : 0.f;
    float s2 = d * d;
    #pragma unroll
    for (int o = 16; o > 0; o >>= 1) s2 += __shfl_xor_sync(~0u, s2, o);
    if ((tid & 31) == 0) red[tid >> 5] = s2;
    __syncthreads();
    float var = (red[0] + red[1] + red[2] + red[3]) / (float)DD;
    if (tid < DD) out[i] = cvt_tf32(d * rsqrtf(var + 1e-5f) * gam[tid] + bet[tid]);
}

__global__ void ln_res_kernel(const float* __restrict__ a, const float* __restrict__ b,
                              const float* __restrict__ gam, const float* __restrict__ bet,
                              float* __restrict__ out)
{
    long row = blockIdx.x; int tid = threadIdx.x;  // 128
    __shared__ float red[4];
    long i = row * DD + tid;
    float v = 0.f;
    if (tid < DD) v = a[i] + b[i];
    float s = (tid < DD) ? v : 0.f;
    #pragma unroll
    for (int o = 16; o > 0; o >>= 1) s += __shfl_xor_sync(~0u, s, o);
    if ((tid & 31) == 0) red[tid >> 5] = s;
    __syncthreads();
    float mean = (red[0] + red[1] + red[2] + red[3]) / (float)DD;
    __syncthreads();
    float d = (tid < DD) ? (v - mean) : 0.f;
    float s2 = d * d;
    #pragma unroll
    for (int o = 16; o > 0; o >>= 1) s2 += __shfl_xor_sync(~0u, s2, o);
    if ((tid & 31) == 0) red[tid >> 5] = s2;
    __syncthreads();
    float var = (red[0] + red[1] + red[2] + red[3]) / (float)DD;
    if (tid < DD) out[i] = cvt_tf32(d * rsqrtf(var + 1e-5f) * gam[tid] + bet[tid]);
}

// ---------------- [T,N,D] -> [N, T*D] transpose --------------------------------
__global__ void transpose_h2_kernel(const float* __restrict__ h2, float* __restrict__ h2t)
{
    long idx = (long)blockIdx.x * 256 + threadIdx.x;
    if (idx >= (long)TN * DD) return;
    long t = idx / ((long)NPTS * DD);
    long r = idx - t * ((long)NPTS * DD);
    long n = r / DD;
    long d = r - n * DD;
    h2t[n * (long)TD + t * DD + d] = h2[idx];
}

// ---------------- split-K deterministic reduction (tf32 out) -------------------
__global__ void splitk_reduce_kernel(const float* __restrict__ part, const float* __restrict__ bias,
                                     float* __restrict__ y, int MN, int Z, int Nc)
{
    int i = blockIdx.x * 256 + threadIdx.x;
    if (i >= MN) return;
    float s = bias[i % Nc];
    for (int z = 0; z < Z; z++) s += part[(long)z * MN + i];
    y[i] = cvt_tf32(s);
}

#define GEMM(TB,RL,AC,SP, gx,gy,gz, A,B,bias,C, M,K,Nc, sA,sB,sC, RND) \
    gemm_kernel<TB,RL,AC,SP><<<dim3(gx,gy,gz), 256, SMEM_GEMM>>>(A,B,bias,C,M,K,Nc,sA,sB,sC,RND)

// ---------------- streaming GEMM launcher --------------------------------------
static void launch_stream(const float* A, const float* B, const float* bias, float* C,
                          int M, int K, int Nc, int rnd, bool relu, bool accf)
{
    int nkc = (K + 31) / 32;
    int KP = nkc * 32 + 4;
    int smem = (3 * A_ST + 64 * KP) * 4;
    int nx = (Nc + 63) / 64;
    int MT = (M + 127) / 128;
    int gy = (296 + nx - 1) / nx;
    if (gy > MT) gy = MT;
    dim3 g(nx, gy);
    if (relu)      gemm_stream<true,  false><<<g, 256, smem>>>(A, B, bias, C, M, K, Nc, KP, rnd);
    else if (accf) gemm_stream<false, true ><<<g, 256, smem>>>(A, B, bias, C, M, K, Nc, KP, rnd);
    else           gemm_stream<false, false><<<g, 256, smem>>>(A, B, bias, C, M, K, Nc, KP, rnd);
}

// ---------------- host orchestration ------------------------------------------
static void run_attention(const float* x4, const float* qw_r, const float* ow_r, const float* ob,
                          float* qkv, float* kvs, float* ksum, float* cat2, float* attout,
                          int rnd_att)
{
    launch_stream(x4, qw_r, nullptr, qkv, TN, DD, D3, 0, false, false);
    kvs_kernel<<<dim3(TT, HH), 256>>>(qkv, (long)NPTS * D3, (long)D3, NPTS, kvs, ksum);
    attnout_kernel<<<dim3(NPTS, TT), 128>>>(qkv, (long)NPTS * D3, (long)D3, NPTS, kvs, ksum,
                                            cat2, (long)NPTS, 1, 0);
    kvs_kernel<<<dim3(NPTS, HH), 256>>>(qkv, (long)D3, (long)NPTS * D3, TT, kvs, ksum);
    attnout_kernel<<<dim3(TT, NPTS), 128>>>(qkv, (long)D3, (long)NPTS * D3, TT, kvs, ksum,
                                            cat2, 1, (long)NPTS, DD);
    launch_stream(cat2, ow_r, ob, attout, TN, D2, DD, rnd_att, false, false);
}

extern "C" void kernel_launch(void* const* d_in, const int* in_sizes, int n_in,
                              void* d_out, int out_size)
{
    (void)in_sizes; (void)n_in; (void)out_size;
    const float* x     = (const float*)d_in[0];
    const float* W_in  = (const float*)d_in[1];
    const float* b_in  = (const float*)d_in[2];
    const float* adp   = (const float*)d_in[3];
    const float* W_tp  = (const float*)d_in[4];
    const float* b_tp  = (const float*)d_in[5];
    const float* qkv_w = (const float*)d_in[6];
    const float* op_w  = (const float*)d_in[7];
    const float* op_b  = (const float*)d_in[8];
    const float* pw_w  = (const float*)d_in[9];
    const float* pw_b  = (const float*)d_in[10];
    const float* fc_w1 = (const float*)d_in[11];
    const float* fc_b1 = (const float*)d_in[12];
    const float* fc_w2 = (const float*)d_in[13];
    const float* fc_b2 = (const float*)d_in[14];
    const float* ln1_g = (const float*)d_in[15];
    const float* ln1_b = (const float*)d_in[16];
    const float* ln2_g = (const float*)d_in[17];
    const float* ln2_b = (const float*)d_in[18];
    const float* ep_w  = (const float*)d_in[19];
    const float* ep_b  = (const float*)d_in[20];
    const float* enc_w1= (const float*)d_in[21];
    const float* enc_b1= (const float*)d_in[22];
    const float* enc_w2= (const float*)d_in[23];
    const float* enc_b2= (const float*)d_in[24];
    const float* out_w = (const float*)d_in[25];
    const float* out_b = (const float*)d_in[26];
    float* out = (float*)d_out;

    static int attr_done = 0;
    if (!attr_done) {
        cudaFuncSetAttribute(gemm_kernel<false,false,false,false>,
                             cudaFuncAttributeMaxDynamicSharedMemorySize, SMEM_GEMM);
        cudaFuncSetAttribute(gemm_kernel<true,false,false,false>,
                             cudaFuncAttributeMaxDynamicSharedMemorySize, SMEM_GEMM);
        cudaFuncSetAttribute(gemm_kernel<false,false,false,true>,
                             cudaFuncAttributeMaxDynamicSharedMemorySize, SMEM_GEMM);
        cudaFuncSetAttribute(gemm_stream<false,false>,
                             cudaFuncAttributeMaxDynamicSharedMemorySize, SMEM_STREAM_MAX);
        cudaFuncSetAttribute(gemm_stream<true,false>,
                             cudaFuncAttributeMaxDynamicSharedMemorySize, SMEM_STREAM_MAX);
        cudaFuncSetAttribute(gemm_stream<false,true>,
                             cudaFuncAttributeMaxDynamicSharedMemorySize, SMEM_STREAM_MAX);
        attr_done = 1;
    }

    float *hcat, *h, *graph, *z1, *qkv, *kvs, *ksum, *cat2, *att0, *att1;
    float *p0, *p1, *h1, *t2, *h2, *h2t, *part, *y, *yh, *wts;
    cudaGetSymbolAddress((void**)&hcat, g_hcat);
    cudaGetSymbolAddress((void**)&h,    g_h);
    cudaGetSymbolAddress((void**)&graph,g_graph);
    cudaGetSymbolAddress((void**)&z1,   g_z1);
    cudaGetSymbolAddress((void**)&qkv,  g_qkv);
    cudaGetSymbolAddress((void**)&kvs,  g_kvs);
    cudaGetSymbolAddress((void**)&ksum, g_ksum);
    cudaGetSymbolAddress((void**)&cat2, g_cat2);
    cudaGetSymbolAddress((void**)&att0, g_att0);
    cudaGetSymbolAddress((void**)&att1, g_att1);
    cudaGetSymbolAddress((void**)&p0,   g_p0);
    cudaGetSymbolAddress((void**)&p1,   g_p1);
    cudaGetSymbolAddress((void**)&h1,   g_h1);
    cudaGetSymbolAddress((void**)&t2,   g_t2);
    cudaGetSymbolAddress((void**)&h2,   g_h2);
    cudaGetSymbolAddress((void**)&h2t,  g_h2t);
    cudaGetSymbolAddress((void**)&part, g_part);
    cudaGetSymbolAddress((void**)&y,    g_y);
    cudaGetSymbolAddress((void**)&yh,   g_yh);
    cudaGetSymbolAddress((void**)&wts,  g_wts);

    float* adp_r  = wts + O_ADP;
    float* Wtp_r  = wts + O_WTP;
    float* qkvw_r = wts + O_QKVW;
    float* opw_r  = wts + O_OPW;
    float* pww_r  = wts + O_PWW;
    float* fc1_r  = wts + O_FC1;
    float* fc2_r  = wts + O_FC2;
    float* epw_r  = wts + O_EPW;
    float* enc1_r = wts + O_ENC1;
    float* enc2_r = wts + O_ENC2;
    float* outw_r = wts + O_OUTW;

    #define RND4(src, dst, n) round4_kernel<<<(((n)/4) + 255) / 256, 256>>>(src, dst, (n)/4)
    RND4(adp,    adp_r,  TT*NPTS*80);
    RND4(W_tp,   Wtp_r,  DD*DD);
    RND4(qkv_w,  qkvw_r, 2*DD*D3);
    RND4(op_w,   opw_r,  2*D2*DD);
    RND4(pw_w,   pww_r,  2*DD*DD);
    RND4(fc_w1,  fc1_r,  DD*D2);
    RND4(fc_w2,  fc2_r,  D2*DD);
    RND4(ep_w,   epw_r,  TD*DD);
    RND4(enc_w1, enc1_r, 3*DD*D2);
    RND4(enc_w2, enc2_r, 3*D2*DD);
    RND4(out_w,  outw_r, DD*TT);

    hcat_kernel<<<((long)TN * DD + 255) / 256, 256>>>(x, W_in, b_in, adp_r, hcat);
    launch_stream(hcat, Wtp_r, b_tp, h, TN, DD, DD, 1, false, false);
    GEMM(true,false,false,false, 7, 4, TT,
         adp_r, adp_r, nullptr, graph, NPTS, 80, NPTS,
         (long)NPTS*80, (long)NPTS*80, (long)NPTS*NPTS, 0);
    normgraph_kernel<<<(TN + 7) / 8, 256>>>(graph);
    GEMM(false,false,false,false, 2, 4, TT,
         graph, h, nullptr, z1, NPTS, NPTS, DD,
         (long)NPTS*NPTS, (long)NPTS*DD, (long)NPTS*DD, 1);
    run_attention(h,  qkvw_r,            opw_r,           op_b,      qkv, kvs, ksum, cat2, att0, 1);
    run_attention(z1, qkvw_r + DD * D3,  opw_r + D2 * DD, op_b + DD, qkv, kvs, ksum, cat2, att1, 0);
    launch_stream(h,    pww_r,           pw_b,      p0, TN, DD, DD, 0, false, false);
    launch_stream(att0, pww_r + DD * DD, pw_b + DD, p1, TN, DD, DD, 0, false, false);
    combine_ln_kernel<<<TN, 128>>>(h, att0, att1, p0, p1, ln1_g, ln1_b, h1);
    launch_stream(h1, fc1_r, fc_b1, cat2, TN, DD, D2, 1, true, false);
    launch_stream(cat2, fc2_r, fc_b2, t2, TN, D2, DD, 0, false, false);
    ln_res_kernel<<<TN, 128>>>(h1, t2, ln2_g, ln2_b, h2);
    transpose_h2_kernel<<<((long)TN * DD + 255) / 256, 256>>>(h2, h2t);
    GEMM(false,false,false,true, 2, 4, SPLITK,
         h2t, epw_r, nullptr, part, NPTS, TD, DD, 0,0,0, 0);
    splitk_reduce_kernel<<<(NPTS * DD + 255) / 256, 256>>>(part, ep_b, y, NPTS * DD, SPLITK, DD);
    for (int i = 0; i < 3; i++) {
        launch_stream(y,  enc1_r + (long)i * DD * D2, enc_b1 + (long)i * D2, yh,
                      NPTS, DD, D2, 1, true, false);
        launch_stream(yh, enc2_r + (long)i * D2 * DD, enc_b2 + (long)i * DD, y,
                      NPTS, D2, DD, 1, false, true);
    }
    launch_stream(y, outw_r, out_b, out, NPTS, DD, TT, 0, false, false);
}

// round 8
// speedup vs baseline: 2.1438x; 1.1063x over previous
#include <cuda_runtime.h>
#include <cuda_fp16.h>
#include <math.h>

#define TT   365
#define NPTS 400
#define DD   104
#define HH   4
#define HD   26
#define TN   (TT*NPTS)      // 146000
#define D2   (2*DD)         // 208
#define D3   (3*DD)         // 312
#define TD   (TT*DD)        // 37960
#define SPLITK 40
#define KCHUNK 960
#define SMA  40              // A/B smem row stride in halves (32 k + 8 pad)
#define A_STH (128*SMA)      // 5120 halves per A stage
#define B_STH (64*SMA)       // 2560 halves per B stage (batched)
#define SMEM_BATCH ((3*A_STH + 3*B_STH)*2)   // 46080 B
#define SMEM_STREAM_MAX 61440

// ---------------- scratch (device globals; no runtime allocation) -------------
__device__ __align__(16) __half g_hcat[(size_t)TN*DD];
__device__ __align__(16) __half g_h   [(size_t)TN*DD];
__device__ __align__(16) __half g_hT  [(size_t)TN*DD];   // [T][D][N]
__device__ __align__(16) __half g_graph[(size_t)TT*NPTS*NPTS];
__device__ __align__(16) __half g_z1  [(size_t)TN*DD];
__device__ __align__(16) __half g_qkv [(size_t)TN*D3];
__device__ float g_kvs [(size_t)NPTS*HH*HD*HD];
__device__ float g_ksum[(size_t)NPTS*HH*HD];
__device__ __align__(16) __half g_cat2[(size_t)TN*D2];
__device__ __align__(16) __half g_att0[(size_t)TN*DD];
__device__ float  g_att1[(size_t)TN*DD];
__device__ float  g_p0  [(size_t)TN*DD];
__device__ float  g_p1  [(size_t)TN*DD];
__device__ __align__(16) __half g_h1  [(size_t)TN*DD];
__device__ float  g_t2  [(size_t)TN*DD];
__device__ __align__(16) __half g_h2  [(size_t)TN*DD];
__device__ __align__(16) __half g_h2t [(size_t)NPTS*TD];
__device__ float  g_part[(size_t)SPLITK*NPTS*DD];
__device__ __align__(16) __half g_y   [(size_t)NPTS*DD];
__device__ __align__(16) __half g_yh  [(size_t)NPTS*D2];
__device__ __align__(16) __half g_wtsh[(size_t)16000000];   // fp16 transposed-weight arena

// offsets into g_wtsh (halves)
#define O_ADP   0L
#define O_WTP   11680000L
#define O_QKVW  11690816L
#define O_OPW   11755712L
#define O_PWW   11798976L
#define O_FC1   11820608L
#define O_FC2   11842240L
#define O_EPW   11863872L
#define O_ENC1  15811712L
#define O_ENC2  15876608L
#define O_OUTW  15941504L

// ---------------- cp.async issue helpers (fp16, 16B = 8 halves) -----------------
__device__ __forceinline__ void issue_a(const __half* __restrict__ A, unsigned sAs,
                                        int bm, int k0, int kend, int M, long K, int tid)
{
    #pragma unroll
    for (int p = 0; p < 2; p++) {
        int idx = tid + p * 256;
        int m = idx >> 2, kq = (idx & 3) << 3;
        int gm = bm + m;
        int rem = kend - (k0 + kq);
        int sz = (gm < M && rem >= 8) ? 16 : 0;
        const __half* src = sz ? A + (long)gm * K + k0 + kq : A;
        unsigned dst = sAs + (unsigned)(m * SMA + kq) * 2u;
        asm volatile("cp.async.ca.shared.global [%0],[%1],16,%2;"
                     :: "r"(dst), "l"(src), "r"(sz));
    }
}

// B rows are [n][k] (transposed weights / hT) — always k-contiguous.
__device__ __forceinline__ void issue_b(const __half* __restrict__ B, unsigned sBs,
                                        int bn, int k0, int kend, int Nc, long K, int tid)
{
    int n = tid >> 2, kq = (tid & 3) << 3;
    int gn = bn + n;
    int rem = kend - (k0 + kq);
    int sz = (gn < Nc && rem >= 8) ? 16 : 0;
    const __half* src = sz ? B + (long)gn * K + k0 + kq : B;
    unsigned dst = sBs + (unsigned)(n * SMA + kq) * 2u;
    asm volatile("cp.async.ca.shared.global [%0],[%1],16,%2;"
                 :: "r"(dst), "l"(src), "r"(sz));
}

// ---------------- fp16 MMA on a k32 chunk ---------------------------------------
__device__ __forceinline__ void mma_chunk(const __half* __restrict__ As, int sbA,
                                          const __half* __restrict__ Bs, int sbB,
                                          int wm, int wn, int lane, float (*acc)[4][4])
{
    int r = lane >> 2, c2 = (lane & 3) << 1;
    #pragma unroll
    for (int ks = 0; ks < 2; ks++) {
        int k0 = ks * 16;
        unsigned a[2][4], b[4][2];
        #pragma unroll
        for (int mt = 0; mt < 2; mt++) {
            const __half* p = As + (wm * 32 + mt * 16 + r) * sbA + k0 + c2;
            a[mt][0] = *reinterpret_cast<const unsigned*>(p);
            a[mt][1] = *reinterpret_cast<const unsigned*>(p + 8 * sbA);
            a[mt][2] = *reinterpret_cast<const unsigned*>(p + 8);
            a[mt][3] = *reinterpret_cast<const unsigned*>(p + 8 * sbA + 8);
        }
        #pragma unroll
        for (int nt = 0; nt < 4; nt++) {
            const __half* q = Bs + (wn * 32 + nt * 8 + r) * sbB + k0 + c2;
            b[nt][0] = *reinterpret_cast<const unsigned*>(q);
            b[nt][1] = *reinterpret_cast<const unsigned*>(q + 8);
        }
        #pragma unroll
        for (int mt = 0; mt < 2; mt++)
            #pragma unroll
            for (int nt = 0; nt < 4; nt++)
                asm("mma.sync.aligned.m16n8k16.row.col.f32.f16.f16.f32 "
                    "{%0,%1,%2,%3},{%4,%5,%6,%7},{%8,%9},{%0,%1,%2,%3};"
                    : "+f"(acc[mt][nt][0]), "+f"(acc[mt][nt][1]),
                      "+f"(acc[mt][nt][2]), "+f"(acc[mt][nt][3])
                    : "r"(a[mt][0]), "r"(a[mt][1]), "r"(a[mt][2]), "r"(a[mt][3]),
                      "r"(b[nt][0]), "r"(b[nt][1]));
    }
}

// ---------------- epilogue -------------------------------------------------------
template<bool RELU, bool ACC, bool SPLIT, typename TC>
__device__ __forceinline__ void epilogue(float (*acc)[4][4], const float* bias,
                                         TC* __restrict__ C, int bm, int bn,
                                         int M, int Nc, int wm, int wn, int lane)
{
    int r = lane >> 2, c2 = (lane & 3) << 1;
    #pragma unroll
    for (int mt = 0; mt < 2; mt++) {
        #pragma unroll
        for (int nt = 0; nt < 4; nt++) {
            int gm0 = bm + wm * 32 + mt * 16 + r;
            int gn0 = bn + wn * 32 + nt * 8 + c2;
            #pragma unroll
            for (int hh = 0; hh < 2; hh++) {
                int gm = gm0 + hh * 8;
                if (gm >= M) continue;
                #pragma unroll
                for (int j = 0; j < 2; j++) {
                    int gn = gn0 + j;
                    if (gn >= Nc) continue;
                    float v = acc[mt][nt][hh * 2 + j];
                    if (!SPLIT && bias) v += bias[gn];
                    if (RELU) v = fmaxf(v, 0.f);
                    long ci = (long)gm * Nc + gn;
                    if (ACC) v += (float)C[ci];
                    C[ci] = (TC)v;
                }
            }
        }
    }
}

// ---------------- batched / split fp16 GEMM (B always [n][k]) -------------------
template<bool SPLIT, typename TC>
__global__ void __launch_bounds__(256)
gemm_kernel(const __half* __restrict__ A, const __half* __restrict__ B,
            const float* __restrict__ bias, TC* __restrict__ C,
            int M, int K, int Nc, long sA, long sB_, long sC)
{
    extern __shared__ __half dsmh[];
    int tid = threadIdx.x;
    int bm = blockIdx.y * 128, bn = blockIdx.x * 64;
    int kbeg = 0, kend = K;
    if (SPLIT) {
        int z = blockIdx.z;
        kbeg = z * KCHUNK;
        kend = min(K, kbeg + KCHUNK);
        C += (long)z * M * Nc;
    } else {
        int z = blockIdx.z;
        A += z * sA; B += z * sB_; C += z * sC;
    }
    int w = tid >> 5, lane = tid & 31;
    int wm = w >> 1, wn = w & 1;
    float acc[2][4][4];
    #pragma unroll
    for (int mt = 0; mt < 2; mt++)
        #pragma unroll
        for (int nt = 0; nt < 4; nt++)
            #pragma unroll
            for (int q = 0; q < 4; q++) acc[mt][nt][q] = 0.f;

    unsigned sbase = (unsigned)__cvta_generic_to_shared(dsmh);
    unsigned sA0 = sbase;
    unsigned sB0 = sbase + 3u * A_STH * 2u;

    int nk = (kend - kbeg + 31) >> 5;
    issue_a(A, sA0, bm, kbeg, kend, M, K, tid);
    issue_b(B, sB0, bn, kbeg, kend, Nc, K, tid);
    asm volatile("cp.async.commit_group;" ::: "memory");
    issue_a(A, sA0 + A_STH * 2u, bm, kbeg + 32, kend, M, K, tid);
    issue_b(B, sB0 + B_STH * 2u, bn, kbeg + 32, kend, Nc, K, tid);
    asm volatile("cp.async.commit_group;" ::: "memory");

    for (int it = 0; it < nk; it++) {
        asm volatile("cp.async.wait_group 1;" ::: "memory");
        __syncthreads();
        int s2 = (it + 2) % 3;
        int kn = kbeg + (it + 2) * 32;
        issue_a(A, sA0 + (unsigned)s2 * A_STH * 2u, bm, kn, kend, M, K, tid);
        issue_b(B, sB0 + (unsigned)s2 * B_STH * 2u, bn, kn, kend, Nc, K, tid);
        asm volatile("cp.async.commit_group;" ::: "memory");
        int sc = it % 3;
        mma_chunk(dsmh + sc * A_STH, SMA, dsmh + 3 * A_STH + sc * B_STH, SMA,
                  wm, wn, lane, acc);
    }
    epilogue<false, false, SPLIT, TC>(acc, bias, C, bm, bn, M, Nc, wm, wn, lane);
}

// ---------------- persistent-B streaming GEMM (NN, non-batched) -----------------
template<bool RELU, bool ACC, typename TC>
__global__ void __launch_bounds__(256)
gemm_stream(const __half* __restrict__ A, const __half* __restrict__ Bt,
            const float* __restrict__ bias, TC* __restrict__ C,
            int M, int K, int Nc, int KP)
{
    extern __shared__ __half dsmh[];
    __half* Asm = dsmh;
    __half* Bsm = dsmh + 3 * A_STH;
    int tid = threadIdx.x;
    int bn = blockIdx.x * 64;
    int nkc = (K + 31) >> 5;
    int KP32 = nkc * 32;
    int MT = (M + 127) >> 7;
    int w = tid >> 5, lane = tid & 31;
    int wm = w >> 1, wn = w & 1;

    unsigned sbase = (unsigned)__cvta_generic_to_shared(dsmh);
    unsigned sA0 = sbase;
    unsigned sB0 = sbase + 3u * A_STH * 2u;

    // one-time B load: Bsm[n][k] (zero-filled OOB)
    int nchunk = KP32 >> 3;
    for (int e = tid; e < 64 * nchunk; e += 256) {
        int n = e / nchunk, kc8 = e - n * nchunk;
        int k = kc8 << 3;
        int gn = bn + n;
        int sz = (gn < Nc && k < K) ? 16 : 0;
        const __half* src = sz ? Bt + (long)gn * K + k : Bt;
        unsigned dst = sB0 + (unsigned)(n * KP + k) * 2u;
        asm volatile("cp.async.ca.shared.global [%0],[%1],16,%2;"
                     :: "r"(dst), "l"(src), "r"(sz));
    }

    int mt_i = blockIdx.y;
    int kc_i = 0;
    if (mt_i < MT) issue_a(A, sA0, mt_i * 128, 0, K, M, K, tid);
    asm volatile("cp.async.commit_group;" ::: "memory");
    if (++kc_i == nkc) { kc_i = 0; mt_i += gridDim.y; }
    if (mt_i < MT) issue_a(A, sA0 + A_STH * 2u, mt_i * 128, kc_i * 32, K, M, K, tid);
    asm volatile("cp.async.commit_group;" ::: "memory");
    if (++kc_i == nkc) { kc_i = 0; mt_i += gridDim.y; }

    float acc[2][4][4];
    int stage = 0;
    for (int mt = blockIdx.y; mt < MT; mt += gridDim.y) {
        #pragma unroll
        for (int mtt = 0; mtt < 2; mtt++)
            #pragma unroll
            for (int nt = 0; nt < 4; nt++)
                #pragma unroll
                for (int q = 0; q < 4; q++) acc[mtt][nt][q] = 0.f;
        for (int kc = 0; kc < nkc; kc++) {
            asm volatile("cp.async.wait_group 1;" ::: "memory");
            __syncthreads();
            int s2 = (stage + 2) % 3;
            if (mt_i < MT) issue_a(A, sA0 + (unsigned)s2 * A_STH * 2u,
                                   mt_i * 128, kc_i * 32, K, M, K, tid);
            asm volatile("cp.async.commit_group;" ::: "memory");
            if (++kc_i == nkc) { kc_i = 0; mt_i += gridDim.y; }
            mma_chunk(Asm + stage * A_STH, SMA, Bsm + kc * 32, KP, wm, wn, lane, acc);
            stage = (stage + 1) % 3;
        }
        epilogue<RELU, ACC, false, TC>(acc, bias, C, mt * 128, bn, M, Nc, wm, wn, lane);
    }
}

// ---------------- fused relu-softmax normalize (fp16 in/out) --------------------
__global__ void normgraph_kernel(__half* __restrict__ g)
{
    long row = (long)blockIdx.x * 8 + (threadIdx.x >> 5);
    if (row >= (long)TN) return;
    int lane = threadIdx.x & 31;
    uint4* p = reinterpret_cast<uint4*>(g + row * NPTS);  // 50 chunks of 8 halves
    float v[2][8]; uint4 u;
    float m = 0.f;
    #pragma unroll
    for (int rch = 0; rch < 2; rch++) {
        int c = lane + rch * 32;
        if (c < 50) {
            u = p[c];
            const __half2* hp = reinterpret_cast<const __half2*>(&u);
            #pragma unroll
            for (int j = 0; j < 4; j++) {
                float2 f = __half22float2(hp[j]);
                v[rch][2 * j] = f.x; v[rch][2 * j + 1] = f.y;
                m = fmaxf(m, fmaxf(f.x, f.y));
            }
        }
    }
    #pragma unroll
    for (int o = 16; o > 0; o >>= 1) m = fmaxf(m, __shfl_xor_sync(~0u, m, o));
    float s = 0.f;
    #pragma unroll
    for (int rch = 0; rch < 2; rch++) {
        int c = lane + rch * 32;
        if (c < 50) {
            #pragma unroll
            for (int j = 0; j < 8; j++) {
                float e = __expf(fmaxf(v[rch][j], 0.f) - m);
                v[rch][j] = e; s += e;
            }
        }
    }
    #pragma unroll
    for (int o = 16; o > 0; o >>= 1) s += __shfl_xor_sync(~0u, s, o);
    float inv = 1.f / s;
    #pragma unroll
    for (int rch = 0; rch < 2; rch++) {
        int c = lane + rch * 32;
        if (c < 50) {
            uint4 ou;
            __half2* hp = reinterpret_cast<__half2*>(&ou);
            #pragma unroll
            for (int j = 0; j < 4; j++)
                hp[j] = __floats2half2_rn(v[rch][2 * j] * inv, v[rch][2 * j + 1] * inv);
            p[c] = ou;
        }
    }
}

// ---------------- weight conversion kernels -------------------------------------
__global__ void rnd2h_kernel(const float* __restrict__ src, __half* __restrict__ dst, long n2)
{
    long i = (long)blockIdx.x * 256 + threadIdx.x;
    if (i >= n2) return;
    float2 f = reinterpret_cast<const float2*>(src)[i];
    reinterpret_cast<__half2*>(dst)[i] = __floats2half2_rn(f.x, f.y);
}

// dst[n][k] = (half)src[k][n]
__global__ void trnd_kernel(const float* __restrict__ src, __half* __restrict__ dst,
                            int K, int Nc)
{
    long j = (long)blockIdx.x * 256 + threadIdx.x;
    if (j >= (long)K * Nc) return;
    int n = (int)(j / K); long k = j - (long)n * K;
    dst[j] = __float2half_rn(src[k * Nc + n]);
}

// ---------------- input proj + concat adaptive embedding ------------------------
__global__ void hcat_kernel(const float* __restrict__ x, const float* __restrict__ W_in,
                            const float* __restrict__ b_in, const __half* __restrict__ adp_h,
                            __half* __restrict__ hcat)
{
    long idx = (long)blockIdx.x * 256 + threadIdx.x;
    if (idx >= (long)TN * DD) return;
    long tn = idx / DD; int j = (int)(idx - tn * DD);
    int t = (int)(tn / NPTS), n = (int)(tn - (long)t * NPTS);
    __half v;
    if (j < 24) {
        const float* xr = x + ((long)n * TT + t) * 3;
        v = __float2half_rn(b_in[j] + xr[0] * W_in[0 * 24 + j]
                            + xr[1] * W_in[1 * 24 + j] + xr[2] * W_in[2 * 24 + j]);
    } else {
        v = adp_h[tn * 80 + (j - 24)];
    }
    hcat[idx] = v;
}

// ---------------- h -> hT [T][D][N] ----------------------------------------------
__global__ void transpose_hT_kernel(const __half* __restrict__ h, __half* __restrict__ hT)
{
    long idx = (long)blockIdx.x * 256 + threadIdx.x;
    if (idx >= (long)TN * DD) return;
    long t = idx / ((long)NPTS * DD);
    long r = idx - t * ((long)NPTS * DD);
    long n = r / DD;
    long d = r - n * DD;
    hT[t * (long)DD * NPTS + d * NPTS + n] = h[idx];
}

// ---------------- linear attention: kvs + ksum ----------------------------------
__global__ void kvs_kernel(const __half* __restrict__ qkv, long sB, long sL, int L,
                           float* __restrict__ kvs, float* __restrict__ ksum)
{
    int b = blockIdx.x, h = blockIdx.y;
    int w = threadIdx.x >> 5, lane = threadIdx.x & 31;
    int chunk = (L + 7) >> 3;
    int l0 = w * chunk, l1 = min(L, l0 + chunk);
    const __half* base = qkv + (long)b * sB + h * HD;
    float acc[HD];
    #pragma unroll
    for (int m = 0; m < HD; m++) acc[m] = 0.f;
    float accs = 0.f;
    for (int l = l0; l < l1; l++) {
        const __half* row = base + (long)l * sL;
        float kk = (lane < HD) ? __half2float(row[DD + lane]) : 0.f;
        float vv = (lane < HD) ? __half2float(row[2 * DD + lane]) : 0.f;
        float ss = kk * kk;
        #pragma unroll
        for (int o = 16; o > 0; o >>= 1) ss += __shfl_xor_sync(~0u, ss, o);
        float inv = 1.f / fmaxf(sqrtf(ss), 1e-12f);
        float kin = kk * inv;
        accs += kin;
        #pragma unroll
        for (int m = 0; m < HD; m++) {
            float km = __shfl_sync(~0u, kin, m);
            acc[m] += km * vv;
        }
    }
    __shared__ float red[8][HD][HD + 2];
    __shared__ float redk[8][32];
    if (lane < HD) {
        #pragma unroll
        for (int m = 0; m < HD; m++) red[w][m][lane] = acc[m];
    }
    redk[w][lane] = accs;
    __syncthreads();
    long basec = ((long)b * HH + h);
    for (int cell = threadIdx.x; cell < HD * HD; cell += 256) {
        int m = cell / HD, d = cell - m * HD;
        float s = 0.f;
        #pragma unroll
        for (int ww = 0; ww < 8; ww++) s += red[ww][m][d];
        kvs[basec * (HD * HD) + cell] = s;
    }
    if (threadIdx.x < HD) {
        float s = 0.f;
        #pragma unroll
        for (int ww = 0; ww < 8; ww++) s += redk[ww][threadIdx.x];
        ksum[basec * HD + threadIdx.x] = s;
    }
}

// ---------------- linear attention: per-token output ----------------------------
__global__ void attnout_kernel(const __half* __restrict__ qkv, long sB, long sL, int L,
                               const float* __restrict__ kvs, const float* __restrict__ ksum,
                               __half* __restrict__ outb, long oB, long oL, int ooff)
{
    int l = blockIdx.x, b = blockIdx.y;
    int tid = threadIdx.x;
    const __half* row = qkv + (long)b * sB + (long)l * sL;
    __shared__ float sq[DD], sv[DD], sinv[HH], sden[HH];
    if (tid < DD) {
        sq[tid] = __half2float(row[tid]);
        sv[tid] = __half2float(row[2 * DD + tid]);
    }
    __syncthreads();
    if (tid < HH) {
        const float* qh = sq + tid * HD;
        float ss = 0.f;
        #pragma unroll
        for (int m = 0; m < HD; m++) ss += qh[m] * qh[m];
        float inv = 1.f / fmaxf(sqrtf(ss), 1e-12f);
        sinv[tid] = inv;
        const float* ks = ksum + ((long)b * HH + tid) * HD;
        float dd = 0.f;
        #pragma unroll
        for (int m = 0; m < HD; m++) dd += qh[m] * ks[m];
        sden[tid] = dd * inv + (float)L;
    }
    __syncthreads();
    if (tid < DD) {
        int h = tid / HD, d = tid - h * HD;
        const float* kv = kvs + ((long)b * HH + h) * (HD * HD) + d;
        const float* qh = sq + h * HD;
        float s = 0.f;
        #pragma unroll
        for (int m = 0; m < HD; m++) s += qh[m] * kv[m * HD];
        float num = s * sinv[h] + (float)L * sv[tid];
        outb[((long)b * oB + (long)l * oL) * D2 + ooff + tid] = __float2half_rn(num / sden[h]);
    }
}

// ---------------- fused combine + LayerNorm --------------------------------------
__global__ void combine_ln_kernel(const __half* __restrict__ h, const __half* __restrict__ a0,
                                  const float* __restrict__ a1, const float* __restrict__ p0,
                                  const float* __restrict__ p1, const float* __restrict__ gam,
                                  const float* __restrict__ bet, __half* __restrict__ out)
{
    long row = blockIdx.x; int tid = threadIdx.x;  // 128
    __shared__ float red[4];
    long i = row * DD + tid;
    float v = 0.f;
    if (tid < DD)
        v = 2.f * (__half2float(h[i]) + __half2float(a0[i]) * p0[i] + 0.01f * a1[i] * p1[i]);
    float s = (tid < DD) ? v : 0.f;
    #pragma unroll
    for (int o = 16; o > 0; o >>= 1) s += __shfl_xor_sync(~0u, s, o);
    if ((tid & 31) == 0) red[tid >> 5] = s;
    __syncthreads();
    float mean = (red[0] + red[1] + red[2] + red[3]) / (float)DD;
    __syncthreads();
    float d = (tid < DD) ? (v - mean) : 0.f;
    float s2 = d * d;
    #pragma unroll
    for (int o = 16; o > 0; o >>= 1) s2 += __shfl_xor_sync(~0u, s2, o);
    if ((tid & 31) == 0) red[tid >> 5] = s2;
    __syncthreads();
    float var = (red[0] + red[1] + red[2] + red[3]) / (float)DD;
    if (tid < DD) out[i] = __float2half_rn(d * rsqrtf(var + 1e-5f) * gam[tid] + bet[tid]);
}

__global__ void ln_res_kernel(const __half* __restrict__ a, const float* __restrict__ b,
                              const float* __restrict__ gam, const float* __restrict__ bet,
                              __half* __restrict__ out)
{
    long row = blockIdx.x; int tid = threadIdx.x;  // 128
    __shared__ float red[4];
    long i = row * DD + tid;
    float v = 0.f;
    if (tid < DD) v = __half2float(a[i]) + b[i];
    float s = (tid < DD) ? v : 0.f;
    #pragma unroll
    for (int o = 16; o > 0; o >>= 1) s += __shfl_xor_sync(~0u, s, o);
    if ((tid & 31) == 0) red[tid >> 5] = s;
    __syncthreads();
    float mean = (red[0] + red[1] + red[2] + red[3]) / (float)DD;
    __syncthreads();
    float d = (tid < DD) ? (v - mean) : 0.f;
    float s2 = d * d;
    #pragma unroll
    for (int o = 16; o > 0; o >>= 1) s2 += __shfl_xor_sync(~0u, s2, o);
    if ((tid & 31) == 0) red[tid >> 5] = s2;
    __syncthreads();
    float var = (red[0] + red[1] + red[2] + red[3]) / (float)DD;
    if (tid < DD) out[i] = __float2half_rn(d * rsqrtf(var + 1e-5f) * gam[tid] + bet[tid]);
}

// ---------------- [T,N,D] -> [N, T*D] transpose ---------------------------------
__global__ void transpose_h2_kernel(const __half* __restrict__ h2, __half* __restrict__ h2t)
{
    long idx = (long)blockIdx.x * 256 + threadIdx.x;
    if (idx >= (long)TN * DD) return;
    long t = idx / ((long)NPTS * DD);
    long r = idx - t * ((long)NPTS * DD);
    long n = r / DD;
    long d = r - n * DD;
    h2t[n * (long)TD + t * DD + d] = h2[idx];
}

// ---------------- split-K deterministic reduction -------------------------------
__global__ void splitk_reduce_kernel(const float* __restrict__ part, const float* __restrict__ bias,
                                     __half* __restrict__ y, int MN, int Z, int Nc)
{
    int i = blockIdx.x * 256 + threadIdx.x;
    if (i >= MN) return;
    float s = bias[i % Nc];
    for (int z = 0; z < Z; z++) s += part[(long)z * MN + i];
    y[i] = __float2half_rn(s);
}

// ---------------- streaming GEMM launcher ---------------------------------------
template<bool RELU, bool ACC, typename TC>
static void launch_stream_t(const __half* A, const __half* Bt, const float* bias, TC* C,
                            int M, int K, int Nc)
{
    int nkc = (K + 31) / 32;
    int KP = nkc * 32 + 8;
    int smem = 3 * A_STH * 2 + 64 * KP * 2;
    int nx = (Nc + 63) / 64;
    int MT = (M + 127) / 128;
    int gy = (444 + nx - 1) / nx;
    if (gy > MT) gy = MT;
    gemm_stream<RELU, ACC, TC><<<dim3(nx, gy), 256, smem>>>(A, Bt, bias, C, M, K, Nc, KP);
}

// ---------------- host orchestration --------------------------------------------
static void run_attention(const __half* x4, const __half* qwT, const __half* owT,
                          const float* ob, __half* qkv, float* kvs, float* ksum,
                          __half* cat2, __half* att_h, float* att_f)
{
    launch_stream_t<false, false, __half>(x4, qwT, nullptr, qkv, TN, DD, D3);
    kvs_kernel<<<dim3(TT, HH), 256>>>(qkv, (long)NPTS * D3, (long)D3, NPTS, kvs, ksum);
    attnout_kernel<<<dim3(NPTS, TT), 128>>>(qkv, (long)NPTS * D3, (long)D3, NPTS, kvs, ksum,
                                            cat2, (long)NPTS, 1, 0);
    kvs_kernel<<<dim3(NPTS, HH), 256>>>(qkv, (long)D3, (long)NPTS * D3, TT, kvs, ksum);
    attnout_kernel<<<dim3(TT, NPTS), 128>>>(qkv, (long)D3, (long)NPTS * D3, TT, kvs, ksum,
                                            cat2, 1, (long)NPTS, DD);
    if (att_h) launch_stream_t<false, false, __half>(cat2, owT, ob, att_h, TN, D2, DD);
    else       launch_stream_t<false, false, float >(cat2, owT, ob, att_f, TN, D2, DD);
}

extern "C" void kernel_launch(void* const* d_in, const int* in_sizes, int n_in,
                              void* d_out, int out_size)
{
    (void)in_sizes; (void)n_in; (void)out_size;
    const float* x     = (const float*)d_in[0];
    const float* W_in  = (const float*)d_in[1];
    const float* b_in  = (const float*)d_in[2];
    const float* adp   = (const float*)d_in[3];
    const float* W_tp  = (const float*)d_in[4];
    const float* b_tp  = (const float*)d_in[5];
    const float* qkv_w = (const float*)d_in[6];
    const float* op_w  = (const float*)d_in[7];
    const float* op_b  = (const float*)d_in[8];
    const float* pw_w  = (const float*)d_in[9];
    const float* pw_b  = (const float*)d_in[10];
    const float* fc_w1 = (const float*)d_in[11];
    const float* fc_b1 = (const float*)d_in[12];
    const float* fc_w2 = (const float*)d_in[13];
    const float* fc_b2 = (const float*)d_in[14];
    const float* ln1_g = (const float*)d_in[15];
    const float* ln1_b = (const float*)d_in[16];
    const float* ln2_g = (const float*)d_in[17];
    const float* ln2_b = (const float*)d_in[18];
    const float* ep_w  = (const float*)d_in[19];
    const float* ep_b  = (const float*)d_in[20];
    const float* enc_w1= (const float*)d_in[21];
    const float* enc_b1= (const float*)d_in[22];
    const float* enc_w2= (const float*)d_in[23];
    const float* enc_b2= (const float*)d_in[24];
    const float* out_w = (const float*)d_in[25];
    const float* out_b = (const float*)d_in[26];
    float* out = (float*)d_out;

    static int attr_done = 0;
    if (!attr_done) {
        cudaFuncSetAttribute(gemm_kernel<false, __half>,
                             cudaFuncAttributeMaxDynamicSharedMemorySize, SMEM_BATCH);
        cudaFuncSetAttribute(gemm_kernel<true, float>,
                             cudaFuncAttributeMaxDynamicSharedMemorySize, SMEM_BATCH);
        cudaFuncSetAttribute(gemm_stream<false, false, __half>,
                             cudaFuncAttributeMaxDynamicSharedMemorySize, SMEM_STREAM_MAX);
        cudaFuncSetAttribute(gemm_stream<true, false, __half>,
                             cudaFuncAttributeMaxDynamicSharedMemorySize, SMEM_STREAM_MAX);
        cudaFuncSetAttribute(gemm_stream<false, true, __half>,
                             cudaFuncAttributeMaxDynamicSharedMemorySize, SMEM_STREAM_MAX);
        cudaFuncSetAttribute(gemm_stream<false, false, float>,
                             cudaFuncAttributeMaxDynamicSharedMemorySize, SMEM_STREAM_MAX);
        attr_done = 1;
    }

    __half *hcat, *h, *hT, *graph, *z1, *qkv, *cat2, *att0, *h1, *h2, *h2t, *y, *yh, *wtsh;
    float *kvs, *ksum, *att1, *p0, *p1, *t2, *part;
    cudaGetSymbolAddress((void**)&hcat, g_hcat);
    cudaGetSymbolAddress((void**)&h,    g_h);
    cudaGetSymbolAddress((void**)&hT,   g_hT);
    cudaGetSymbolAddress((void**)&graph,g_graph);
    cudaGetSymbolAddress((void**)&z1,   g_z1);
    cudaGetSymbolAddress((void**)&qkv,  g_qkv);
    cudaGetSymbolAddress((void**)&kvs,  g_kvs);
    cudaGetSymbolAddress((void**)&ksum, g_ksum);
    cudaGetSymbolAddress((void**)&cat2, g_cat2);
    cudaGetSymbolAddress((void**)&att0, g_att0);
    cudaGetSymbolAddress((void**)&att1, g_att1);
    cudaGetSymbolAddress((void**)&p0,   g_p0);
    cudaGetSymbolAddress((void**)&p1,   g_p1);
    cudaGetSymbolAddress((void**)&h1,   g_h1);
    cudaGetSymbolAddress((void**)&t2,   g_t2);
    cudaGetSymbolAddress((void**)&h2,   g_h2);
    cudaGetSymbolAddress((void**)&h2t,  g_h2t);
    cudaGetSymbolAddress((void**)&part, g_part);
    cudaGetSymbolAddress((void**)&y,    g_y);
    cudaGetSymbolAddress((void**)&yh,   g_yh);
    cudaGetSymbolAddress((void**)&wtsh, g_wtsh);

    __half* adp_h  = wtsh + O_ADP;
    __half* WtpT   = wtsh + O_WTP;
    __half* qkvwT  = wtsh + O_QKVW;
    __half* opwT   = wtsh + O_OPW;
    __half* pwwT   = wtsh + O_PWW;
    __half* fc1T   = wtsh + O_FC1;
    __half* fc2T   = wtsh + O_FC2;
    __half* epwT   = wtsh + O_EPW;
    __half* enc1T  = wtsh + O_ENC1;
    __half* enc2T  = wtsh + O_ENC2;
    __half* outwT  = wtsh + O_OUTW;

    // ---- weight conversion: adp plain; all GEMM weights transposed [n][k] ----
    {
        long n2 = (long)TT * NPTS * 80 / 2;
        rnd2h_kernel<<<(n2 + 255) / 256, 256>>>(adp, adp_h, n2);
    }
    #define TRND(src, dst, K_, N_) \
        trnd_kernel<<<(((long)(K_) * (N_)) + 255) / 256, 256>>>(src, dst, K_, N_)
    TRND(W_tp, WtpT, DD, DD);
    TRND(qkv_w,            qkvwT,             DD, D3);
    TRND(qkv_w + DD * D3,  qkvwT + D3 * DD,   DD, D3);
    TRND(op_w,             opwT,              D2, DD);
    TRND(op_w + D2 * DD,   opwT + DD * D2,    D2, DD);
    TRND(pw_w,             pwwT,              DD, DD);
    TRND(pw_w + DD * DD,   pwwT + DD * DD,    DD, DD);
    TRND(fc_w1, fc1T, DD, D2);
    TRND(fc_w2, fc2T, D2, DD);
    TRND(ep_w,  epwT, TD, DD);
    for (int i = 0; i < 3; i++) {
        TRND(enc_w1 + (long)i * DD * D2, enc1T + (long)i * D2 * DD, DD, D2);
        TRND(enc_w2 + (long)i * D2 * DD, enc2T + (long)i * DD * D2, D2, DD);
    }
    TRND(out_w, outwT, DD, TT);

    // ---- forward ----
    hcat_kernel<<<((long)TN * DD + 255) / 256, 256>>>(x, W_in, b_in, adp_h, hcat);
    launch_stream_t<false, false, __half>(hcat, WtpT, b_tp, h, TN, DD, DD);
    // graph[t] = adp_t @ adp_t^T (B = adp rows, k-contiguous)
    gemm_kernel<false, __half><<<dim3(7, 4, TT), 256, SMEM_BATCH>>>(
        adp_h, adp_h, nullptr, graph, NPTS, 80, NPTS,
        (long)NPTS * 80, (long)NPTS * 80, (long)NPTS * NPTS);
    normgraph_kernel<<<(TN + 7) / 8, 256>>>(graph);
    // z1[t] = graph_t @ h_t  (B = hT_t rows [104][400])
    transpose_hT_kernel<<<((long)TN * DD + 255) / 256, 256>>>(h, hT);
    gemm_kernel<false, __half><<<dim3(2, 4, TT), 256, SMEM_BATCH>>>(
        graph, hT, nullptr, z1, NPTS, NPTS, DD,
        (long)NPTS * NPTS, (long)DD * NPTS, (long)NPTS * DD);
    run_attention(h,  qkvwT,           opwT,           op_b,      qkv, kvs, ksum, cat2, att0, nullptr);
    run_attention(z1, qkvwT + D3 * DD, opwT + DD * D2, op_b + DD, qkv, kvs, ksum, cat2, nullptr, att1);
    launch_stream_t<false, false, float>(h,    pwwT,           pw_b,      p0, TN, DD, DD);
    launch_stream_t<false, false, float>(att0, pwwT + DD * DD, pw_b + DD, p1, TN, DD, DD);
    combine_ln_kernel<<<TN, 128>>>(h, att0, att1, p0, p1, ln1_g, ln1_b, h1);
    launch_stream_t<true,  false, __half>(h1,   fc1T, fc_b1, cat2, TN, DD, D2);
    launch_stream_t<false, false, float >(cat2, fc2T, fc_b2, t2,   TN, D2, DD);
    ln_res_kernel<<<TN, 128>>>(h1, t2, ln2_g, ln2_b, h2);
    transpose_h2_kernel<<<((long)TN * DD + 255) / 256, 256>>>(h2, h2t);
    gemm_kernel<true, float><<<dim3(2, 4, SPLITK), 256, SMEM_BATCH>>>(
        h2t, epwT, nullptr, part, NPTS, TD, DD, 0, 0, 0);
    splitk_reduce_kernel<<<(NPTS * DD + 255) / 256, 256>>>(part, ep_b, y, NPTS * DD, SPLITK, DD);
    for (int i = 0; i < 3; i++) {
        launch_stream_t<true,  false, __half>(y,  enc1T + (long)i * D2 * DD,
                                              enc_b1 + (long)i * D2, yh, NPTS, DD, D2);
        launch_stream_t<false, true,  __half>(yh, enc2T + (long)i * DD * D2,
                                              enc_b2 + (long)i * DD, y,  NPTS, D2, DD);
    }
    launch_stream_t<false, false, float>(y, outwT, out_b, out, NPTS, DD, TT);
}

// round 9
// speedup vs baseline: 2.4010x; 1.1200x over previous
#include <cuda_runtime.h>
#include <cuda_fp16.h>
#include <math.h>

#define TT   365
#define NPTS 400
#define DD   104
#define HH   4
#define HD   26
#define TN   (TT*NPTS)      // 146000
#define D2   (2*DD)         // 208
#define D3   (3*DD)         // 312
#define TD   (TT*DD)        // 37960
#define SPLITK 40
#define KCHUNK 960
#define SMA  40              // A/B smem row stride in halves (32 k + 8 pad)
#define A_STH (128*SMA)
#define B_STH (64*SMA)
#define SMEM_BATCH ((3*A_STH + 3*B_STH)*2)
#define SMEM_STREAM_MAX 61440

// ---------------- scratch (device globals; no runtime allocation) -------------
__device__ __align__(16) __half g_hcat[(size_t)TN*DD];
__device__ __align__(16) __half g_h   [(size_t)TN*DD];
__device__ __align__(16) __half g_hT  [(size_t)TN*DD];   // [T][D][N]
__device__ __align__(16) __half g_graph[(size_t)TT*NPTS*NPTS];
__device__ __align__(16) __half g_z1  [(size_t)TN*DD];
__device__ __align__(16) __half g_qkv [(size_t)TN*D3];
__device__ float g_kvs_s [(size_t)TT*HH*HD*HD];
__device__ float g_ksum_s[(size_t)TT*HH*HD];
__device__ float g_kvs_t [(size_t)NPTS*HH*HD*HD];
__device__ float g_ksum_t[(size_t)NPTS*HH*HD];
__device__ __align__(16) __half g_cat2[(size_t)TN*D2];
__device__ __align__(16) __half g_att0[(size_t)TN*DD];
__device__ float  g_att1[(size_t)TN*DD];
__device__ float  g_p0  [(size_t)TN*DD];
__device__ float  g_p1  [(size_t)TN*DD];
__device__ __align__(16) __half g_h1  [(size_t)TN*DD];
__device__ float  g_t2  [(size_t)TN*DD];
__device__ __align__(16) __half g_h2t [(size_t)NPTS*TD];
__device__ float  g_part[(size_t)SPLITK*NPTS*DD];
__device__ __align__(16) __half g_y   [(size_t)NPTS*DD];
__device__ __align__(16) __half g_yh  [(size_t)NPTS*D2];
__device__ __align__(16) __half g_wtsh[(size_t)16000000];

// offsets into g_wtsh (halves)
#define O_ADP   0L
#define O_WTP   11680000L
#define O_QKVW  11690816L
#define O_OPW   11755712L
#define O_PWW   11798976L
#define O_FC1   11820608L
#define O_FC2   11842240L
#define O_EPW   11863872L
#define O_ENC1  15811712L
#define O_ENC2  15876608L
#define O_OUTW  15941504L

// ---------------- cp.async issue helpers ----------------------------------------
__device__ __forceinline__ void issue_a(const __half* __restrict__ A, unsigned sAs,
                                        int bm, int k0, int kend, int M, long K, int tid)
{
    #pragma unroll
    for (int p = 0; p < 2; p++) {
        int idx = tid + p * 256;
        int m = idx >> 2, kq = (idx & 3) << 3;
        int gm = bm + m;
        int rem = kend - (k0 + kq);
        int sz = (gm < M && rem >= 8) ? 16 : 0;
        const __half* src = sz ? A + (long)gm * K + k0 + kq : A;
        unsigned dst = sAs + (unsigned)(m * SMA + kq) * 2u;
        asm volatile("cp.async.ca.shared.global [%0],[%1],16,%2;"
                     :: "r"(dst), "l"(src), "r"(sz));
    }
}

__device__ __forceinline__ void issue_b(const __half* __restrict__ B, unsigned sBs,
                                        int bn, int k0, int kend, int Nc, long K, int tid)
{
    int n = tid >> 2, kq = (tid & 3) << 3;
    int gn = bn + n;
    int rem = kend - (k0 + kq);
    int sz = (gn < Nc && rem >= 8) ? 16 : 0;
    const __half* src = sz ? B + (long)gn * K + k0 + kq : B;
    unsigned dst = sBs + (unsigned)(n * SMA + kq) * 2u;
    asm volatile("cp.async.ca.shared.global [%0],[%1],16,%2;"
                 :: "r"(dst), "l"(src), "r"(sz));
}

// ---------------- fp16 MMA on a k32 chunk ---------------------------------------
__device__ __forceinline__ void mma_chunk(const __half* __restrict__ As, int sbA,
                                          const __half* __restrict__ Bs, int sbB,
                                          int wm, int wn, int lane, float (*acc)[4][4])
{
    int r = lane >> 2, c2 = (lane & 3) << 1;
    #pragma unroll
    for (int ks = 0; ks < 2; ks++) {
        int k0 = ks * 16;
        unsigned a[2][4], b[4][2];
        #pragma unroll
        for (int mt = 0; mt < 2; mt++) {
            const __half* p = As + (wm * 32 + mt * 16 + r) * sbA + k0 + c2;
            a[mt][0] = *reinterpret_cast<const unsigned*>(p);
            a[mt][1] = *reinterpret_cast<const unsigned*>(p + 8 * sbA);
            a[mt][2] = *reinterpret_cast<const unsigned*>(p + 8);
            a[mt][3] = *reinterpret_cast<const unsigned*>(p + 8 * sbA + 8);
        }
        #pragma unroll
        for (int nt = 0; nt < 4; nt++) {
            const __half* q = Bs + (wn * 32 + nt * 8 + r) * sbB + k0 + c2;
            b[nt][0] = *reinterpret_cast<const unsigned*>(q);
            b[nt][1] = *reinterpret_cast<const unsigned*>(q + 8);
        }
        #pragma unroll
        for (int mt = 0; mt < 2; mt++)
            #pragma unroll
            for (int nt = 0; nt < 4; nt++)
                asm("mma.sync.aligned.m16n8k16.row.col.f32.f16.f16.f32 "
                    "{%0,%1,%2,%3},{%4,%5,%6,%7},{%8,%9},{%0,%1,%2,%3};"
                    : "+f"(acc[mt][nt][0]), "+f"(acc[mt][nt][1]),
                      "+f"(acc[mt][nt][2]), "+f"(acc[mt][nt][3])
                    : "r"(a[mt][0]), "r"(a[mt][1]), "r"(a[mt][2]), "r"(a[mt][3]),
                      "r"(b[nt][0]), "r"(b[nt][1]));
    }
}

// ---------------- epilogue -------------------------------------------------------
template<bool RELU, bool ACC, bool SPLIT, typename TC>
__device__ __forceinline__ void epilogue(float (*acc)[4][4], const float* bias,
                                         TC* __restrict__ C, int bm, int bn,
                                         int M, int Nc, int wm, int wn, int lane)
{
    int r = lane >> 2, c2 = (lane & 3) << 1;
    #pragma unroll
    for (int mt = 0; mt < 2; mt++) {
        #pragma unroll
        for (int nt = 0; nt < 4; nt++) {
            int gm0 = bm + wm * 32 + mt * 16 + r;
            int gn0 = bn + wn * 32 + nt * 8 + c2;
            #pragma unroll
            for (int hh = 0; hh < 2; hh++) {
                int gm = gm0 + hh * 8;
                if (gm >= M) continue;
                #pragma unroll
                for (int j = 0; j < 2; j++) {
                    int gn = gn0 + j;
                    if (gn >= Nc) continue;
                    float v = acc[mt][nt][hh * 2 + j];
                    if (!SPLIT && bias) v += bias[gn];
                    if (RELU) v = fmaxf(v, 0.f);
                    long ci = (long)gm * Nc + gn;
                    if (ACC) v += (float)C[ci];
                    C[ci] = (TC)v;
                }
            }
        }
    }
}

// ---------------- batched / split fp16 GEMM (B always [n][k]) -------------------
template<bool SPLIT, typename TC>
__global__ void __launch_bounds__(256)
gemm_kernel(const __half* __restrict__ A, const __half* __restrict__ B,
            const float* __restrict__ bias, TC* __restrict__ C,
            int M, int K, int Nc, long sA, long sB_, long sC)
{
    extern __shared__ __half dsmh[];
    int tid = threadIdx.x;
    int bm = blockIdx.y * 128, bn = blockIdx.x * 64;
    int kbeg = 0, kend = K;
    if (SPLIT) {
        int z = blockIdx.z;
        kbeg = z * KCHUNK;
        kend = min(K, kbeg + KCHUNK);
        C += (long)z * M * Nc;
    } else {
        int z = blockIdx.z;
        A += z * sA; B += z * sB_; C += z * sC;
    }
    int w = tid >> 5, lane = tid & 31;
    int wm = w >> 1, wn = w & 1;
    float acc[2][4][4];
    #pragma unroll
    for (int mt = 0; mt < 2; mt++)
        #pragma unroll
        for (int nt = 0; nt < 4; nt++)
            #pragma unroll
            for (int q = 0; q < 4; q++) acc[mt][nt][q] = 0.f;

    unsigned sbase = (unsigned)__cvta_generic_to_shared(dsmh);
    unsigned sA0 = sbase;
    unsigned sB0 = sbase + 3u * A_STH * 2u;

    int nk = (kend - kbeg + 31) >> 5;
    issue_a(A, sA0, bm, kbeg, kend, M, K, tid);
    issue_b(B, sB0, bn, kbeg, kend, Nc, K, tid);
    asm volatile("cp.async.commit_group;" ::: "memory");
    issue_a(A, sA0 + A_STH * 2u, bm, kbeg + 32, kend, M, K, tid);
    issue_b(B, sB0 + B_STH * 2u, bn, kbeg + 32, kend, Nc, K, tid);
    asm volatile("cp.async.commit_group;" ::: "memory");

    for (int it = 0; it < nk; it++) {
        asm volatile("cp.async.wait_group 1;" ::: "memory");
        __syncthreads();
        int s2 = (it + 2) % 3;
        int kn = kbeg + (it + 2) * 32;
        issue_a(A, sA0 + (unsigned)s2 * A_STH * 2u, bm, kn, kend, M, K, tid);
        issue_b(B, sB0 + (unsigned)s2 * B_STH * 2u, bn, kn, kend, Nc, K, tid);
        asm volatile("cp.async.commit_group;" ::: "memory");
        int sc = it % 3;
        mma_chunk(dsmh + sc * A_STH, SMA, dsmh + 3 * A_STH + sc * B_STH, SMA,
                  wm, wn, lane, acc);
    }
    epilogue<false, false, SPLIT, TC>(acc, bias, C, bm, bn, M, Nc, wm, wn, lane);
}

// ---------------- persistent-B streaming GEMM (NN, non-batched) -----------------
template<bool RELU, bool ACC, typename TC>
__global__ void __launch_bounds__(256)
gemm_stream(const __half* __restrict__ A, const __half* __restrict__ Bt,
            const float* __restrict__ bias, TC* __restrict__ C,
            int M, int K, int Nc, int KP)
{
    extern __shared__ __half dsmh[];
    __half* Asm = dsmh;
    __half* Bsm = dsmh + 3 * A_STH;
    int tid = threadIdx.x;
    int bn = blockIdx.x * 64;
    int nkc = (K + 31) >> 5;
    int KP32 = nkc * 32;
    int MT = (M + 127) >> 7;
    int w = tid >> 5, lane = tid & 31;
    int wm = w >> 1, wn = w & 1;

    unsigned sbase = (unsigned)__cvta_generic_to_shared(dsmh);
    unsigned sA0 = sbase;
    unsigned sB0 = sbase + 3u * A_STH * 2u;

    int nchunk = KP32 >> 3;
    for (int e = tid; e < 64 * nchunk; e += 256) {
        int n = e / nchunk, kc8 = e - n * nchunk;
        int k = kc8 << 3;
        int gn = bn + n;
        int sz = (gn < Nc && k < K) ? 16 : 0;
        const __half* src = sz ? Bt + (long)gn * K + k : Bt;
        unsigned dst = sB0 + (unsigned)(n * KP + k) * 2u;
        asm volatile("cp.async.ca.shared.global [%0],[%1],16,%2;"
                     :: "r"(dst), "l"(src), "r"(sz));
    }

    int mt_i = blockIdx.y;
    int kc_i = 0;
    if (mt_i < MT) issue_a(A, sA0, mt_i * 128, 0, K, M, K, tid);
    asm volatile("cp.async.commit_group;" ::: "memory");
    if (++kc_i == nkc) { kc_i = 0; mt_i += gridDim.y; }
    if (mt_i < MT) issue_a(A, sA0 + A_STH * 2u, mt_i * 128, kc_i * 32, K, M, K, tid);
    asm volatile("cp.async.commit_group;" ::: "memory");
    if (++kc_i == nkc) { kc_i = 0; mt_i += gridDim.y; }

    float acc[2][4][4];
    int stage = 0;
    for (int mt = blockIdx.y; mt < MT; mt += gridDim.y) {
        #pragma unroll
        for (int mtt = 0; mtt < 2; mtt++)
            #pragma unroll
            for (int nt = 0; nt < 4; nt++)
                #pragma unroll
                for (int q = 0; q < 4; q++) acc[mtt][nt][q] = 0.f;
        for (int kc = 0; kc < nkc; kc++) {
            asm volatile("cp.async.wait_group 1;" ::: "memory");
            __syncthreads();
            int s2 = (stage + 2) % 3;
            if (mt_i < MT) issue_a(A, sA0 + (unsigned)s2 * A_STH * 2u,
                                   mt_i * 128, kc_i * 32, K, M, K, tid);
            asm volatile("cp.async.commit_group;" ::: "memory");
            if (++kc_i == nkc) { kc_i = 0; mt_i += gridDim.y; }
            mma_chunk(Asm + stage * A_STH, SMA, Bsm + kc * 32, KP, wm, wn, lane, acc);
            stage = (stage + 1) % 3;
        }
        epilogue<RELU, ACC, false, TC>(acc, bias, C, mt * 128, bn, M, Nc, wm, wn, lane);
    }
}

// ---------------- fused relu-softmax normalize (fp16 in/out) --------------------
__global__ void normgraph_kernel(__half* __restrict__ g)
{
    long row = (long)blockIdx.x * 8 + (threadIdx.x >> 5);
    if (row >= (long)TN) return;
    int lane = threadIdx.x & 31;
    uint4* p = reinterpret_cast<uint4*>(g + row * NPTS);
    float v[2][8]; uint4 u;
    float m = 0.f;
    #pragma unroll
    for (int rch = 0; rch < 2; rch++) {
        int c = lane + rch * 32;
        if (c < 50) {
            u = p[c];
            const __half2* hp = reinterpret_cast<const __half2*>(&u);
            #pragma unroll
            for (int j = 0; j < 4; j++) {
                float2 f = __half22float2(hp[j]);
                v[rch][2 * j] = f.x; v[rch][2 * j + 1] = f.y;
                m = fmaxf(m, fmaxf(f.x, f.y));
            }
        }
    }
    #pragma unroll
    for (int o = 16; o > 0; o >>= 1) m = fmaxf(m, __shfl_xor_sync(~0u, m, o));
    float s = 0.f;
    #pragma unroll
    for (int rch = 0; rch < 2; rch++) {
        int c = lane + rch * 32;
        if (c < 50) {
            #pragma unroll
            for (int j = 0; j < 8; j++) {
                float e = __expf(fmaxf(v[rch][j], 0.f) - m);
                v[rch][j] = e; s += e;
            }
        }
    }
    #pragma unroll
    for (int o = 16; o > 0; o >>= 1) s += __shfl_xor_sync(~0u, s, o);
    float inv = 1.f / s;
    #pragma unroll
    for (int rch = 0; rch < 2; rch++) {
        int c = lane + rch * 32;
        if (c < 50) {
            uint4 ou;
            __half2* hp = reinterpret_cast<__half2*>(&ou);
            #pragma unroll
            for (int j = 0; j < 4; j++)
                hp[j] = __floats2half2_rn(v[rch][2 * j] * inv, v[rch][2 * j + 1] * inv);
            p[c] = ou;
        }
    }
}

// ---------------- weight conversion kernels -------------------------------------
__global__ void rnd2h_kernel(const float* __restrict__ src, __half* __restrict__ dst, long n2)
{
    long i = (long)blockIdx.x * 256 + threadIdx.x;
    if (i >= n2) return;
    float2 f = reinterpret_cast<const float2*>(src)[i];
    reinterpret_cast<__half2*>(dst)[i] = __floats2half2_rn(f.x, f.y);
}

__global__ void trnd_kernel(const float* __restrict__ src, __half* __restrict__ dst,
                            int K, int Nc)
{
    long j = (long)blockIdx.x * 256 + threadIdx.x;
    if (j >= (long)K * Nc) return;
    int n = (int)(j / K); long k = j - (long)n * K;
    dst[j] = __float2half_rn(src[k * Nc + n]);
}

// ---------------- input proj + concat adaptive embedding ------------------------
__global__ void hcat_kernel(const float* __restrict__ x, const float* __restrict__ W_in,
                            const float* __restrict__ b_in, const __half* __restrict__ adp_h,
                            __half* __restrict__ hcat)
{
    long idx = (long)blockIdx.x * 256 + threadIdx.x;
    if (idx >= (long)TN * DD) return;
    long tn = idx / DD; int j = (int)(idx - tn * DD);
    int t = (int)(tn / NPTS), n = (int)(tn - (long)t * NPTS);
    __half v;
    if (j < 24) {
        const float* xr = x + ((long)n * TT + t) * 3;
        v = __float2half_rn(b_in[j] + xr[0] * W_in[0 * 24 + j]
                            + xr[1] * W_in[1 * 24 + j] + xr[2] * W_in[2 * 24 + j]);
    } else {
        v = adp_h[tn * 80 + (j - 24)];
    }
    hcat[idx] = v;
}

// ---------------- h -> hT [T][D][N] ----------------------------------------------
__global__ void transpose_hT_kernel(const __half* __restrict__ h, __half* __restrict__ hT)
{
    long idx = (long)blockIdx.x * 256 + threadIdx.x;
    if (idx >= (long)TN * DD) return;
    long t = idx / ((long)NPTS * DD);
    long r = idx - t * ((long)NPTS * DD);
    long n = r / DD;
    long d = r - n * DD;
    hT[t * (long)DD * NPTS + d * NPTS + n] = h[idx];
}

// ---------------- linear attention: kvs + ksum ----------------------------------
__global__ void kvs_kernel(const __half* __restrict__ qkv, long sB, long sL, int L,
                           float* __restrict__ kvs, float* __restrict__ ksum)
{
    int b = blockIdx.x, h = blockIdx.y;
    int w = threadIdx.x >> 5, lane = threadIdx.x & 31;
    int chunk = (L + 7) >> 3;
    int l0 = w * chunk, l1 = min(L, l0 + chunk);
    const __half* base = qkv + (long)b * sB + h * HD;
    float acc[HD];
    #pragma unroll
    for (int m = 0; m < HD; m++) acc[m] = 0.f;
    float accs = 0.f;
    for (int l = l0; l < l1; l++) {
        const __half* row = base + (long)l * sL;
        float kk = (lane < HD) ? __half2float(row[DD + lane]) : 0.f;
        float vv = (lane < HD) ? __half2float(row[2 * DD + lane]) : 0.f;
        float ss = kk * kk;
        #pragma unroll
        for (int o = 16; o > 0; o >>= 1) ss += __shfl_xor_sync(~0u, ss, o);
        float inv = 1.f / fmaxf(sqrtf(ss), 1e-12f);
        float kin = kk * inv;
        accs += kin;
        #pragma unroll
        for (int m = 0; m < HD; m++) {
            float km = __shfl_sync(~0u, kin, m);
            acc[m] += km * vv;
        }
    }
    __shared__ float red[8][HD][HD + 2];
    __shared__ float redk[8][32];
    if (lane < HD) {
        #pragma unroll
        for (int m = 0; m < HD; m++) red[w][m][lane] = acc[m];
    }
    redk[w][lane] = accs;
    __syncthreads();
    long basec = ((long)b * HH + h);
    for (int cell = threadIdx.x; cell < HD * HD; cell += 256) {
        int m = cell / HD, d = cell - m * HD;
        float s = 0.f;
        #pragma unroll
        for (int ww = 0; ww < 8; ww++) s += red[ww][m][d];
        kvs[basec * (HD * HD) + cell] = s;
    }
    if (threadIdx.x < HD) {
        float s = 0.f;
        #pragma unroll
        for (int ww = 0; ww < 8; ww++) s += redk[ww][threadIdx.x];
        ksum[basec * HD + threadIdx.x] = s;
    }
}

// ---------------- fused spatial+temporal attention output -----------------------
// block (n, t): reads qkv row (t,n) once, writes cat2 row [spatial | temporal].
__global__ void attnout2_kernel(const __half* __restrict__ qkv,
                                const float* __restrict__ kvs_s, const float* __restrict__ ksum_s,
                                const float* __restrict__ kvs_t, const float* __restrict__ ksum_t,
                                __half* __restrict__ cat2)
{
    int n = blockIdx.x, t = blockIdx.y;
    int tid = threadIdx.x;
    long tok = (long)t * NPTS + n;
    const __half* row = qkv + tok * D3;
    __shared__ float sq[DD], sv[DD], sinv[HH], sden_s[HH], sden_t[HH];
    if (tid < DD) {
        sq[tid] = __half2float(row[tid]);
        sv[tid] = __half2float(row[2 * DD + tid]);
    }
    __syncthreads();
    if (tid < HH) {
        const float* qh = sq + tid * HD;
        float ss = 0.f;
        #pragma unroll
        for (int m = 0; m < HD; m++) ss += qh[m] * qh[m];
        float inv = 1.f / fmaxf(sqrtf(ss), 1e-12f);
        sinv[tid] = inv;
        const float* ks = ksum_s + ((long)t * HH + tid) * HD;
        const float* kt = ksum_t + ((long)n * HH + tid) * HD;
        float ds = 0.f, dt = 0.f;
        #pragma unroll
        for (int m = 0; m < HD; m++) { ds += qh[m] * ks[m]; dt += qh[m] * kt[m]; }
        sden_s[tid] = ds * inv + (float)NPTS;
        sden_t[tid] = dt * inv + (float)TT;
    }
    __syncthreads();
    if (tid < DD) {
        int h = tid / HD, d = tid - h * HD;
        const float* qh = sq + h * HD;
        const float* kv_s = kvs_s + ((long)t * HH + h) * (HD * HD) + d;
        const float* kv_t = kvs_t + ((long)n * HH + h) * (HD * HD) + d;
        float ss = 0.f, st = 0.f;
        #pragma unroll
        for (int m = 0; m < HD; m++) {
            ss += qh[m] * kv_s[m * HD];
            st += qh[m] * kv_t[m * HD];
        }
        float inv = sinv[h], vv = sv[tid];
        cat2[tok * D2 + tid]      = __float2half_rn((ss * inv + (float)NPTS * vv) / sden_s[h]);
        cat2[tok * D2 + DD + tid] = __float2half_rn((st * inv + (float)TT   * vv) / sden_t[h]);
    }
}

// ---------------- fused combine + LayerNorm --------------------------------------
__global__ void combine_ln_kernel(const __half* __restrict__ h, const __half* __restrict__ a0,
                                  const float* __restrict__ a1, const float* __restrict__ p0,
                                  const float* __restrict__ p1, const float* __restrict__ gam,
                                  const float* __restrict__ bet, __half* __restrict__ out)
{
    long row = blockIdx.x; int tid = threadIdx.x;
    __shared__ float red[4];
    long i = row * DD + tid;
    float v = 0.f;
    if (tid < DD)
        v = 2.f * (__half2float(h[i]) + __half2float(a0[i]) * p0[i] + 0.01f * a1[i] * p1[i]);
    float s = (tid < DD) ? v : 0.f;
    #pragma unroll
    for (int o = 16; o > 0; o >>= 1) s += __shfl_xor_sync(~0u, s, o);
    if ((tid & 31) == 0) red[tid >> 5] = s;
    __syncthreads();
    float mean = (red[0] + red[1] + red[2] + red[3]) / (float)DD;
    __syncthreads();
    float d = (tid < DD) ? (v - mean) : 0.f;
    float s2 = d * d;
    #pragma unroll
    for (int o = 16; o > 0; o >>= 1) s2 += __shfl_xor_sync(~0u, s2, o);
    if ((tid & 31) == 0) red[tid >> 5] = s2;
    __syncthreads();
    float var = (red[0] + red[1] + red[2] + red[3]) / (float)DD;
    if (tid < DD) out[i] = __float2half_rn(d * rsqrtf(var + 1e-5f) * gam[tid] + bet[tid]);
}

// ln + residual, writing DIRECTLY into transposed layout h2t[n][t*DD+d]
__global__ void ln_res_t_kernel(const __half* __restrict__ a, const float* __restrict__ b,
                                const float* __restrict__ gam, const float* __restrict__ bet,
                                __half* __restrict__ h2t)
{
    long row = blockIdx.x; int tid = threadIdx.x;
    __shared__ float red[4];
    long i = row * DD + tid;
    float v = 0.f;
    if (tid < DD) v = __half2float(a[i]) + b[i];
    float s = (tid < DD) ? v : 0.f;
    #pragma unroll
    for (int o = 16; o > 0; o >>= 1) s += __shfl_xor_sync(~0u, s, o);
    if ((tid & 31) == 0) red[tid >> 5] = s;
    __syncthreads();
    float mean = (red[0] + red[1] + red[2] + red[3]) / (float)DD;
    __syncthreads();
    float d = (tid < DD) ? (v - mean) : 0.f;
    float s2 = d * d;
    #pragma unroll
    for (int o = 16; o > 0; o >>= 1) s2 += __shfl_xor_sync(~0u, s2, o);
    if ((tid & 31) == 0) red[tid >> 5] = s2;
    __syncthreads();
    float var = (red[0] + red[1] + red[2] + red[3]) / (float)DD;
    if (tid < DD) {
        long t = row / NPTS, n = row - t * NPTS;
        h2t[n * (long)TD + t * DD + tid] =
            __float2half_rn(d * rsqrtf(var + 1e-5f) * gam[tid] + bet[tid]);
    }
}

// ---------------- split-K deterministic reduction -------------------------------
__global__ void splitk_reduce_kernel(const float* __restrict__ part, const float* __restrict__ bias,
                                     __half* __restrict__ y, int MN, int Z, int Nc)
{
    int i = blockIdx.x * 256 + threadIdx.x;
    if (i >= MN) return;
    float s = bias[i % Nc];
    for (int z = 0; z < Z; z++) s += part[(long)z * MN + i];
    y[i] = __float2half_rn(s);
}

// ---------------- streaming GEMM launcher ---------------------------------------
template<bool RELU, bool ACC, typename TC>
static void launch_stream_t(const __half* A, const __half* Bt, const float* bias, TC* C,
                            int M, int K, int Nc, cudaStream_t st)
{
    int nkc = (K + 31) / 32;
    int KP = nkc * 32 + 8;
    int smem = 3 * A_STH * 2 + 64 * KP * 2;
    int nx = (Nc + 63) / 64;
    int MT = (M + 127) / 128;
    int gy = (444 + nx - 1) / nx;
    if (gy > MT) gy = MT;
    gemm_stream<RELU, ACC, TC><<<dim3(nx, gy), 256, smem, st>>>(A, Bt, bias, C, M, K, Nc, KP);
}

// ---------------- host orchestration --------------------------------------------
static void run_attention(const __half* x4, const __half* qwT, const __half* owT,
                          const float* ob, __half* qkv,
                          float* kvs_s, float* ksum_s, float* kvs_t, float* ksum_t,
                          __half* cat2, __half* att_h, float* att_f, cudaStream_t st)
{
    launch_stream_t<false, false, __half>(x4, qwT, nullptr, qkv, TN, DD, D3, st);
    kvs_kernel<<<dim3(TT, HH), 256, 0, st>>>(qkv, (long)NPTS * D3, (long)D3, NPTS, kvs_s, ksum_s);
    kvs_kernel<<<dim3(NPTS, HH), 256, 0, st>>>(qkv, (long)D3, (long)NPTS * D3, TT, kvs_t, ksum_t);
    attnout2_kernel<<<dim3(NPTS, TT), 128, 0, st>>>(qkv, kvs_s, ksum_s, kvs_t, ksum_t, cat2);
    if (att_h) launch_stream_t<false, false, __half>(cat2, owT, ob, att_h, TN, D2, DD, st);
    else       launch_stream_t<false, false, float >(cat2, owT, ob, att_f, TN, D2, DD, st);
}

extern "C" void kernel_launch(void* const* d_in, const int* in_sizes, int n_in,
                              void* d_out, int out_size)
{
    (void)in_sizes; (void)n_in; (void)out_size;
    const float* x     = (const float*)d_in[0];
    const float* W_in  = (const float*)d_in[1];
    const float* b_in  = (const float*)d_in[2];
    const float* adp   = (const float*)d_in[3];
    const float* W_tp  = (const float*)d_in[4];
    const float* b_tp  = (const float*)d_in[5];
    const float* qkv_w = (const float*)d_in[6];
    const float* op_w  = (const float*)d_in[7];
    const float* op_b  = (const float*)d_in[8];
    const float* pw_w  = (const float*)d_in[9];
    const float* pw_b  = (const float*)d_in[10];
    const float* fc_w1 = (const float*)d_in[11];
    const float* fc_b1 = (const float*)d_in[12];
    const float* fc_w2 = (const float*)d_in[13];
    const float* fc_b2 = (const float*)d_in[14];
    const float* ln1_g = (const float*)d_in[15];
    const float* ln1_b = (const float*)d_in[16];
    const float* ln2_g = (const float*)d_in[17];
    const float* ln2_b = (const float*)d_in[18];
    const float* ep_w  = (const float*)d_in[19];
    const float* ep_b  = (const float*)d_in[20];
    const float* enc_w1= (const float*)d_in[21];
    const float* enc_b1= (const float*)d_in[22];
    const float* enc_w2= (const float*)d_in[23];
    const float* enc_b2= (const float*)d_in[24];
    const float* out_w = (const float*)d_in[25];
    const float* out_b = (const float*)d_in[26];
    float* out = (float*)d_out;

    static cudaStream_t s1 = nullptr;
    static cudaEvent_t evA0, evA1, evB0, evB1;
    if (!s1) {
        cudaStreamCreateWithFlags(&s1, cudaStreamNonBlocking);
        cudaEventCreateWithFlags(&evA0, cudaEventDisableTiming);
        cudaEventCreateWithFlags(&evA1, cudaEventDisableTiming);
        cudaEventCreateWithFlags(&evB0, cudaEventDisableTiming);
        cudaEventCreateWithFlags(&evB1, cudaEventDisableTiming);
        cudaFuncSetAttribute(gemm_kernel<false, __half>,
                             cudaFuncAttributeMaxDynamicSharedMemorySize, SMEM_BATCH);
        cudaFuncSetAttribute(gemm_kernel<true, float>,
                             cudaFuncAttributeMaxDynamicSharedMemorySize, SMEM_BATCH);
        cudaFuncSetAttribute(gemm_stream<false, false, __half>,
                             cudaFuncAttributeMaxDynamicSharedMemorySize, SMEM_STREAM_MAX);
        cudaFuncSetAttribute(gemm_stream<true, false, __half>,
                             cudaFuncAttributeMaxDynamicSharedMemorySize, SMEM_STREAM_MAX);
        cudaFuncSetAttribute(gemm_stream<false, true, __half>,
                             cudaFuncAttributeMaxDynamicSharedMemorySize, SMEM_STREAM_MAX);
        cudaFuncSetAttribute(gemm_stream<false, false, float>,
                             cudaFuncAttributeMaxDynamicSharedMemorySize, SMEM_STREAM_MAX);
    }

    __half *hcat, *h, *hT, *graph, *z1, *qkv, *cat2, *att0, *h1, *h2t, *y, *yh, *wtsh;
    float *kvs_s, *ksum_s, *kvs_t, *ksum_t, *att1, *p0, *p1, *t2, *part;
    cudaGetSymbolAddress((void**)&hcat, g_hcat);
    cudaGetSymbolAddress((void**)&h,    g_h);
    cudaGetSymbolAddress((void**)&hT,   g_hT);
    cudaGetSymbolAddress((void**)&graph,g_graph);
    cudaGetSymbolAddress((void**)&z1,   g_z1);
    cudaGetSymbolAddress((void**)&qkv,  g_qkv);
    cudaGetSymbolAddress((void**)&kvs_s, g_kvs_s);
    cudaGetSymbolAddress((void**)&ksum_s,g_ksum_s);
    cudaGetSymbolAddress((void**)&kvs_t, g_kvs_t);
    cudaGetSymbolAddress((void**)&ksum_t,g_ksum_t);
    cudaGetSymbolAddress((void**)&cat2, g_cat2);
    cudaGetSymbolAddress((void**)&att0, g_att0);
    cudaGetSymbolAddress((void**)&att1, g_att1);
    cudaGetSymbolAddress((void**)&p0,   g_p0);
    cudaGetSymbolAddress((void**)&p1,   g_p1);
    cudaGetSymbolAddress((void**)&h1,   g_h1);
    cudaGetSymbolAddress((void**)&t2,   g_t2);
    cudaGetSymbolAddress((void**)&h2t,  g_h2t);
    cudaGetSymbolAddress((void**)&part, g_part);
    cudaGetSymbolAddress((void**)&y,    g_y);
    cudaGetSymbolAddress((void**)&yh,   g_yh);
    cudaGetSymbolAddress((void**)&wtsh, g_wtsh);

    __half* adp_h  = wtsh + O_ADP;
    __half* WtpT   = wtsh + O_WTP;
    __half* qkvwT  = wtsh + O_QKVW;
    __half* opwT   = wtsh + O_OPW;
    __half* pwwT   = wtsh + O_PWW;
    __half* fc1T   = wtsh + O_FC1;
    __half* fc2T   = wtsh + O_FC2;
    __half* epwT   = wtsh + O_EPW;
    __half* enc1T  = wtsh + O_ENC1;
    __half* enc2T  = wtsh + O_ENC2;
    __half* outwT  = wtsh + O_OUTW;

    // ---- adp conversion first (both branches need it) ----
    {
        long n2 = (long)TT * NPTS * 80 / 2;
        rnd2h_kernel<<<(n2 + 255) / 256, 256>>>(adp, adp_h, n2);
    }

    // ======== FORK A: graph branch + ep_w transpose on s1 ========
    cudaEventRecord(evA0, 0);
    cudaStreamWaitEvent(s1, evA0, 0);
    gemm_kernel<false, __half><<<dim3(7, 4, TT), 256, SMEM_BATCH, s1>>>(
        adp_h, adp_h, nullptr, graph, NPTS, 80, NPTS,
        (long)NPTS * 80, (long)NPTS * 80, (long)NPTS * NPTS);
    normgraph_kernel<<<(TN + 7) / 8, 256, 0, s1>>>(graph);
    trnd_kernel<<<(((long)TD * DD) + 255) / 256, 256, 0, s1>>>(ep_w, epwT, TD, DD);

    // ---- main: remaining weight conversions ----
    #define TRND(src, dst, K_, N_) \
        trnd_kernel<<<(((long)(K_) * (N_)) + 255) / 256, 256>>>(src, dst, K_, N_)
    TRND(W_tp, WtpT, DD, DD);
    TRND(qkv_w,            qkvwT,             DD, D3);
    TRND(qkv_w + DD * D3,  qkvwT + D3 * DD,   DD, D3);
    TRND(op_w,             opwT,              D2, DD);
    TRND(op_w + D2 * DD,   opwT + DD * D2,    D2, DD);
    TRND(pw_w,             pwwT,              DD, DD);
    TRND(pw_w + DD * DD,   pwwT + DD * DD,    DD, DD);
    TRND(fc_w1, fc1T, DD, D2);
    TRND(fc_w2, fc2T, D2, DD);
    for (int i = 0; i < 3; i++) {
        TRND(enc_w1 + (long)i * DD * D2, enc1T + (long)i * D2 * DD, DD, D2);
        TRND(enc_w2 + (long)i * D2 * DD, enc2T + (long)i * DD * D2, D2, DD);
    }
    TRND(out_w, outwT, DD, TT);

    // ---- main: h chain + attention branch 0 ----
    hcat_kernel<<<((long)TN * DD + 255) / 256, 256>>>(x, W_in, b_in, adp_h, hcat);
    launch_stream_t<false, false, __half>(hcat, WtpT, b_tp, h, TN, DD, DD, 0);
    transpose_hT_kernel<<<((long)TN * DD + 255) / 256, 256>>>(h, hT);
    run_attention(h, qkvwT, opwT, op_b, qkv, kvs_s, ksum_s, kvs_t, ksum_t,
                  cat2, att0, nullptr, 0);

    // ======== JOIN A; FORK B: z1 + attention branch 1 on s1 ========
    cudaEventRecord(evA1, s1);
    cudaStreamWaitEvent(0, evA1, 0);
    cudaEventRecord(evB0, 0);
    cudaStreamWaitEvent(s1, evB0, 0);
    gemm_kernel<false, __half><<<dim3(2, 4, TT), 256, SMEM_BATCH, s1>>>(
        graph, hT, nullptr, z1, NPTS, NPTS, DD,
        (long)NPTS * NPTS, (long)DD * NPTS, (long)NPTS * DD);
    run_attention(z1, qkvwT + D3 * DD, opwT + DD * D2, op_b + DD, qkv,
                  kvs_s, ksum_s, kvs_t, ksum_t, cat2, nullptr, att1, s1);

    // ---- main (concurrent): pointwise gates ----
    launch_stream_t<false, false, float>(h,    pwwT,           pw_b,      p0, TN, DD, DD, 0);
    launch_stream_t<false, false, float>(att0, pwwT + DD * DD, pw_b + DD, p1, TN, DD, DD, 0);

    // ======== JOIN B ========
    cudaEventRecord(evB1, s1);
    cudaStreamWaitEvent(0, evB1, 0);

    combine_ln_kernel<<<TN, 128>>>(h, att0, att1, p0, p1, ln1_g, ln1_b, h1);
    launch_stream_t<true,  false, __half>(h1,   fc1T, fc_b1, cat2, TN, DD, D2, 0);
    launch_stream_t<false, false, float >(cat2, fc2T, fc_b2, t2,   TN, D2, DD, 0);
    ln_res_t_kernel<<<TN, 128>>>(h1, t2, ln2_g, ln2_b, h2t);
    gemm_kernel<true, float><<<dim3(2, 4, SPLITK), 256, SMEM_BATCH>>>(
        h2t, epwT, nullptr, part, NPTS, TD, DD, 0, 0, 0);
    splitk_reduce_kernel<<<(NPTS * DD + 255) / 256, 256>>>(part, ep_b, y, NPTS * DD, SPLITK, DD);
    for (int i = 0; i < 3; i++) {
        launch_stream_t<true,  false, __half>(y,  enc1T + (long)i * D2 * DD,
                                              enc_b1 + (long)i * D2, yh, NPTS, DD, D2, 0);
        launch_stream_t<false, true,  __half>(yh, enc2T + (long)i * DD * D2,
                                              enc_b2 + (long)i * DD, y,  NPTS, D2, DD, 0);
    }
    launch_stream_t<false, false, float>(y, outwT, out_b, out, NPTS, DD, TT, 0);
}

// round 10
// speedup vs baseline: 2.4095x; 1.0035x over previous
#include <cuda_runtime.h>
#include <cuda_fp16.h>
#include <math.h>

#define TT   365
#define NPTS 400
#define DD   104
#define HH   4
#define HD   26
#define TN   (TT*NPTS)      // 146000
#define D2   (2*DD)         // 208
#define D3   (3*DD)         // 312
#define TD   (TT*DD)        // 37960
#define SPLITK 40
#define KCHUNK 960
#define SMA  40              // A/B smem row stride in halves (32 k + 8 pad)
#define A_STH (128*SMA)
#define B_STH (64*SMA)
#define SMEM_BATCH ((3*A_STH + 3*B_STH)*2)
#define SMEM_STREAM_MAX 61440

// ---------------- scratch (device globals; no runtime allocation) -------------
__device__ __align__(16) __half g_hcat[(size_t)TN*DD];
__device__ __align__(16) __half g_h   [(size_t)TN*DD];
__device__ __align__(16) __half g_hT  [(size_t)TN*DD];   // [T][D][N]
__device__ __align__(16) __half g_graph[(size_t)TT*NPTS*NPTS];
__device__ __align__(16) __half g_z1  [(size_t)TN*DD];
__device__ __align__(16) __half g_qkv [(size_t)TN*D3];
__device__ __align__(16) __half g_qkv2[(size_t)TN*D3];
__device__ float g_kvs_s [(size_t)TT*HH*HD*HD];
__device__ float g_ksum_s[(size_t)TT*HH*HD];
__device__ float g_kvs_t [(size_t)NPTS*HH*HD*HD];
__device__ float g_ksum_t[(size_t)NPTS*HH*HD];
__device__ float g_kvs_s2 [(size_t)TT*HH*HD*HD];
__device__ float g_ksum_s2[(size_t)TT*HH*HD];
__device__ float g_kvs_t2 [(size_t)NPTS*HH*HD*HD];
__device__ float g_ksum_t2[(size_t)NPTS*HH*HD];
__device__ __align__(16) __half g_cat2 [(size_t)TN*D2];
__device__ __align__(16) __half g_cat2b[(size_t)TN*D2];
__device__ __align__(16) __half g_att0[(size_t)TN*DD];
__device__ float  g_att1[(size_t)TN*DD];
__device__ float  g_p0  [(size_t)TN*DD];
__device__ float  g_p1  [(size_t)TN*DD];
__device__ __align__(16) __half g_h1  [(size_t)TN*DD];
__device__ float  g_t2  [(size_t)TN*DD];
__device__ __align__(16) __half g_h2t [(size_t)NPTS*TD];
__device__ float  g_part[(size_t)SPLITK*NPTS*DD];
__device__ __align__(16) __half g_y   [(size_t)NPTS*DD];
__device__ __align__(16) __half g_yh  [(size_t)NPTS*D2];
__device__ __align__(16) __half g_wtsh[(size_t)16000000];

// offsets into g_wtsh (halves)
#define O_ADP   0L
#define O_WTP   11680000L
#define O_QKVW  11690816L
#define O_OPW   11755712L
#define O_PWW   11798976L
#define O_FC1   11820608L
#define O_FC2   11842240L
#define O_EPW   11863872L
#define O_ENC1  15811712L
#define O_ENC2  15876608L
#define O_OUTW  15941504L

// ---------------- cp.async issue helpers ----------------------------------------
__device__ __forceinline__ void issue_a(const __half* __restrict__ A, unsigned sAs,
                                        int bm, int k0, int kend, int M, long K, int tid)
{
    #pragma unroll
    for (int p = 0; p < 2; p++) {
        int idx = tid + p * 256;
        int m = idx >> 2, kq = (idx & 3) << 3;
        int gm = bm + m;
        int rem = kend - (k0 + kq);
        int sz = (gm < M && rem >= 8) ? 16 : 0;
        const __half* src = sz ? A + (long)gm * K + k0 + kq : A;
        unsigned dst = sAs + (unsigned)(m * SMA + kq) * 2u;
        asm volatile("cp.async.ca.shared.global [%0],[%1],16,%2;"
                     :: "r"(dst), "l"(src), "r"(sz));
    }
}

__device__ __forceinline__ void issue_b(const __half* __restrict__ B, unsigned sBs,
                                        int bn, int k0, int kend, int Nc, long K, int tid)
{
    int n = tid >> 2, kq = (tid & 3) << 3;
    int gn = bn + n;
    int rem = kend - (k0 + kq);
    int sz = (gn < Nc && rem >= 8) ? 16 : 0;
    const __half* src = sz ? B + (long)gn * K + k0 + kq : B;
    unsigned dst = sBs + (unsigned)(n * SMA + kq) * 2u;
    asm volatile("cp.async.ca.shared.global [%0],[%1],16,%2;"
                 :: "r"(dst), "l"(src), "r"(sz));
}

// ---------------- fp16 MMA on a k32 chunk ---------------------------------------
__device__ __forceinline__ void mma_chunk(const __half* __restrict__ As, int sbA,
                                          const __half* __restrict__ Bs, int sbB,
                                          int wm, int wn, int lane, float (*acc)[4][4])
{
    int r = lane >> 2, c2 = (lane & 3) << 1;
    #pragma unroll
    for (int ks = 0; ks < 2; ks++) {
        int k0 = ks * 16;
        unsigned a[2][4], b[4][2];
        #pragma unroll
        for (int mt = 0; mt < 2; mt++) {
            const __half* p = As + (wm * 32 + mt * 16 + r) * sbA + k0 + c2;
            a[mt][0] = *reinterpret_cast<const unsigned*>(p);
            a[mt][1] = *reinterpret_cast<const unsigned*>(p + 8 * sbA);
            a[mt][2] = *reinterpret_cast<const unsigned*>(p + 8);
            a[mt][3] = *reinterpret_cast<const unsigned*>(p + 8 * sbA + 8);
        }
        #pragma unroll
        for (int nt = 0; nt < 4; nt++) {
            const __half* q = Bs + (wn * 32 + nt * 8 + r) * sbB + k0 + c2;
            b[nt][0] = *reinterpret_cast<const unsigned*>(q);
            b[nt][1] = *reinterpret_cast<const unsigned*>(q + 8);
        }
        #pragma unroll
        for (int mt = 0; mt < 2; mt++)
            #pragma unroll
            for (int nt = 0; nt < 4; nt++)
                asm("mma.sync.aligned.m16n8k16.row.col.f32.f16.f16.f32 "
                    "{%0,%1,%2,%3},{%4,%5,%6,%7},{%8,%9},{%0,%1,%2,%3};"
                    : "+f"(acc[mt][nt][0]), "+f"(acc[mt][nt][1]),
                      "+f"(acc[mt][nt][2]), "+f"(acc[mt][nt][3])
                    : "r"(a[mt][0]), "r"(a[mt][1]), "r"(a[mt][2]), "r"(a[mt][3]),
                      "r"(b[nt][0]), "r"(b[nt][1]));
    }
}

// ---------------- epilogue -------------------------------------------------------
template<bool RELU, bool ACC, bool SPLIT, typename TC>
__device__ __forceinline__ void epilogue(float (*acc)[4][4], const float* bias,
                                         TC* __restrict__ C, int bm, int bn,
                                         int M, int Nc, int wm, int wn, int lane)
{
    int r = lane >> 2, c2 = (lane & 3) << 1;
    #pragma unroll
    for (int mt = 0; mt < 2; mt++) {
        #pragma unroll
        for (int nt = 0; nt < 4; nt++) {
            int gm0 = bm + wm * 32 + mt * 16 + r;
            int gn0 = bn + wn * 32 + nt * 8 + c2;
            #pragma unroll
            for (int hh = 0; hh < 2; hh++) {
                int gm = gm0 + hh * 8;
                if (gm >= M) continue;
                #pragma unroll
                for (int j = 0; j < 2; j++) {
                    int gn = gn0 + j;
                    if (gn >= Nc) continue;
                    float v = acc[mt][nt][hh * 2 + j];
                    if (!SPLIT && bias) v += bias[gn];
                    if (RELU) v = fmaxf(v, 0.f);
                    long ci = (long)gm * Nc + gn;
                    if (ACC) v += (float)C[ci];
                    C[ci] = (TC)v;
                }
            }
        }
    }
}

// ---------------- batched / split fp16 GEMM (B always [n][k]) -------------------
template<bool SPLIT, typename TC>
__global__ void __launch_bounds__(256)
gemm_kernel(const __half* __restrict__ A, const __half* __restrict__ B,
            const float* __restrict__ bias, TC* __restrict__ C,
            int M, int K, int Nc, long sA, long sB_, long sC)
{
    extern __shared__ __half dsmh[];
    int tid = threadIdx.x;
    int bm = blockIdx.y * 128, bn = blockIdx.x * 64;
    int kbeg = 0, kend = K;
    if (SPLIT) {
        int z = blockIdx.z;
        kbeg = z * KCHUNK;
        kend = min(K, kbeg + KCHUNK);
        C += (long)z * M * Nc;
    } else {
        int z = blockIdx.z;
        A += z * sA; B += z * sB_; C += z * sC;
    }
    int w = tid >> 5, lane = tid & 31;
    int wm = w >> 1, wn = w & 1;
    float acc[2][4][4];
    #pragma unroll
    for (int mt = 0; mt < 2; mt++)
        #pragma unroll
        for (int nt = 0; nt < 4; nt++)
            #pragma unroll
            for (int q = 0; q < 4; q++) acc[mt][nt][q] = 0.f;

    unsigned sbase = (unsigned)__cvta_generic_to_shared(dsmh);
    unsigned sA0 = sbase;
    unsigned sB0 = sbase + 3u * A_STH * 2u;

    int nk = (kend - kbeg + 31) >> 5;
    issue_a(A, sA0, bm, kbeg, kend, M, K, tid);
    issue_b(B, sB0, bn, kbeg, kend, Nc, K, tid);
    asm volatile("cp.async.commit_group;" ::: "memory");
    issue_a(A, sA0 + A_STH * 2u, bm, kbeg + 32, kend, M, K, tid);
    issue_b(B, sB0 + B_STH * 2u, bn, kbeg + 32, kend, Nc, K, tid);
    asm volatile("cp.async.commit_group;" ::: "memory");

    for (int it = 0; it < nk; it++) {
        asm volatile("cp.async.wait_group 1;" ::: "memory");
        __syncthreads();
        int s2 = (it + 2) % 3;
        int kn = kbeg + (it + 2) * 32;
        issue_a(A, sA0 + (unsigned)s2 * A_STH * 2u, bm, kn, kend, M, K, tid);
        issue_b(B, sB0 + (unsigned)s2 * B_STH * 2u, bn, kn, kend, Nc, K, tid);
        asm volatile("cp.async.commit_group;" ::: "memory");
        int sc = it % 3;
        mma_chunk(dsmh + sc * A_STH, SMA, dsmh + 3 * A_STH + sc * B_STH, SMA,
                  wm, wn, lane, acc);
    }
    epilogue<false, false, SPLIT, TC>(acc, bias, C, bm, bn, M, Nc, wm, wn, lane);
}

// ---------------- persistent-B streaming GEMM (NN, non-batched) -----------------
template<bool RELU, bool ACC, typename TC>
__global__ void __launch_bounds__(256)
gemm_stream(const __half* __restrict__ A, const __half* __restrict__ Bt,
            const float* __restrict__ bias, TC* __restrict__ C,
            int M, int K, int Nc, int KP)
{
    extern __shared__ __half dsmh[];
    __half* Asm = dsmh;
    __half* Bsm = dsmh + 3 * A_STH;
    int tid = threadIdx.x;
    int bn = blockIdx.x * 64;
    int nkc = (K + 31) >> 5;
    int KP32 = nkc * 32;
    int MT = (M + 127) >> 7;
    int w = tid >> 5, lane = tid & 31;
    int wm = w >> 1, wn = w & 1;

    unsigned sbase = (unsigned)__cvta_generic_to_shared(dsmh);
    unsigned sA0 = sbase;
    unsigned sB0 = sbase + 3u * A_STH * 2u;

    int nchunk = KP32 >> 3;
    for (int e = tid; e < 64 * nchunk; e += 256) {
        int n = e / nchunk, kc8 = e - n * nchunk;
        int k = kc8 << 3;
        int gn = bn + n;
        int sz = (gn < Nc && k < K) ? 16 : 0;
        const __half* src = sz ? Bt + (long)gn * K + k : Bt;
        unsigned dst = sB0 + (unsigned)(n * KP + k) * 2u;
        asm volatile("cp.async.ca.shared.global [%0],[%1],16,%2;"
                     :: "r"(dst), "l"(src), "r"(sz));
    }

    int mt_i = blockIdx.y;
    int kc_i = 0;
    if (mt_i < MT) issue_a(A, sA0, mt_i * 128, 0, K, M, K, tid);
    asm volatile("cp.async.commit_group;" ::: "memory");
    if (++kc_i == nkc) { kc_i = 0; mt_i += gridDim.y; }
    if (mt_i < MT) issue_a(A, sA0 + A_STH * 2u, mt_i * 128, kc_i * 32, K, M, K, tid);
    asm volatile("cp.async.commit_group;" ::: "memory");
    if (++kc_i == nkc) { kc_i = 0; mt_i += gridDim.y; }

    float acc[2][4][4];
    int stage = 0;
    for (int mt = blockIdx.y; mt < MT; mt += gridDim.y) {
        #pragma unroll
        for (int mtt = 0; mtt < 2; mtt++)
            #pragma unroll
            for (int nt = 0; nt < 4; nt++)
                #pragma unroll
                for (int q = 0; q < 4; q++) acc[mtt][nt][q] = 0.f;
        for (int kc = 0; kc < nkc; kc++) {
            asm volatile("cp.async.wait_group 1;" ::: "memory");
            __syncthreads();
            int s2 = (stage + 2) % 3;
            if (mt_i < MT) issue_a(A, sA0 + (unsigned)s2 * A_STH * 2u,
                                   mt_i * 128, kc_i * 32, K, M, K, tid);
            asm volatile("cp.async.commit_group;" ::: "memory");
            if (++kc_i == nkc) { kc_i = 0; mt_i += gridDim.y; }
            mma_chunk(Asm + stage * A_STH, SMA, Bsm + kc * 32, KP, wm, wn, lane, acc);
            stage = (stage + 1) % 3;
        }
        epilogue<RELU, ACC, false, TC>(acc, bias, C, mt * 128, bn, M, Nc, wm, wn, lane);
    }
}

// ---------------- fused relu-softmax normalize (fp16 in/out) --------------------
__global__ void normgraph_kernel(__half* __restrict__ g)
{
    long row = (long)blockIdx.x * 8 + (threadIdx.x >> 5);
    if (row >= (long)TN) return;
    int lane = threadIdx.x & 31;
    uint4* p = reinterpret_cast<uint4*>(g + row * NPTS);
    float v[2][8]; uint4 u;
    float m = 0.f;
    #pragma unroll
    for (int rch = 0; rch < 2; rch++) {
        int c = lane + rch * 32;
        if (c < 50) {
            u = p[c];
            const __half2* hp = reinterpret_cast<const __half2*>(&u);
            #pragma unroll
            for (int j = 0; j < 4; j++) {
                float2 f = __half22float2(hp[j]);
                v[rch][2 * j] = f.x; v[rch][2 * j + 1] = f.y;
                m = fmaxf(m, fmaxf(f.x, f.y));
            }
        }
    }
    #pragma unroll
    for (int o = 16; o > 0; o >>= 1) m = fmaxf(m, __shfl_xor_sync(~0u, m, o));
    float s = 0.f;
    #pragma unroll
    for (int rch = 0; rch < 2; rch++) {
        int c = lane + rch * 32;
        if (c < 50) {
            #pragma unroll
            for (int j = 0; j < 8; j++) {
                float e = __expf(fmaxf(v[rch][j], 0.f) - m);
                v[rch][j] = e; s += e;
            }
        }
    }
    #pragma unroll
    for (int o = 16; o > 0; o >>= 1) s += __shfl_xor_sync(~0u, s, o);
    float inv = 1.f / s;
    #pragma unroll
    for (int rch = 0; rch < 2; rch++) {
        int c = lane + rch * 32;
        if (c < 50) {
            uint4 ou;
            __half2* hp = reinterpret_cast<__half2*>(&ou);
            #pragma unroll
            for (int j = 0; j < 4; j++)
                hp[j] = __floats2half2_rn(v[rch][2 * j] * inv, v[rch][2 * j + 1] * inv);
            p[c] = ou;
        }
    }
}

// ---------------- weight conversion kernels -------------------------------------
__global__ void rnd2h_kernel(const float* __restrict__ src, __half* __restrict__ dst, long n2)
{
    long i = (long)blockIdx.x * 256 + threadIdx.x;
    if (i >= n2) return;
    float2 f = reinterpret_cast<const float2*>(src)[i];
    reinterpret_cast<__half2*>(dst)[i] = __floats2half2_rn(f.x, f.y);
}

__global__ void trnd_kernel(const float* __restrict__ src, __half* __restrict__ dst,
                            int K, int Nc)
{
    long j = (long)blockIdx.x * 256 + threadIdx.x;
    if (j >= (long)K * Nc) return;
    int n = (int)(j / K); long k = j - (long)n * K;
    dst[j] = __float2half_rn(src[k * Nc + n]);
}

// tiled transpose for big weights: dst[n][k] = (half)src[k][n], coalesced both ways
__global__ void trnd_tiled_kernel(const float* __restrict__ src, __half* __restrict__ dst,
                                  int K, int Nc)
{
    __shared__ float tile[32][33];
    int k0 = blockIdx.x * 32, n0 = blockIdx.y * 32;
    int tx = threadIdx.x & 31, ty = threadIdx.x >> 5;   // 256 threads: ty 0..7
    #pragma unroll
    for (int i = ty; i < 32; i += 8) {
        int k = k0 + i, n = n0 + tx;
        tile[i][tx] = (k < K && n < Nc) ? src[(long)k * Nc + n] : 0.f;
    }
    __syncthreads();
    #pragma unroll
    for (int i = ty; i < 32; i += 8) {
        int n = n0 + i, k = k0 + tx;
        if (n < Nc && k < K) dst[(long)n * K + k] = __float2half_rn(tile[tx][i]);
    }
}

// ---------------- input proj + concat adaptive embedding ------------------------
__global__ void hcat_kernel(const float* __restrict__ x, const float* __restrict__ W_in,
                            const float* __restrict__ b_in, const __half* __restrict__ adp_h,
                            __half* __restrict__ hcat)
{
    long idx = (long)blockIdx.x * 256 + threadIdx.x;
    if (idx >= (long)TN * DD) return;
    long tn = idx / DD; int j = (int)(idx - tn * DD);
    int t = (int)(tn / NPTS), n = (int)(tn - (long)t * NPTS);
    __half v;
    if (j < 24) {
        const float* xr = x + ((long)n * TT + t) * 3;
        v = __float2half_rn(b_in[j] + xr[0] * W_in[0 * 24 + j]
                            + xr[1] * W_in[1 * 24 + j] + xr[2] * W_in[2 * 24 + j]);
    } else {
        v = adp_h[tn * 80 + (j - 24)];
    }
    hcat[idx] = v;
}

// ---------------- h -> hT [T][D][N] ----------------------------------------------
__global__ void transpose_hT_kernel(const __half* __restrict__ h, __half* __restrict__ hT)
{
    long idx = (long)blockIdx.x * 256 + threadIdx.x;
    if (idx >= (long)TN * DD) return;
    long t = idx / ((long)NPTS * DD);
    long r = idx - t * ((long)NPTS * DD);
    long n = r / DD;
    long d = r - n * DD;
    hT[t * (long)DD * NPTS + d * NPTS + n] = h[idx];
}

// ---------------- linear attention: kvs + ksum ----------------------------------
__global__ void kvs_kernel(const __half* __restrict__ qkv, long sB, long sL, int L,
                           float* __restrict__ kvs, float* __restrict__ ksum)
{
    int b = blockIdx.x, h = blockIdx.y;
    int w = threadIdx.x >> 5, lane = threadIdx.x & 31;
    int chunk = (L + 7) >> 3;
    int l0 = w * chunk, l1 = min(L, l0 + chunk);
    const __half* base = qkv + (long)b * sB + h * HD;
    float acc[HD];
    #pragma unroll
    for (int m = 0; m < HD; m++) acc[m] = 0.f;
    float accs = 0.f;
    for (int l = l0; l < l1; l++) {
        const __half* row = base + (long)l * sL;
        float kk = (lane < HD) ? __half2float(row[DD + lane]) : 0.f;
        float vv = (lane < HD) ? __half2float(row[2 * DD + lane]) : 0.f;
        float ss = kk * kk;
        #pragma unroll
        for (int o = 16; o > 0; o >>= 1) ss += __shfl_xor_sync(~0u, ss, o);
        float inv = 1.f / fmaxf(sqrtf(ss), 1e-12f);
        float kin = kk * inv;
        accs += kin;
        #pragma unroll
        for (int m = 0; m < HD; m++) {
            float km = __shfl_sync(~0u, kin, m);
            acc[m] += km * vv;
        }
    }
    __shared__ float red[8][HD][HD + 2];
    __shared__ float redk[8][32];
    if (lane < HD) {
        #pragma unroll
        for (int m = 0; m < HD; m++) red[w][m][lane] = acc[m];
    }
    redk[w][lane] = accs;
    __syncthreads();
    long basec = ((long)b * HH + h);
    for (int cell = threadIdx.x; cell < HD * HD; cell += 256) {
        int m = cell / HD, d = cell - m * HD;
        float s = 0.f;
        #pragma unroll
        for (int ww = 0; ww < 8; ww++) s += red[ww][m][d];
        kvs[basec * (HD * HD) + cell] = s;
    }
    if (threadIdx.x < HD) {
        float s = 0.f;
        #pragma unroll
        for (int ww = 0; ww < 8; ww++) s += redk[ww][threadIdx.x];
        ksum[basec * HD + threadIdx.x] = s;
    }
}

// ---------------- fused spatial+temporal attention output -----------------------
__global__ void attnout2_kernel(const __half* __restrict__ qkv,
                                const float* __restrict__ kvs_s, const float* __restrict__ ksum_s,
                                const float* __restrict__ kvs_t, const float* __restrict__ ksum_t,
                                __half* __restrict__ cat2)
{
    int n = blockIdx.x, t = blockIdx.y;
    int tid = threadIdx.x;
    long tok = (long)t * NPTS + n;
    const __half* row = qkv + tok * D3;
    __shared__ float sq[DD], sv[DD], sinv[HH], sden_s[HH], sden_t[HH];
    if (tid < DD) {
        sq[tid] = __half2float(row[tid]);
        sv[tid] = __half2float(row[2 * DD + tid]);
    }
    __syncthreads();
    if (tid < HH) {
        const float* qh = sq + tid * HD;
        float ss = 0.f;
        #pragma unroll
        for (int m = 0; m < HD; m++) ss += qh[m] * qh[m];
        float inv = 1.f / fmaxf(sqrtf(ss), 1e-12f);
        sinv[tid] = inv;
        const float* ks = ksum_s + ((long)t * HH + tid) * HD;
        const float* kt = ksum_t + ((long)n * HH + tid) * HD;
        float ds = 0.f, dt = 0.f;
        #pragma unroll
        for (int m = 0; m < HD; m++) { ds += qh[m] * ks[m]; dt += qh[m] * kt[m]; }
        sden_s[tid] = ds * inv + (float)NPTS;
        sden_t[tid] = dt * inv + (float)TT;
    }
    __syncthreads();
    if (tid < DD) {
        int h = tid / HD, d = tid - h * HD;
        const float* qh = sq + h * HD;
        const float* kv_s = kvs_s + ((long)t * HH + h) * (HD * HD) + d;
        const float* kv_t = kvs_t + ((long)n * HH + h) * (HD * HD) + d;
        float ss = 0.f, st = 0.f;
        #pragma unroll
        for (int m = 0; m < HD; m++) {
            ss += qh[m] * kv_s[m * HD];
            st += qh[m] * kv_t[m * HD];
        }
        float inv = sinv[h], vv = sv[tid];
        cat2[tok * D2 + tid]      = __float2half_rn((ss * inv + (float)NPTS * vv) / sden_s[h]);
        cat2[tok * D2 + DD + tid] = __float2half_rn((st * inv + (float)TT   * vv) / sden_t[h]);
    }
}

// ---------------- fused combine + LayerNorm --------------------------------------
__global__ void combine_ln_kernel(const __half* __restrict__ h, const __half* __restrict__ a0,
                                  const float* __restrict__ a1, const float* __restrict__ p0,
                                  const float* __restrict__ p1, const float* __restrict__ gam,
                                  const float* __restrict__ bet, __half* __restrict__ out)
{
    long row = blockIdx.x; int tid = threadIdx.x;
    __shared__ float red[4];
    long i = row * DD + tid;
    float v = 0.f;
    if (tid < DD)
        v = 2.f * (__half2float(h[i]) + __half2float(a0[i]) * p0[i] + 0.01f * a1[i] * p1[i]);
    float s = (tid < DD) ? v : 0.f;
    #pragma unroll
    for (int o = 16; o > 0; o >>= 1) s += __shfl_xor_sync(~0u, s, o);
    if ((tid & 31) == 0) red[tid >> 5] = s;
    __syncthreads();
    float mean = (red[0] + red[1] + red[2] + red[3]) / (float)DD;
    __syncthreads();
    float d = (tid < DD) ? (v - mean) : 0.f;
    float s2 = d * d;
    #pragma unroll
    for (int o = 16; o > 0; o >>= 1) s2 += __shfl_xor_sync(~0u, s2, o);
    if ((tid & 31) == 0) red[tid >> 5] = s2;
    __syncthreads();
    float var = (red[0] + red[1] + red[2] + red[3]) / (float)DD;
    if (tid < DD) out[i] = __float2half_rn(d * rsqrtf(var + 1e-5f) * gam[tid] + bet[tid]);
}

// ln + residual, writing DIRECTLY into transposed layout h2t[n][t*DD+d]
__global__ void ln_res_t_kernel(const __half* __restrict__ a, const float* __restrict__ b,
                                const float* __restrict__ gam, const float* __restrict__ bet,
                                __half* __restrict__ h2t)
{
    long row = blockIdx.x; int tid = threadIdx.x;
    __shared__ float red[4];
    long i = row * DD + tid;
    float v = 0.f;
    if (tid < DD) v = __half2float(a[i]) + b[i];
    float s = (tid < DD) ? v : 0.f;
    #pragma unroll
    for (int o = 16; o > 0; o >>= 1) s += __shfl_xor_sync(~0u, s, o);
    if ((tid & 31) == 0) red[tid >> 5] = s;
    __syncthreads();
    float mean = (red[0] + red[1] + red[2] + red[3]) / (float)DD;
    __syncthreads();
    float d = (tid < DD) ? (v - mean) : 0.f;
    float s2 = d * d;
    #pragma unroll
    for (int o = 16; o > 0; o >>= 1) s2 += __shfl_xor_sync(~0u, s2, o);
    if ((tid & 31) == 0) red[tid >> 5] = s2;
    __syncthreads();
    float var = (red[0] + red[1] + red[2] + red[3]) / (float)DD;
    if (tid < DD) {
        long t = row / NPTS, n = row - t * NPTS;
        h2t[n * (long)TD + t * DD + tid] =
            __float2half_rn(d * rsqrtf(var + 1e-5f) * gam[tid] + bet[tid]);
    }
}

// ---------------- split-K deterministic reduction -------------------------------
__global__ void splitk_reduce_kernel(const float* __restrict__ part, const float* __restrict__ bias,
                                     __half* __restrict__ y, int MN, int Z, int Nc)
{
    int i = blockIdx.x * 256 + threadIdx.x;
    if (i >= MN) return;
    float s = bias[i % Nc];
    for (int z = 0; z < Z; z++) s += part[(long)z * MN + i];
    y[i] = __float2half_rn(s);
}

// ---------------- streaming GEMM launcher ---------------------------------------
template<bool RELU, bool ACC, typename TC>
static void launch_stream_t(const __half* A, const __half* Bt, const float* bias, TC* C,
                            int M, int K, int Nc, cudaStream_t st)
{
    int nkc = (K + 31) / 32;
    int KP = nkc * 32 + 8;
    int smem = 3 * A_STH * 2 + 64 * KP * 2;
    int nx = (Nc + 63) / 64;
    int MT = (M + 127) / 128;
    int gy = (444 + nx - 1) / nx;
    if (gy > MT) gy = MT;
    gemm_stream<RELU, ACC, TC><<<dim3(nx, gy), 256, smem, st>>>(A, Bt, bias, C, M, K, Nc, KP);
}

// ---------------- host orchestration --------------------------------------------
static void run_attention(const __half* x4, const __half* qwT, const __half* owT,
                          const float* ob, __half* qkv,
                          float* kvs_s, float* ksum_s, float* kvs_t, float* ksum_t,
                          __half* cat2, __half* att_h, float* att_f, cudaStream_t st)
{
    launch_stream_t<false, false, __half>(x4, qwT, nullptr, qkv, TN, DD, D3, st);
    kvs_kernel<<<dim3(TT, HH), 256, 0, st>>>(qkv, (long)NPTS * D3, (long)D3, NPTS, kvs_s, ksum_s);
    kvs_kernel<<<dim3(NPTS, HH), 256, 0, st>>>(qkv, (long)D3, (long)NPTS * D3, TT, kvs_t, ksum_t);
    attnout2_kernel<<<dim3(NPTS, TT), 128, 0, st>>>(qkv, kvs_s, ksum_s, kvs_t, ksum_t, cat2);
    if (att_h) launch_stream_t<false, false, __half>(cat2, owT, ob, att_h, TN, D2, DD, st);
    else       launch_stream_t<false, false, float >(cat2, owT, ob, att_f, TN, D2, DD, st);
}

extern "C" void kernel_launch(void* const* d_in, const int* in_sizes, int n_in,
                              void* d_out, int out_size)
{
    (void)in_sizes; (void)n_in; (void)out_size;
    const float* x     = (const float*)d_in[0];
    const float* W_in  = (const float*)d_in[1];
    const float* b_in  = (const float*)d_in[2];
    const float* adp   = (const float*)d_in[3];
    const float* W_tp  = (const float*)d_in[4];
    const float* b_tp  = (const float*)d_in[5];
    const float* qkv_w = (const float*)d_in[6];
    const float* op_w  = (const float*)d_in[7];
    const float* op_b  = (const float*)d_in[8];
    const float* pw_w  = (const float*)d_in[9];
    const float* pw_b  = (const float*)d_in[10];
    const float* fc_w1 = (const float*)d_in[11];
    const float* fc_b1 = (const float*)d_in[12];
    const float* fc_w2 = (const float*)d_in[13];
    const float* fc_b2 = (const float*)d_in[14];
    const float* ln1_g = (const float*)d_in[15];
    const float* ln1_b = (const float*)d_in[16];
    const float* ln2_g = (const float*)d_in[17];
    const float* ln2_b = (const float*)d_in[18];
    const float* ep_w  = (const float*)d_in[19];
    const float* ep_b  = (const float*)d_in[20];
    const float* enc_w1= (const float*)d_in[21];
    const float* enc_b1= (const float*)d_in[22];
    const float* enc_w2= (const float*)d_in[23];
    const float* enc_b2= (const float*)d_in[24];
    const float* out_w = (const float*)d_in[25];
    const float* out_b = (const float*)d_in[26];
    float* out = (float*)d_out;

    static cudaStream_t s1 = nullptr;
    static cudaEvent_t evAdp, evHT, evB1;
    if (!s1) {
        cudaStreamCreateWithFlags(&s1, cudaStreamNonBlocking);
        cudaEventCreateWithFlags(&evAdp, cudaEventDisableTiming);
        cudaEventCreateWithFlags(&evHT,  cudaEventDisableTiming);
        cudaEventCreateWithFlags(&evB1,  cudaEventDisableTiming);
        cudaFuncSetAttribute(gemm_kernel<false, __half>,
                             cudaFuncAttributeMaxDynamicSharedMemorySize, SMEM_BATCH);
        cudaFuncSetAttribute(gemm_kernel<true, float>,
                             cudaFuncAttributeMaxDynamicSharedMemorySize, SMEM_BATCH);
        cudaFuncSetAttribute(gemm_stream<false, false, __half>,
                             cudaFuncAttributeMaxDynamicSharedMemorySize, SMEM_STREAM_MAX);
        cudaFuncSetAttribute(gemm_stream<true, false, __half>,
                             cudaFuncAttributeMaxDynamicSharedMemorySize, SMEM_STREAM_MAX);
        cudaFuncSetAttribute(gemm_stream<false, true, __half>,
                             cudaFuncAttributeMaxDynamicSharedMemorySize, SMEM_STREAM_MAX);
        cudaFuncSetAttribute(gemm_stream<false, false, float>,
                             cudaFuncAttributeMaxDynamicSharedMemorySize, SMEM_STREAM_MAX);
    }

    __half *hcat, *h, *hT, *graph, *z1, *qkv, *qkv2, *cat2, *cat2b, *att0;
    __half *h1, *h2t, *y, *yh, *wtsh;
    float *kvs_s, *ksum_s, *kvs_t, *ksum_t, *kvs_s2, *ksum_s2, *kvs_t2, *ksum_t2;
    float *att1, *p0, *p1, *t2, *part;
    cudaGetSymbolAddress((void**)&hcat, g_hcat);
    cudaGetSymbolAddress((void**)&h,    g_h);
    cudaGetSymbolAddress((void**)&hT,   g_hT);
    cudaGetSymbolAddress((void**)&graph,g_graph);
    cudaGetSymbolAddress((void**)&z1,   g_z1);
    cudaGetSymbolAddress((void**)&qkv,  g_qkv);
    cudaGetSymbolAddress((void**)&qkv2, g_qkv2);
    cudaGetSymbolAddress((void**)&kvs_s,  g_kvs_s);
    cudaGetSymbolAddress((void**)&ksum_s, g_ksum_s);
    cudaGetSymbolAddress((void**)&kvs_t,  g_kvs_t);
    cudaGetSymbolAddress((void**)&ksum_t, g_ksum_t);
    cudaGetSymbolAddress((void**)&kvs_s2, g_kvs_s2);
    cudaGetSymbolAddress((void**)&ksum_s2,g_ksum_s2);
    cudaGetSymbolAddress((void**)&kvs_t2, g_kvs_t2);
    cudaGetSymbolAddress((void**)&ksum_t2,g_ksum_t2);
    cudaGetSymbolAddress((void**)&cat2,  g_cat2);
    cudaGetSymbolAddress((void**)&cat2b, g_cat2b);
    cudaGetSymbolAddress((void**)&att0, g_att0);
    cudaGetSymbolAddress((void**)&att1, g_att1);
    cudaGetSymbolAddress((void**)&p0,   g_p0);
    cudaGetSymbolAddress((void**)&p1,   g_p1);
    cudaGetSymbolAddress((void**)&h1,   g_h1);
    cudaGetSymbolAddress((void**)&t2,   g_t2);
    cudaGetSymbolAddress((void**)&h2t,  g_h2t);
    cudaGetSymbolAddress((void**)&part, g_part);
    cudaGetSymbolAddress((void**)&y,    g_y);
    cudaGetSymbolAddress((void**)&yh,   g_yh);
    cudaGetSymbolAddress((void**)&wtsh, g_wtsh);

    __half* adp_h  = wtsh + O_ADP;
    __half* WtpT   = wtsh + O_WTP;
    __half* qkvwT  = wtsh + O_QKVW;
    __half* opwT   = wtsh + O_OPW;
    __half* pwwT   = wtsh + O_PWW;
    __half* fc1T   = wtsh + O_FC1;
    __half* fc2T   = wtsh + O_FC2;
    __half* epwT   = wtsh + O_EPW;
    __half* enc1T  = wtsh + O_ENC1;
    __half* enc2T  = wtsh + O_ENC2;
    __half* outwT  = wtsh + O_OUTW;

    // ---- adp conversion first (graph branch + hcat need it) ----
    {
        long n2 = (long)TT * NPTS * 80 / 2;
        rnd2h_kernel<<<(n2 + 255) / 256, 256>>>(adp, adp_h, n2);
    }

    // ======== FORK: graph branch on s1 ========
    cudaEventRecord(evAdp, 0);
    cudaStreamWaitEvent(s1, evAdp, 0);
    gemm_kernel<false, __half><<<dim3(7, 4, TT), 256, SMEM_BATCH, s1>>>(
        adp_h, adp_h, nullptr, graph, NPTS, 80, NPTS,
        (long)NPTS * 80, (long)NPTS * 80, (long)NPTS * NPTS);
    normgraph_kernel<<<(TN + 7) / 8, 256, 0, s1>>>(graph);

    // ---- main: remaining weight conversions ----
    #define TRND(src, dst, K_, N_) \
        trnd_kernel<<<(((long)(K_) * (N_)) + 255) / 256, 256>>>(src, dst, K_, N_)
    TRND(W_tp, WtpT, DD, DD);
    TRND(qkv_w,            qkvwT,             DD, D3);
    TRND(qkv_w + DD * D3,  qkvwT + D3 * DD,   DD, D3);
    TRND(op_w,             opwT,              D2, DD);
    TRND(op_w + D2 * DD,   opwT + DD * D2,    D2, DD);
    TRND(pw_w,             pwwT,              DD, DD);
    TRND(pw_w + DD * DD,   pwwT + DD * DD,    DD, DD);
    TRND(fc_w1, fc1T, DD, D2);
    TRND(fc_w2, fc2T, D2, DD);
    for (int i = 0; i < 3; i++) {
        TRND(enc_w1 + (long)i * DD * D2, enc1T + (long)i * D2 * DD, DD, D2);
        TRND(enc_w2 + (long)i * D2 * DD, enc2T + (long)i * DD * D2, D2, DD);
    }
    TRND(out_w, outwT, DD, TT);
    trnd_tiled_kernel<<<dim3((TD + 31) / 32, (DD + 31) / 32), 256>>>(ep_w, epwT, TD, DD);

    // ---- main: h chain ----
    hcat_kernel<<<((long)TN * DD + 255) / 256, 256>>>(x, W_in, b_in, adp_h, hcat);
    launch_stream_t<false, false, __half>(hcat, WtpT, b_tp, h, TN, DD, DD, 0);
    transpose_hT_kernel<<<((long)TN * DD + 255) / 256, 256>>>(h, hT);
    cudaEventRecord(evHT, 0);

    // ======== s1: z1 + attention branch 1 (fully concurrent with branch 0) ======
    cudaStreamWaitEvent(s1, evHT, 0);
    gemm_kernel<false, __half><<<dim3(2, 4, TT), 256, SMEM_BATCH, s1>>>(
        graph, hT, nullptr, z1, NPTS, NPTS, DD,
        (long)NPTS * NPTS, (long)DD * NPTS, (long)NPTS * DD);
    run_attention(z1, qkvwT + D3 * DD, opwT + DD * D2, op_b + DD, qkv2,
                  kvs_s2, ksum_s2, kvs_t2, ksum_t2, cat2b, nullptr, att1, s1);
    cudaEventRecord(evB1, s1);

    // ---- main (concurrent): p0, attention branch 0, p1 ----
    launch_stream_t<false, false, float>(h, pwwT, pw_b, p0, TN, DD, DD, 0);
    run_attention(h, qkvwT, opwT, op_b, qkv, kvs_s, ksum_s, kvs_t, ksum_t,
                  cat2, att0, nullptr, 0);
    launch_stream_t<false, false, float>(att0, pwwT + DD * DD, pw_b + DD, p1, TN, DD, DD, 0);

    // ======== JOIN ========
    cudaStreamWaitEvent(0, evB1, 0);

    combine_ln_kernel<<<TN, 128>>>(h, att0, att1, p0, p1, ln1_g, ln1_b, h1);
    launch_stream_t<true,  false, __half>(h1,   fc1T, fc_b1, cat2, TN, DD, D2, 0);
    launch_stream_t<false, false, float >(cat2, fc2T, fc_b2, t2,   TN, D2, DD, 0);
    ln_res_t_kernel<<<TN, 128>>>(h1, t2, ln2_g, ln2_b, h2t);
    gemm_kernel<true, float><<<dim3(2, 4, SPLITK), 256, SMEM_BATCH>>>(
        h2t, epwT, nullptr, part, NPTS, TD, DD, 0, 0, 0);
    splitk_reduce_kernel<<<(NPTS * DD + 255) / 256, 256>>>(part, ep_b, y, NPTS * DD, SPLITK, DD);
    for (int i = 0; i < 3; i++) {
        launch_stream_t<true,  false, __half>(y,  enc1T + (long)i * D2 * DD,
                                              enc_b1 + (long)i * D2, yh, NPTS, DD, D2, 0);
        launch_stream_t<false, true,  __half>(yh, enc2T + (long)i * DD * D2,
                                              enc_b2 + (long)i * DD, y,  NPTS, D2, DD, 0);
    }
    launch_stream_t<false, false, float>(y, outwT, out_b, out, NPTS, DD, TT, 0);
}